// round 9
// baseline (speedup 1.0000x reference)
#include <cuda_runtime.h>
#include <cuda_bf16.h>
#include <cstdint>

#define BATCH 2
#define SEQL  4096
#define OUTD  512
#define NHEAD 8
#define RATE  4
#define NSUB  1025
#define NSUBP 1088
#define NCOMBO 64
#define SCALE 0.125f
#define LOG2E 1.44269504088896340736f
#define NEGBIG 1e30f

#define MPB   4160
#define MXP   (2 * MPB)     // 8320 = 65 * 128

#define BQ 128
#define SK 72
#define BSW 68

typedef __nv_bfloat16 bf16;

__device__ bf16 g_Qh[(size_t)NCOMBO * NSUBP * 64];
__device__ bf16 g_Ql[(size_t)NCOMBO * NSUBP * 64];
__device__ bf16 g_Kh[(size_t)NCOMBO * NSUBP * 64];
__device__ bf16 g_Kl[(size_t)NCOMBO * NSUBP * 64];
__device__ bf16 g_VTh[(size_t)NCOMBO * 64 * NSUBP];
__device__ bf16 g_VTl[(size_t)NCOMBO * 64 * NSUBP];
__device__ float g_Vf[(size_t)NCOMBO * NSUBP * 64];
__device__ bf16 g_xh[(size_t)MXP * OUTD];
__device__ bf16 g_xl[(size_t)MXP * OUTD];
__device__ bf16 g_WhT[3][OUTD * OUTD];
__device__ bf16 g_WlT[3][OUTD * OUTD];

__device__ __forceinline__ uint32_t packbf(float hi, float lo) {
    uint32_t r; asm("cvt.rn.bf16x2.f32 %0, %1, %2;" : "=r"(r) : "f"(hi), "f"(lo)); return r;
}
__device__ __forceinline__ void cpasync16(uint32_t s, const void* g) {
    asm volatile("cp.async.cg.shared.global [%0], [%1], 16;\n" :: "r"(s), "l"(g));
}
__device__ __forceinline__ void cpcommit() { asm volatile("cp.async.commit_group;\n"); }
__device__ __forceinline__ void cpwait0()  { asm volatile("cp.async.wait_group 0;\n"); }
__device__ __forceinline__ void cpwait1()  { asm volatile("cp.async.wait_group 1;\n"); }

__device__ __forceinline__ void mma16816(float* d, const uint32_t* a, uint32_t b0, uint32_t b1) {
    asm volatile("mma.sync.aligned.m16n8k16.row.col.f32.bf16.bf16.f32 "
        "{%0,%1,%2,%3}, {%4,%5,%6,%7}, {%8,%9}, {%0,%1,%2,%3};"
        : "+f"(d[0]), "+f"(d[1]), "+f"(d[2]), "+f"(d[3])
        : "r"(a[0]), "r"(a[1]), "r"(a[2]), "r"(a[3]), "r"(b0), "r"(b1));
}
__device__ __forceinline__ void ldmat4(uint32_t* r, uint32_t addr) {
    asm volatile("ldmatrix.sync.aligned.m8n8.x4.shared.b16 {%0,%1,%2,%3}, [%4];"
        : "=r"(r[0]), "=r"(r[1]), "=r"(r[2]), "=r"(r[3]) : "r"(addr));
}
__device__ __forceinline__ void ldmat2(uint32_t* r, uint32_t addr) {
    asm volatile("ldmatrix.sync.aligned.m8n8.x2.shared.b16 {%0,%1}, [%2];"
        : "=r"(r[0]), "=r"(r[1]) : "r"(addr));
}

// ---------------------------------------------------------------------------
__global__ __launch_bounds__(256) void splitx_kernel(const float* __restrict__ x)
{
    int idx = blockIdx.x * 256 + threadIdx.x;
    int flat = idx * 4;
    int b = flat / (SEQL * OUTD);
    int rem = flat - b * (SEQL * OUTD);
    int t = rem / OUTD;
    int k = rem - t * OUTD;
    float4 v = *(const float4*)(x + (size_t)flat);
    size_t o = ((size_t)(b * MPB + t)) * OUTD + k;
    float hx = __bfloat162float(__float2bfloat16(v.x));
    float hy = __bfloat162float(__float2bfloat16(v.y));
    float hz = __bfloat162float(__float2bfloat16(v.z));
    float hw = __bfloat162float(__float2bfloat16(v.w));
    *(uint2*)(g_xh + o) = make_uint2(packbf(hy, hx), packbf(hw, hz));
    *(uint2*)(g_xl + o) = make_uint2(packbf(v.y - hy, v.x - hx), packbf(v.w - hw, v.z - hz));
}

__global__ __launch_bounds__(256) void splitw_kernel(
    const float* __restrict__ Wq, const float* __restrict__ Wk, const float* __restrict__ Wv)
{
    int k = blockIdx.x, z = blockIdx.y;
    const float* W = (z == 0) ? Wq : (z == 1) ? Wk : Wv;
    #pragma unroll
    for (int half = 0; half < 2; half++) {
        int n = threadIdx.x + half * 256;
        float v = W[(size_t)k * OUTD + n];
        bf16 h = __float2bfloat16(v);
        g_WhT[z][(size_t)n * OUTD + k] = h;
        g_WlT[z][(size_t)n * OUTD + k] = __float2bfloat16(v - __bfloat162float(h));
    }
}

// ---------------------------------------------------------------------------
// Tensor-core projection: per CTA M=128, N=128 (2 heads), K=512 (mma.sync).
// ---------------------------------------------------------------------------
#define KT 32
#define SA 40
#define P_AH 0
#define P_AL (2 * 128 * SA)
#define P_BH (4 * 128 * SA)
#define P_BL (6 * 128 * SA)
#define SC 132
#define P_SMEM_BYTES 81920

__global__ __launch_bounds__(256, 2) void proj_tc_kernel()
{
    extern __shared__ __align__(16) bf16 psm[];
    const int tid = threadIdx.x;
    const int w = tid >> 5, l = tid & 31;
    const int lq = l >> 2, c = l & 3;
    const int wm = w & 3, wn = w >> 2;
    const int z  = blockIdx.x;
    const int hp = blockIdx.y;
    const int m0 = blockIdx.z * 128;
    const int n0 = hp * 128;
    const uint32_t su = (uint32_t)__cvta_generic_to_shared(psm);

    const bf16* WhT = g_WhT[z] + (size_t)n0 * OUTD;
    const bf16* WlT = g_WlT[z] + (size_t)n0 * OUTD;

    auto stage = [&](int kt, int bi) {
        const int k0 = kt * KT;
        #pragma unroll
        for (int it = 0; it < 4; it++) {
            int cid = tid + it * 256;
            int sp = cid >> 9, rem = cid & 511;
            int row = rem >> 2, seg = rem & 3;
            uint32_t dst = su + (uint32_t)(((sp ? P_AL : P_AH) + bi * 128 * SA + row * SA + seg * 8) * 2);
            const bf16* src = (sp ? g_xl : g_xh) + (size_t)(m0 + row) * OUTD + k0 + seg * 8;
            cpasync16(dst, src);
        }
        #pragma unroll
        for (int it = 0; it < 4; it++) {
            int cid = tid + it * 256;
            int sp = cid >> 9, rem = cid & 511;
            int row = rem >> 2, seg = rem & 3;
            uint32_t dst = su + (uint32_t)(((sp ? P_BL : P_BH) + bi * 128 * SA + row * SA + seg * 8) * 2);
            const bf16* src = (sp ? WlT : WhT) + (size_t)row * OUTD + k0 + seg * 8;
            cpasync16(dst, src);
        }
        cpcommit();
    };

    stage(0, 0);

    float acc[2][8][4];
    #pragma unroll
    for (int i = 0; i < 2; i++)
        #pragma unroll
        for (int j = 0; j < 8; j++)
            #pragma unroll
            for (int t = 0; t < 4; t++) acc[i][j][t] = 0.f;

    const int la16 = l & 15;
    const int la8  = l >> 4;
    const int lb8  = l & 7;
    const int lbm  = (l >> 3) & 1;

    for (int kt = 0; kt < OUTD / KT; kt++) {
        if (kt < OUTD / KT - 1) { stage(kt + 1, (kt + 1) & 1); cpwait1(); }
        else cpwait0();
        __syncthreads();
        const int bi = kt & 1;
        const uint32_t ahb = su + (uint32_t)((P_AH + bi * 128 * SA) * 2);
        const uint32_t alb = su + (uint32_t)((P_AL + bi * 128 * SA) * 2);
        const uint32_t bhb = su + (uint32_t)((P_BH + bi * 128 * SA) * 2);
        const uint32_t blb = su + (uint32_t)((P_BL + bi * 128 * SA) * 2);

        #pragma unroll
        for (int hh = 0; hh < 2; hh++) {
            const int kb = hh * 16;
            uint32_t ah[2][4], al[2][4];
            #pragma unroll
            for (int mb = 0; mb < 2; mb++) {
                uint32_t off = (uint32_t)((wm * 32 + mb * 16 + la16) * SA * 2 + (kb + la8 * 8) * 2);
                ldmat4(ah[mb], ahb + off);
                ldmat4(al[mb], alb + off);
            }
            #pragma unroll
            for (int nb = 0; nb < 8; nb++) {
                uint32_t off = (uint32_t)((wn * 64 + nb * 8 + lb8) * SA * 2 + (kb + lbm * 8) * 2);
                uint32_t bh[2], bl[2];
                ldmat2(bh, bhb + off);
                ldmat2(bl, blb + off);
                #pragma unroll
                for (int mb = 0; mb < 2; mb++) {
                    mma16816(acc[mb][nb], ah[mb], bh[0], bh[1]);
                    mma16816(acc[mb][nb], al[mb], bh[0], bh[1]);
                    mma16816(acc[mb][nb], ah[mb], bl[0], bl[1]);
                }
            }
        }
        __syncthreads();
    }

    float* C = (float*)psm;
    #pragma unroll
    for (int mb = 0; mb < 2; mb++) {
        int r0 = wm * 32 + mb * 16 + lq;
        #pragma unroll
        for (int nb = 0; nb < 8; nb++) {
            int col = wn * 64 + nb * 8 + c * 2;
            *(float2*)(C + r0 * SC + col)       = make_float2(acc[mb][nb][0], acc[mb][nb][1]);
            *(float2*)(C + (r0 + 8) * SC + col) = make_float2(acc[mb][nb][2], acc[mb][nb][3]);
        }
    }
    __syncthreads();

    const int bb = m0 / MPB;
    const int t0 = m0 - bb * MPB;
    const bool fast = ((m0 + 127) / MPB == bb) && (t0 + 128 <= SEQL);

    if (z == 2 && fast) {
        const int iq0 = t0 >> 2;
        {
            int r = tid >> 1, hh2 = tid & 1;
            int head = hp * 2 + hh2;
            int t = t0 + r;
            int iq = t >> 2, r4 = t & 3;
            int combo = (bb * NHEAD + head) * RATE + r4;
            size_t orow = ((size_t)combo * NSUBP + iq) * 64;
            #pragma unroll
            for (int j = 0; j < 16; j++)
                *(float4*)(g_Vf + orow + j * 4) = *(const float4*)(C + r * SC + hh2 * 64 + j * 4);
        }
        {
            int hh2 = tid & 1;
            int head = hp * 2 + hh2;
            int tid2 = tid >> 1;
            int g = tid2 & 7, r4 = (tid2 >> 3) & 3, dl = tid2 >> 5;
            int combo = (bb * NHEAD + head) * RATE + r4;
            #pragma unroll
            for (int it = 0; it < 16; it++) {
                int d = it * 4 + dl;
                float v[4], hi[4];
                #pragma unroll
                for (int j = 0; j < 4; j++) {
                    int r = (g * 4 + j) * 4 + r4;
                    v[j] = C[r * SC + hh2 * 64 + d];
                    hi[j] = __bfloat162float(__float2bfloat16(v[j]));
                }
                uint2 uh = make_uint2(packbf(hi[1], hi[0]), packbf(hi[3], hi[2]));
                uint2 ul = make_uint2(packbf(v[1] - hi[1], v[0] - hi[0]),
                                      packbf(v[3] - hi[3], v[2] - hi[2]));
                size_t o = ((size_t)combo * 64 + d) * NSUBP + iq0 + g * 4;
                *(uint2*)(g_VTh + o) = uh;
                *(uint2*)(g_VTl + o) = ul;
            }
        }
    } else {
        int r = tid >> 1, hh2 = tid & 1;
        int head = hp * 2 + hh2;
        int m = m0 + r;
        int b = m / MPB;
        int t = m - b * MPB;
        if (t < SEQL) {
            int iq = t >> 2, r4 = t & 3;
            int combo = (b * NHEAD + head) * RATE + r4;
            size_t orow = ((size_t)combo * NSUBP + iq) * 64;
            #pragma unroll
            for (int j = 0; j < 16; j++) {
                int d = j * 4;
                float4 v = *(const float4*)(C + r * SC + hh2 * 64 + d);
                float vf[4] = {v.x, v.y, v.z, v.w};
                if (z == 0) {
                    #pragma unroll
                    for (int e = 0; e < 4; e++) vf[e] *= SCALE * LOG2E;
                }
                float h0 = __bfloat162float(__float2bfloat16(vf[0]));
                float h1 = __bfloat162float(__float2bfloat16(vf[1]));
                float h2 = __bfloat162float(__float2bfloat16(vf[2]));
                float h3 = __bfloat162float(__float2bfloat16(vf[3]));
                uint2 uh = make_uint2(packbf(h1, h0), packbf(h3, h2));
                uint2 ul = make_uint2(packbf(vf[1] - h1, vf[0] - h0), packbf(vf[3] - h3, vf[2] - h2));
                if (z == 0) {
                    *(uint2*)(g_Qh + orow + d) = uh;
                    *(uint2*)(g_Ql + orow + d) = ul;
                } else if (z == 1) {
                    *(uint2*)(g_Kh + orow + d) = uh;
                    *(uint2*)(g_Kl + orow + d) = ul;
                } else {
                    *(float4*)(g_Vf + orow + d) = v;
                    float hs[4] = {h0, h1, h2, h3};
                    #pragma unroll
                    for (int e = 0; e < 4; e++) {
                        size_t ot = ((size_t)combo * 64 + d + e) * NSUBP + iq;
                        g_VTh[ot] = __float2bfloat16(hs[e]);
                        g_VTl[ot] = __float2bfloat16(vf[e] - hs[e]);
                    }
                }
            }
        }
    }
}

// ---------------------------------------------------------------------------
// Flash attention: deferred l-reduction + split softmax/PV halves.
// ---------------------------------------------------------------------------
#define SM_QH 0
#define SM_QL (BQ * SK)
#define SM_BUF (2 * BQ * SK)
#define BUF_SZ (4 * 64 * SK)
#define SMEM_BYTES ((SM_BUF + 2 * BUF_SZ) * 2)   // 110592

__global__ __launch_bounds__(256, 2) void attn_kernel(float* __restrict__ out)
{
    extern __shared__ __align__(16) bf16 sm[];
    bf16* QhS = sm + SM_QH;
    bf16* QlS = sm + SM_QL;

    const int tid = threadIdx.x;
    const int w = tid >> 5, l = tid & 31;
    const int lq = l >> 2;
    const int c  = l & 3;
    const int combo = blockIdx.y;
    const int q0 = blockIdx.x * BQ;
    const uint32_t smem_u32 = (uint32_t)__cvta_generic_to_shared(sm);

    const size_t gq = (size_t)combo * NSUBP * 64;
    const size_t gvt = (size_t)combo * 64 * NSUBP;

    #pragma unroll
    for (int it = 0; it < 8; it++) {
        int cid = tid + it * 256;
        int arr = cid >> 10;
        int rem = cid & 1023;
        int row = rem >> 3, seg = rem & 7;
        uint32_t dst = smem_u32 + (uint32_t)(((arr ? SM_QL : SM_QH) + row * SK) * 2 + seg * 16);
        const bf16* src = (arr ? g_Ql : g_Qh) + gq + (size_t)(q0 + row) * 64 + seg * 8;
        cpasync16(dst, src);
    }
    cpcommit();

    {
        #pragma unroll
        for (int it = 0; it < 8; it++) {
            int cid = tid + it * 256;
            int arr = cid >> 9;
            int rem = cid & 511;
            int row = rem >> 3, seg = rem & 7;
            uint32_t dst = smem_u32 + (uint32_t)((SM_BUF + arr * 64 * SK + row * SK) * 2 + seg * 16);
            const bf16* src;
            if (arr == 0)      src = g_Kh + gq + (size_t)row * 64 + seg * 8;
            else if (arr == 1) src = g_Kl + gq + (size_t)row * 64 + seg * 8;
            else if (arr == 2) src = g_VTh + gvt + (size_t)row * NSUBP + seg * 8;
            else               src = g_VTl + gvt + (size_t)row * NSUBP + seg * 8;
            cpasync16(dst, src);
        }
        cpcommit();
    }
    cpwait0();
    __syncthreads();

    uint32_t qh[4][4], ql[4][4];
    {
        const int la16 = l & 15, la8 = l >> 4;
        uint32_t qhb = smem_u32 + (uint32_t)((SM_QH + (w * 16 + la16) * SK) * 2);
        uint32_t qlb = smem_u32 + (uint32_t)((SM_QL + (w * 16 + la16) * SK) * 2);
        #pragma unroll
        for (int kc = 0; kc < 4; kc++) {
            uint32_t off = (uint32_t)((kc * 16 + la8 * 8) * 2);
            ldmat4(qh[kc], qhb + off);
            ldmat4(ql[kc], qlb + off);
        }
    }

    float oacc[8][4];
    #pragma unroll
    for (int j = 0; j < 8; j++)
        #pragma unroll
        for (int t = 0; t < 4; t++) oacc[j][t] = 0.f;
    // l0/l1 are PER-LANE PARTIAL sums (quad-reduced only in the epilogue)
    float m0 = -NEGBIG, m1 = -NEGBIG, l0 = 0.f, l1 = 0.f;

    const int lrow8 = l & 7;
    const int lcol8 = l >> 3;
    const uint32_t boff_lane = (uint32_t)(lrow8 * SK * 2 + lcol8 * 16);

    for (int kt = 0; kt < 16; kt++) {
        __syncthreads();
        if (kt < 15) {
            const int ks = (kt + 1) * 64;
            const int boff = SM_BUF + ((kt + 1) & 1) * BUF_SZ;
            #pragma unroll
            for (int it = 0; it < 8; it++) {
                int cid = tid + it * 256;
                int arr = cid >> 9;
                int rem = cid & 511;
                int row = rem >> 3, seg = rem & 7;
                uint32_t dst = smem_u32 + (uint32_t)((boff + arr * 64 * SK + row * SK) * 2 + seg * 16);
                const bf16* src;
                if (arr == 0)      src = g_Kh + gq + (size_t)(ks + row) * 64 + seg * 8;
                else if (arr == 1) src = g_Kl + gq + (size_t)(ks + row) * 64 + seg * 8;
                else if (arr == 2) src = g_VTh + gvt + (size_t)row * NSUBP + ks + seg * 8;
                else               src = g_VTl + gvt + (size_t)row * NSUBP + ks + seg * 8;
                cpasync16(dst, src);
            }
            cpcommit();
            cpwait1();
        } else {
            cpwait0();
        }
        __syncthreads();

        const int bufbase = SM_BUF + (kt & 1) * BUF_SZ;
        const uint32_t khb = smem_u32 + (uint32_t)((bufbase) * 2) + boff_lane;
        const uint32_t klb = smem_u32 + (uint32_t)((bufbase + 64 * SK) * 2) + boff_lane;
        const uint32_t vhb = smem_u32 + (uint32_t)((bufbase + 2 * 64 * SK) * 2) + boff_lane;
        const uint32_t vlb = smem_u32 + (uint32_t)((bufbase + 3 * 64 * SK) * 2) + boff_lane;

        // ---- S = Q K^T ----
        float sacc[8][4];
        #pragma unroll
        for (int j = 0; j < 8; j++) {
            #pragma unroll
            for (int t = 0; t < 4; t++) sacc[j][t] = 0.f;
            uint32_t bh[8], bl[8];
            uint32_t a = khb + (uint32_t)(j * 8 * SK * 2);
            ldmat4(bh, a); ldmat4(bh + 4, a + 64);
            uint32_t a2 = klb + (uint32_t)(j * 8 * SK * 2);
            ldmat4(bl, a2); ldmat4(bl + 4, a2 + 64);
            #pragma unroll
            for (int kc = 0; kc < 4; kc++) {
                mma16816(sacc[j], qh[kc], bh[2 * kc], bh[2 * kc + 1]);
                mma16816(sacc[j], ql[kc], bh[2 * kc], bh[2 * kc + 1]);
                mma16816(sacc[j], qh[kc], bl[2 * kc], bl[2 * kc + 1]);
            }
        }

        // ---- max reduce + alpha (exp2 domain) ----
        float rmx0 = -NEGBIG, rmx1 = -NEGBIG;
        #pragma unroll
        for (int j = 0; j < 8; j++) {
            rmx0 = fmaxf(rmx0, fmaxf(sacc[j][0], sacc[j][1]));
            rmx1 = fmaxf(rmx1, fmaxf(sacc[j][2], sacc[j][3]));
        }
        rmx0 = fmaxf(rmx0, __shfl_xor_sync(0xffffffffu, rmx0, 1));
        rmx0 = fmaxf(rmx0, __shfl_xor_sync(0xffffffffu, rmx0, 2));
        rmx1 = fmaxf(rmx1, __shfl_xor_sync(0xffffffffu, rmx1, 1));
        rmx1 = fmaxf(rmx1, __shfl_xor_sync(0xffffffffu, rmx1, 2));

        float mn0 = fmaxf(m0, rmx0), mn1 = fmaxf(m1, rmx1);
        float a0 = exp2f(m0 - mn0), a1 = exp2f(m1 - mn1);
        m0 = mn0; m1 = mn1;
        l0 *= a0; l1 *= a1;
        #pragma unroll
        for (int j = 0; j < 8; j++) {
            oacc[j][0] *= a0; oacc[j][1] *= a0;
            oacc[j][2] *= a1; oacc[j][3] *= a1;
        }

        // ---- two kc-halves: exp2+pack interleaved with PV MMAs ----
        float s0p = 0.f, s1p = 0.f;
        #pragma unroll
        for (int half = 0; half < 2; half++) {
            uint32_t pah[2][4], pal[2][4];
            #pragma unroll
            for (int kk = 0; kk < 2; kk++) {
                int kc = half * 2 + kk;
                int j0 = 2 * kc, j1 = 2 * kc + 1;
                sacc[j0][0] = exp2f(sacc[j0][0] - mn0);
                sacc[j0][1] = exp2f(sacc[j0][1] - mn0);
                sacc[j0][2] = exp2f(sacc[j0][2] - mn1);
                sacc[j0][3] = exp2f(sacc[j0][3] - mn1);
                sacc[j1][0] = exp2f(sacc[j1][0] - mn0);
                sacc[j1][1] = exp2f(sacc[j1][1] - mn0);
                sacc[j1][2] = exp2f(sacc[j1][2] - mn1);
                sacc[j1][3] = exp2f(sacc[j1][3] - mn1);
                s0p += sacc[j0][0] + sacc[j0][1] + sacc[j1][0] + sacc[j1][1];
                s1p += sacc[j0][2] + sacc[j0][3] + sacc[j1][2] + sacc[j1][3];
                uint32_t h;
                h = packbf(sacc[j0][1], sacc[j0][0]); pah[kk][0] = h;
                pal[kk][0] = packbf(sacc[j0][1] - __uint_as_float(h & 0xffff0000u),
                                    sacc[j0][0] - __uint_as_float(h << 16));
                h = packbf(sacc[j0][3], sacc[j0][2]); pah[kk][1] = h;
                pal[kk][1] = packbf(sacc[j0][3] - __uint_as_float(h & 0xffff0000u),
                                    sacc[j0][2] - __uint_as_float(h << 16));
                h = packbf(sacc[j1][1], sacc[j1][0]); pah[kk][2] = h;
                pal[kk][2] = packbf(sacc[j1][1] - __uint_as_float(h & 0xffff0000u),
                                    sacc[j1][0] - __uint_as_float(h << 16));
                h = packbf(sacc[j1][3], sacc[j1][2]); pah[kk][3] = h;
                pal[kk][3] = packbf(sacc[j1][3] - __uint_as_float(h & 0xffff0000u),
                                    sacc[j1][2] - __uint_as_float(h << 16));
            }
            // PV for this half: ldmat4 at +0 covers kc {0,1}; +64 covers {2,3}
            #pragma unroll
            for (int j = 0; j < 8; j++) {
                uint32_t bh[4], bl[4];
                uint32_t a = vhb + (uint32_t)(j * 8 * SK * 2) + half * 64;
                ldmat4(bh, a);
                uint32_t a2 = vlb + (uint32_t)(j * 8 * SK * 2) + half * 64;
                ldmat4(bl, a2);
                #pragma unroll
                for (int kk = 0; kk < 2; kk++) {
                    mma16816(oacc[j], pah[kk], bh[2 * kk], bh[2 * kk + 1]);
                    mma16816(oacc[j], pal[kk], bh[2 * kk], bh[2 * kk + 1]);
                    mma16816(oacc[j], pah[kk], bl[2 * kk], bl[2 * kk + 1]);
                }
            }
        }
        l0 += s0p;
        l1 += s1p;
    }

    // ---- band pass (7 banded logits) + analytic zero key ----
    __syncthreads();
    float* Kband = (float*)(sm + SM_BUF);
    float* Vband = Kband + 134 * BSW;
    for (int i = tid; i < 134 * 64; i += 256) {
        int rr = i >> 6, d = i & 63;
        int g = q0 - 3 + rr;
        float kv = 0.f, vv = 0.f;
        if (g >= 0) {
            size_t o = gq + (size_t)g * 64 + d;
            kv = __bfloat162float(g_Kh[o]) + __bfloat162float(g_Kl[o]);
            vv = g_Vf[o];
        }
        Kband[rr * BSW + d] = kv;
        Vband[rr * BSW + d] = vv;
    }
    __syncthreads();

    float bl[2][2];
    #pragma unroll
    for (int rh = 0; rh < 2; rh++) {
        int qlcl = w * 16 + lq + 8 * rh;
        int kk0 = c, kk1 = c + 4;
        float acc0 = 0.f, acc1 = 0.f;
        const float* kb0 = Kband + (qlcl + kk0) * BSW;
        const float* kb1 = Kband + (qlcl + kk1) * BSW;
        #pragma unroll 8
        for (int d = 0; d < 64; d++) {
            float qf = __bfloat162float(QhS[qlcl * SK + d]) + __bfloat162float(QlS[qlcl * SK + d]);
            acc0 += qf * kb0[d];
            if (kk1 < 7) acc1 += qf * kb1[d];
        }
        bl[rh][0] = acc0;
        bl[rh][1] = (kk1 < 7) ? acc1 : -NEGBIG;
    }

    {
        float rmx0 = fmaxf(bl[0][0], bl[0][1]);
        float rmx1 = fmaxf(bl[1][0], bl[1][1]);
        rmx0 = fmaxf(rmx0, __shfl_xor_sync(0xffffffffu, rmx0, 1));
        rmx0 = fmaxf(rmx0, __shfl_xor_sync(0xffffffffu, rmx0, 2));
        rmx1 = fmaxf(rmx1, __shfl_xor_sync(0xffffffffu, rmx1, 1));
        rmx1 = fmaxf(rmx1, __shfl_xor_sync(0xffffffffu, rmx1, 2));
        float mn0 = fmaxf(fmaxf(m0, rmx0), 0.f);
        float mn1 = fmaxf(fmaxf(m1, rmx1), 0.f);
        float a0 = exp2f(m0 - mn0), a1 = exp2f(m1 - mn1);
        m0 = mn0; m1 = mn1;
        float p00 = exp2f(bl[0][0] - mn0);
        float p01 = (c + 4 < 7) ? exp2f(bl[0][1] - mn0) : 0.f;
        float p10 = exp2f(bl[1][0] - mn1);
        float p11 = (c + 4 < 7) ? exp2f(bl[1][1] - mn1) : 0.f;
        // per-lane partial l update; zero-key term added by lane c==0 only
        l0 = l0 * a0 + p00 + p01 + ((c == 0) ? exp2f(-mn0) : 0.f);
        l1 = l1 * a1 + p10 + p11 + ((c == 0) ? exp2f(-mn1) : 0.f);
        #pragma unroll
        for (int j = 0; j < 8; j++) {
            oacc[j][0] *= a0; oacc[j][1] *= a0;
            oacc[j][2] *= a1; oacc[j][3] *= a1;
        }

        int r0 = w * 16 + lq;
        #pragma unroll
        for (int kk = 0; kk < 7; kk++) {
            int src = (l & ~3) | (kk & 3);
            float pb0 = __shfl_sync(0xffffffffu, (kk < 4) ? p00 : p01, src);
            float pb1 = __shfl_sync(0xffffffffu, (kk < 4) ? p10 : p11, src);
            const float* v0 = Vband + (r0 + kk) * BSW + c * 2;
            const float* v1 = Vband + (r0 + 8 + kk) * BSW + c * 2;
            #pragma unroll
            for (int j = 0; j < 8; j++) {
                float2 a = *(const float2*)(v0 + j * 8);
                float2 bq = *(const float2*)(v1 + j * 8);
                oacc[j][0] += pb0 * a.x; oacc[j][1] += pb0 * a.y;
                oacc[j][2] += pb1 * bq.x; oacc[j][3] += pb1 * bq.y;
            }
        }
    }

    // ---- epilogue: quad-reduce the deferred l partials, normalize, store ----
    l0 += __shfl_xor_sync(0xffffffffu, l0, 1);
    l0 += __shfl_xor_sync(0xffffffffu, l0, 2);
    l1 += __shfl_xor_sync(0xffffffffu, l1, 1);
    l1 += __shfl_xor_sync(0xffffffffu, l1, 2);

    const int b = combo >> 5;
    const int h = (combo >> 2) & 7;
    const int r = combo & 3;
    float inv0 = 1.f / l0, inv1 = 1.f / l1;
    int qg = q0 + w * 16 + lq;
    size_t o0 = ((size_t)(b * SEQL + qg * 4 + r)) * OUTD + h * 64 + c * 2;
    size_t o1 = ((size_t)(b * SEQL + (qg + 8) * 4 + r)) * OUTD + h * 64 + c * 2;
    #pragma unroll
    for (int j = 0; j < 8; j++) {
        *(float2*)(out + o0 + j * 8) = make_float2(oacc[j][0] * inv0, oacc[j][1] * inv0);
        *(float2*)(out + o1 + j * 8) = make_float2(oacc[j][2] * inv1, oacc[j][3] * inv1);
    }
}

// ---------------------------------------------------------------------------
extern "C" void kernel_launch(void* const* d_in, const int* in_sizes, int n_in,
                              void* d_out, int out_size)
{
    const float* x  = (const float*)d_in[0];
    const float* Wq = (const float*)d_in[1];
    const float* Wk = (const float*)d_in[2];
    const float* Wv = (const float*)d_in[3];
    float* out = (float*)d_out;

    cudaFuncSetAttribute(attn_kernel, cudaFuncAttributeMaxDynamicSharedMemorySize, SMEM_BYTES);
    cudaFuncSetAttribute(proj_tc_kernel, cudaFuncAttributeMaxDynamicSharedMemorySize, P_SMEM_BYTES);

    splitx_kernel<<<(BATCH * SEQL * OUTD / 4) / 256, 256>>>(x);
    splitw_kernel<<<dim3(OUTD, 3), 256>>>(Wq, Wk, Wv);

    dim3 pgrid(3, NHEAD / 2, MXP / 128);        // z, head-pair, m-tile
    proj_tc_kernel<<<pgrid, 256, P_SMEM_BYTES>>>();

    dim3 agrid(SEQL / RATE / BQ, NCOMBO);
    attn_kernel<<<agrid, 256, SMEM_BYTES>>>(out);
}

// round 10
// speedup vs baseline: 1.0359x; 1.0359x over previous
#include <cuda_runtime.h>
#include <cuda_bf16.h>
#include <cstdint>

#define BATCH 2
#define SEQL  4096
#define OUTD  512
#define NHEAD 8
#define RATE  4
#define NSUB  1025
#define NSUBP 1088
#define NCOMBO 64
#define SCALE 0.125f
#define LOG2E 1.44269504088896340736f
#define NEGBIG 1e30f

#define MPB   4160
#define MXP   (2 * MPB)     // 8320 = 65 * 128

#define BQ 128
#define SK 72
#define BSW 68

typedef __nv_bfloat16 bf16;

__device__ bf16 g_Qh[(size_t)NCOMBO * NSUBP * 64];
__device__ bf16 g_Ql[(size_t)NCOMBO * NSUBP * 64];
__device__ bf16 g_Kh[(size_t)NCOMBO * NSUBP * 64];
__device__ bf16 g_Kl[(size_t)NCOMBO * NSUBP * 64];
__device__ bf16 g_VTh[(size_t)NCOMBO * 64 * NSUBP];
__device__ bf16 g_VTl[(size_t)NCOMBO * 64 * NSUBP];
__device__ float g_Vf[(size_t)NCOMBO * NSUBP * 64];
__device__ bf16 g_xh[(size_t)MXP * OUTD];
__device__ bf16 g_xl[(size_t)MXP * OUTD];
__device__ bf16 g_WhT[3][OUTD * OUTD];
__device__ bf16 g_WlT[3][OUTD * OUTD];

__device__ __forceinline__ uint32_t packbf(float hi, float lo) {
    uint32_t r; asm("cvt.rn.bf16x2.f32 %0, %1, %2;" : "=r"(r) : "f"(hi), "f"(lo)); return r;
}
__device__ __forceinline__ void cpasync16(uint32_t s, const void* g) {
    asm volatile("cp.async.cg.shared.global [%0], [%1], 16;\n" :: "r"(s), "l"(g));
}
__device__ __forceinline__ void cpcommit() { asm volatile("cp.async.commit_group;\n"); }
__device__ __forceinline__ void cpwait0()  { asm volatile("cp.async.wait_group 0;\n"); }
__device__ __forceinline__ void cpwait1()  { asm volatile("cp.async.wait_group 1;\n"); }

__device__ __forceinline__ void mma16816(float* d, const uint32_t* a, uint32_t b0, uint32_t b1) {
    asm volatile("mma.sync.aligned.m16n8k16.row.col.f32.bf16.bf16.f32 "
        "{%0,%1,%2,%3}, {%4,%5,%6,%7}, {%8,%9}, {%0,%1,%2,%3};"
        : "+f"(d[0]), "+f"(d[1]), "+f"(d[2]), "+f"(d[3])
        : "r"(a[0]), "r"(a[1]), "r"(a[2]), "r"(a[3]), "r"(b0), "r"(b1));
}
__device__ __forceinline__ void ldmat4(uint32_t* r, uint32_t addr) {
    asm volatile("ldmatrix.sync.aligned.m8n8.x4.shared.b16 {%0,%1,%2,%3}, [%4];"
        : "=r"(r[0]), "=r"(r[1]), "=r"(r[2]), "=r"(r[3]) : "r"(addr));
}
__device__ __forceinline__ void ldmat2(uint32_t* r, uint32_t addr) {
    asm volatile("ldmatrix.sync.aligned.m8n8.x2.shared.b16 {%0,%1}, [%2];"
        : "=r"(r[0]), "=r"(r[1]) : "r"(addr));
}

// ---------------------------------------------------------------------------
__global__ __launch_bounds__(256) void splitx_kernel(const float* __restrict__ x)
{
    int idx = blockIdx.x * 256 + threadIdx.x;
    int flat = idx * 4;
    int b = flat / (SEQL * OUTD);
    int rem = flat - b * (SEQL * OUTD);
    int t = rem / OUTD;
    int k = rem - t * OUTD;
    float4 v = *(const float4*)(x + (size_t)flat);
    size_t o = ((size_t)(b * MPB + t)) * OUTD + k;
    float hx = __bfloat162float(__float2bfloat16(v.x));
    float hy = __bfloat162float(__float2bfloat16(v.y));
    float hz = __bfloat162float(__float2bfloat16(v.z));
    float hw = __bfloat162float(__float2bfloat16(v.w));
    *(uint2*)(g_xh + o) = make_uint2(packbf(hy, hx), packbf(hw, hz));
    *(uint2*)(g_xl + o) = make_uint2(packbf(v.y - hy, v.x - hx), packbf(v.w - hw, v.z - hz));
}

__global__ __launch_bounds__(256) void splitw_kernel(
    const float* __restrict__ Wq, const float* __restrict__ Wk, const float* __restrict__ Wv)
{
    int k = blockIdx.x, z = blockIdx.y;
    const float* W = (z == 0) ? Wq : (z == 1) ? Wk : Wv;
    #pragma unroll
    for (int half = 0; half < 2; half++) {
        int n = threadIdx.x + half * 256;
        float v = W[(size_t)k * OUTD + n];
        bf16 h = __float2bfloat16(v);
        g_WhT[z][(size_t)n * OUTD + k] = h;
        g_WlT[z][(size_t)n * OUTD + k] = __float2bfloat16(v - __bfloat162float(h));
    }
}

// ---------------------------------------------------------------------------
// Tensor-core projection: per CTA M=128, N=128 (2 heads), K=512 (mma.sync).
// z<=1: direct-from-fragment epilogue (no smem C). z==2: C staging + VT.
// ---------------------------------------------------------------------------
#define KT 32
#define SA 40
#define P_AH 0
#define P_AL (2 * 128 * SA)
#define P_BH (4 * 128 * SA)
#define P_BL (6 * 128 * SA)
#define SC 132
#define P_SMEM_BYTES 81920

__global__ __launch_bounds__(256, 2) void proj_tc_kernel()
{
    extern __shared__ __align__(16) bf16 psm[];
    const int tid = threadIdx.x;
    const int w = tid >> 5, l = tid & 31;
    const int lq = l >> 2, c = l & 3;
    const int wm = w & 3, wn = w >> 2;
    const int z  = blockIdx.x;
    const int hp = blockIdx.y;
    const int m0 = blockIdx.z * 128;
    const int n0 = hp * 128;
    const uint32_t su = (uint32_t)__cvta_generic_to_shared(psm);

    const bf16* WhT = g_WhT[z] + (size_t)n0 * OUTD;
    const bf16* WlT = g_WlT[z] + (size_t)n0 * OUTD;

    auto stage = [&](int kt, int bi) {
        const int k0 = kt * KT;
        #pragma unroll
        for (int it = 0; it < 4; it++) {
            int cid = tid + it * 256;
            int sp = cid >> 9, rem = cid & 511;
            int row = rem >> 2, seg = rem & 3;
            uint32_t dst = su + (uint32_t)(((sp ? P_AL : P_AH) + bi * 128 * SA + row * SA + seg * 8) * 2);
            const bf16* src = (sp ? g_xl : g_xh) + (size_t)(m0 + row) * OUTD + k0 + seg * 8;
            cpasync16(dst, src);
        }
        #pragma unroll
        for (int it = 0; it < 4; it++) {
            int cid = tid + it * 256;
            int sp = cid >> 9, rem = cid & 511;
            int row = rem >> 2, seg = rem & 3;
            uint32_t dst = su + (uint32_t)(((sp ? P_BL : P_BH) + bi * 128 * SA + row * SA + seg * 8) * 2);
            const bf16* src = (sp ? WlT : WhT) + (size_t)row * OUTD + k0 + seg * 8;
            cpasync16(dst, src);
        }
        cpcommit();
    };

    stage(0, 0);

    float acc[2][8][4];
    #pragma unroll
    for (int i = 0; i < 2; i++)
        #pragma unroll
        for (int j = 0; j < 8; j++)
            #pragma unroll
            for (int t = 0; t < 4; t++) acc[i][j][t] = 0.f;

    const int la16 = l & 15;
    const int la8  = l >> 4;
    const int lb8  = l & 7;
    const int lbm  = (l >> 3) & 1;

    for (int kt = 0; kt < OUTD / KT; kt++) {
        if (kt < OUTD / KT - 1) { stage(kt + 1, (kt + 1) & 1); cpwait1(); }
        else cpwait0();
        __syncthreads();
        const int bi = kt & 1;
        const uint32_t ahb = su + (uint32_t)((P_AH + bi * 128 * SA) * 2);
        const uint32_t alb = su + (uint32_t)((P_AL + bi * 128 * SA) * 2);
        const uint32_t bhb = su + (uint32_t)((P_BH + bi * 128 * SA) * 2);
        const uint32_t blb = su + (uint32_t)((P_BL + bi * 128 * SA) * 2);

        #pragma unroll
        for (int hh = 0; hh < 2; hh++) {
            const int kb = hh * 16;
            uint32_t ah[2][4], al[2][4];
            #pragma unroll
            for (int mb = 0; mb < 2; mb++) {
                uint32_t off = (uint32_t)((wm * 32 + mb * 16 + la16) * SA * 2 + (kb + la8 * 8) * 2);
                ldmat4(ah[mb], ahb + off);
                ldmat4(al[mb], alb + off);
            }
            #pragma unroll
            for (int nb = 0; nb < 8; nb++) {
                uint32_t off = (uint32_t)((wn * 64 + nb * 8 + lb8) * SA * 2 + (kb + lbm * 8) * 2);
                uint32_t bh[2], bl[2];
                ldmat2(bh, bhb + off);
                ldmat2(bl, blb + off);
                #pragma unroll
                for (int mb = 0; mb < 2; mb++) {
                    mma16816(acc[mb][nb], ah[mb], bh[0], bh[1]);
                    mma16816(acc[mb][nb], al[mb], bh[0], bh[1]);
                    mma16816(acc[mb][nb], ah[mb], bl[0], bl[1]);
                }
            }
        }
        __syncthreads();
    }

    if (z <= 1) {
        // ---- direct-from-fragment epilogue for Q (z=0) / K (z=1) ----
        bf16* GH = z ? g_Kh : g_Qh;
        bf16* GL = z ? g_Kl : g_Ql;
        const float fac = z ? 1.f : (SCALE * LOG2E);
        #pragma unroll
        for (int mb = 0; mb < 2; mb++) {
            #pragma unroll
            for (int rh = 0; rh < 2; rh++) {
                int r = wm * 32 + mb * 16 + lq + rh * 8;
                int m = m0 + r;
                int b = m / MPB;
                int t = m - b * MPB;
                if (t >= SEQL) continue;
                int iq = t >> 2, r4 = t & 3;
                #pragma unroll
                for (int nb = 0; nb < 8; nb++) {
                    int col = wn * 64 + nb * 8 + c * 2;
                    int head = hp * 2 + (col >> 6);
                    int d = col & 63;
                    int combo = (b * NHEAD + head) * RATE + r4;
                    size_t o = ((size_t)combo * NSUBP + iq) * 64 + d;
                    float v0 = acc[mb][nb][rh * 2 + 0] * fac;
                    float v1 = acc[mb][nb][rh * 2 + 1] * fac;
                    float h0 = __bfloat162float(__float2bfloat16(v0));
                    float h1 = __bfloat162float(__float2bfloat16(v1));
                    *(uint32_t*)(GH + o) = packbf(h1, h0);
                    *(uint32_t*)(GL + o) = packbf(v1 - h1, v0 - h0);
                }
            }
        }
        return;
    }

    // ---- z==2: stage C in smem, then Vf row-major + VT transposed ----
    float* C = (float*)psm;
    #pragma unroll
    for (int mb = 0; mb < 2; mb++) {
        int r0 = wm * 32 + mb * 16 + lq;
        #pragma unroll
        for (int nb = 0; nb < 8; nb++) {
            int col = wn * 64 + nb * 8 + c * 2;
            *(float2*)(C + r0 * SC + col)       = make_float2(acc[mb][nb][0], acc[mb][nb][1]);
            *(float2*)(C + (r0 + 8) * SC + col) = make_float2(acc[mb][nb][2], acc[mb][nb][3]);
        }
    }
    __syncthreads();

    const int bb = m0 / MPB;
    const int t0 = m0 - bb * MPB;
    const bool fast = ((m0 + 127) / MPB == bb) && (t0 + 128 <= SEQL);

    if (fast) {
        const int iq0 = t0 >> 2;
        {
            int r = tid >> 1, hh2 = tid & 1;
            int head = hp * 2 + hh2;
            int t = t0 + r;
            int iq = t >> 2, r4 = t & 3;
            int combo = (bb * NHEAD + head) * RATE + r4;
            size_t orow = ((size_t)combo * NSUBP + iq) * 64;
            #pragma unroll
            for (int j = 0; j < 16; j++)
                *(float4*)(g_Vf + orow + j * 4) = *(const float4*)(C + r * SC + hh2 * 64 + j * 4);
        }
        {
            int hh2 = tid & 1;
            int head = hp * 2 + hh2;
            int tid2 = tid >> 1;
            int g = tid2 & 7, r4 = (tid2 >> 3) & 3, dl = tid2 >> 5;
            int combo = (bb * NHEAD + head) * RATE + r4;
            #pragma unroll
            for (int it = 0; it < 16; it++) {
                int d = it * 4 + dl;
                float v[4], hi[4];
                #pragma unroll
                for (int j = 0; j < 4; j++) {
                    int r = (g * 4 + j) * 4 + r4;
                    v[j] = C[r * SC + hh2 * 64 + d];
                    hi[j] = __bfloat162float(__float2bfloat16(v[j]));
                }
                uint2 uh = make_uint2(packbf(hi[1], hi[0]), packbf(hi[3], hi[2]));
                uint2 ul = make_uint2(packbf(v[1] - hi[1], v[0] - hi[0]),
                                      packbf(v[3] - hi[3], v[2] - hi[2]));
                size_t o = ((size_t)combo * 64 + d) * NSUBP + iq0 + g * 4;
                *(uint2*)(g_VTh + o) = uh;
                *(uint2*)(g_VTl + o) = ul;
            }
        }
    } else {
        int r = tid >> 1, hh2 = tid & 1;
        int head = hp * 2 + hh2;
        int m = m0 + r;
        int b = m / MPB;
        int t = m - b * MPB;
        if (t < SEQL) {
            int iq = t >> 2, r4 = t & 3;
            int combo = (b * NHEAD + head) * RATE + r4;
            size_t orow = ((size_t)combo * NSUBP + iq) * 64;
            #pragma unroll
            for (int j = 0; j < 16; j++) {
                int d = j * 4;
                float4 v = *(const float4*)(C + r * SC + hh2 * 64 + d);
                float vf[4] = {v.x, v.y, v.z, v.w};
                float h0 = __bfloat162float(__float2bfloat16(vf[0]));
                float h1 = __bfloat162float(__float2bfloat16(vf[1]));
                float h2 = __bfloat162float(__float2bfloat16(vf[2]));
                float h3 = __bfloat162float(__float2bfloat16(vf[3]));
                *(float4*)(g_Vf + orow + d) = v;
                float hs[4] = {h0, h1, h2, h3};
                #pragma unroll
                for (int e = 0; e < 4; e++) {
                    size_t ot = ((size_t)combo * 64 + d + e) * NSUBP + iq;
                    g_VTh[ot] = __float2bfloat16(hs[e]);
                    g_VTl[ot] = __float2bfloat16(vf[e] - hs[e]);
                }
            }
        }
    }
}

// ---------------------------------------------------------------------------
// Flash attention: R7 version (best measured: 220us).
// ---------------------------------------------------------------------------
#define SM_QH 0
#define SM_QL (BQ * SK)
#define SM_BUF (2 * BQ * SK)
#define BUF_SZ (4 * 64 * SK)
#define SMEM_BYTES ((SM_BUF + 2 * BUF_SZ) * 2)   // 110592

__global__ __launch_bounds__(256, 2) void attn_kernel(float* __restrict__ out)
{
    extern __shared__ __align__(16) bf16 sm[];
    bf16* QhS = sm + SM_QH;
    bf16* QlS = sm + SM_QL;

    const int tid = threadIdx.x;
    const int w = tid >> 5, l = tid & 31;
    const int lq = l >> 2;
    const int c  = l & 3;
    const int combo = blockIdx.y;
    const int q0 = blockIdx.x * BQ;
    const uint32_t smem_u32 = (uint32_t)__cvta_generic_to_shared(sm);

    const size_t gq = (size_t)combo * NSUBP * 64;
    const size_t gvt = (size_t)combo * 64 * NSUBP;

    #pragma unroll
    for (int it = 0; it < 8; it++) {
        int cid = tid + it * 256;
        int arr = cid >> 10;
        int rem = cid & 1023;
        int row = rem >> 3, seg = rem & 7;
        uint32_t dst = smem_u32 + (uint32_t)(((arr ? SM_QL : SM_QH) + row * SK) * 2 + seg * 16);
        const bf16* src = (arr ? g_Ql : g_Qh) + gq + (size_t)(q0 + row) * 64 + seg * 8;
        cpasync16(dst, src);
    }
    cpcommit();

    {
        #pragma unroll
        for (int it = 0; it < 8; it++) {
            int cid = tid + it * 256;
            int arr = cid >> 9;
            int rem = cid & 511;
            int row = rem >> 3, seg = rem & 7;
            uint32_t dst = smem_u32 + (uint32_t)((SM_BUF + arr * 64 * SK + row * SK) * 2 + seg * 16);
            const bf16* src;
            if (arr == 0)      src = g_Kh + gq + (size_t)row * 64 + seg * 8;
            else if (arr == 1) src = g_Kl + gq + (size_t)row * 64 + seg * 8;
            else if (arr == 2) src = g_VTh + gvt + (size_t)row * NSUBP + seg * 8;
            else               src = g_VTl + gvt + (size_t)row * NSUBP + seg * 8;
            cpasync16(dst, src);
        }
        cpcommit();
    }
    cpwait0();
    __syncthreads();

    uint32_t qh[4][4], ql[4][4];
    {
        const int la16 = l & 15, la8 = l >> 4;
        uint32_t qhb = smem_u32 + (uint32_t)((SM_QH + (w * 16 + la16) * SK) * 2);
        uint32_t qlb = smem_u32 + (uint32_t)((SM_QL + (w * 16 + la16) * SK) * 2);
        #pragma unroll
        for (int kc = 0; kc < 4; kc++) {
            uint32_t off = (uint32_t)((kc * 16 + la8 * 8) * 2);
            ldmat4(qh[kc], qhb + off);
            ldmat4(ql[kc], qlb + off);
        }
    }

    float oacc[8][4];
    #pragma unroll
    for (int j = 0; j < 8; j++)
        #pragma unroll
        for (int t = 0; t < 4; t++) oacc[j][t] = 0.f;
    float m0 = -NEGBIG, m1 = -NEGBIG, l0 = 0.f, l1 = 0.f;

    const int lrow8 = l & 7;
    const int lcol8 = l >> 3;
    const uint32_t boff_lane = (uint32_t)(lrow8 * SK * 2 + lcol8 * 16);

    for (int kt = 0; kt < 16; kt++) {
        __syncthreads();
        if (kt < 15) {
            const int ks = (kt + 1) * 64;
            const int boff = SM_BUF + ((kt + 1) & 1) * BUF_SZ;
            #pragma unroll
            for (int it = 0; it < 8; it++) {
                int cid = tid + it * 256;
                int arr = cid >> 9;
                int rem = cid & 511;
                int row = rem >> 3, seg = rem & 7;
                uint32_t dst = smem_u32 + (uint32_t)((boff + arr * 64 * SK + row * SK) * 2 + seg * 16);
                const bf16* src;
                if (arr == 0)      src = g_Kh + gq + (size_t)(ks + row) * 64 + seg * 8;
                else if (arr == 1) src = g_Kl + gq + (size_t)(ks + row) * 64 + seg * 8;
                else if (arr == 2) src = g_VTh + gvt + (size_t)row * NSUBP + ks + seg * 8;
                else               src = g_VTl + gvt + (size_t)row * NSUBP + ks + seg * 8;
                cpasync16(dst, src);
            }
            cpcommit();
            cpwait1();
        } else {
            cpwait0();
        }
        __syncthreads();

        const int bufbase = SM_BUF + (kt & 1) * BUF_SZ;
        const uint32_t khb = smem_u32 + (uint32_t)((bufbase) * 2) + boff_lane;
        const uint32_t klb = smem_u32 + (uint32_t)((bufbase + 64 * SK) * 2) + boff_lane;
        const uint32_t vhb = smem_u32 + (uint32_t)((bufbase + 2 * 64 * SK) * 2) + boff_lane;
        const uint32_t vlb = smem_u32 + (uint32_t)((bufbase + 3 * 64 * SK) * 2) + boff_lane;

        float sacc[8][4];
        #pragma unroll
        for (int j = 0; j < 8; j++) {
            #pragma unroll
            for (int t = 0; t < 4; t++) sacc[j][t] = 0.f;
            uint32_t bh[8], bl[8];
            uint32_t a = khb + (uint32_t)(j * 8 * SK * 2);
            ldmat4(bh, a); ldmat4(bh + 4, a + 64);
            uint32_t a2 = klb + (uint32_t)(j * 8 * SK * 2);
            ldmat4(bl, a2); ldmat4(bl + 4, a2 + 64);
            #pragma unroll
            for (int kc = 0; kc < 4; kc++) {
                mma16816(sacc[j], qh[kc], bh[2 * kc], bh[2 * kc + 1]);
                mma16816(sacc[j], ql[kc], bh[2 * kc], bh[2 * kc + 1]);
                mma16816(sacc[j], qh[kc], bl[2 * kc], bl[2 * kc + 1]);
            }
        }

        float rmx0 = -NEGBIG, rmx1 = -NEGBIG;
        #pragma unroll
        for (int j = 0; j < 8; j++) {
            rmx0 = fmaxf(rmx0, fmaxf(sacc[j][0], sacc[j][1]));
            rmx1 = fmaxf(rmx1, fmaxf(sacc[j][2], sacc[j][3]));
        }
        rmx0 = fmaxf(rmx0, __shfl_xor_sync(0xffffffffu, rmx0, 1));
        rmx0 = fmaxf(rmx0, __shfl_xor_sync(0xffffffffu, rmx0, 2));
        rmx1 = fmaxf(rmx1, __shfl_xor_sync(0xffffffffu, rmx1, 1));
        rmx1 = fmaxf(rmx1, __shfl_xor_sync(0xffffffffu, rmx1, 2));

        float mn0 = fmaxf(m0, rmx0), mn1 = fmaxf(m1, rmx1);
        float a0 = exp2f(m0 - mn0), a1 = exp2f(m1 - mn1);
        m0 = mn0; m1 = mn1;
        float s0 = 0.f, s1 = 0.f;
        #pragma unroll
        for (int j = 0; j < 8; j++) {
            sacc[j][0] = exp2f(sacc[j][0] - mn0);
            sacc[j][1] = exp2f(sacc[j][1] - mn0);
            sacc[j][2] = exp2f(sacc[j][2] - mn1);
            sacc[j][3] = exp2f(sacc[j][3] - mn1);
            s0 += sacc[j][0] + sacc[j][1];
            s1 += sacc[j][2] + sacc[j][3];
        }
        s0 += __shfl_xor_sync(0xffffffffu, s0, 1);
        s0 += __shfl_xor_sync(0xffffffffu, s0, 2);
        s1 += __shfl_xor_sync(0xffffffffu, s1, 1);
        s1 += __shfl_xor_sync(0xffffffffu, s1, 2);
        l0 = l0 * a0 + s0;
        l1 = l1 * a1 + s1;
        #pragma unroll
        for (int j = 0; j < 8; j++) {
            oacc[j][0] *= a0; oacc[j][1] *= a0;
            oacc[j][2] *= a1; oacc[j][3] *= a1;
        }

        uint32_t pah[4][4], pal[4][4];
        #pragma unroll
        for (int kc = 0; kc < 4; kc++) {
            int j0 = 2 * kc, j1 = 2 * kc + 1;
            uint32_t h;
            h = packbf(sacc[j0][1], sacc[j0][0]); pah[kc][0] = h;
            pal[kc][0] = packbf(sacc[j0][1] - __uint_as_float(h & 0xffff0000u),
                                sacc[j0][0] - __uint_as_float(h << 16));
            h = packbf(sacc[j0][3], sacc[j0][2]); pah[kc][1] = h;
            pal[kc][1] = packbf(sacc[j0][3] - __uint_as_float(h & 0xffff0000u),
                                sacc[j0][2] - __uint_as_float(h << 16));
            h = packbf(sacc[j1][1], sacc[j1][0]); pah[kc][2] = h;
            pal[kc][2] = packbf(sacc[j1][1] - __uint_as_float(h & 0xffff0000u),
                                sacc[j1][0] - __uint_as_float(h << 16));
            h = packbf(sacc[j1][3], sacc[j1][2]); pah[kc][3] = h;
            pal[kc][3] = packbf(sacc[j1][3] - __uint_as_float(h & 0xffff0000u),
                                sacc[j1][2] - __uint_as_float(h << 16));
        }

        #pragma unroll
        for (int j = 0; j < 8; j++) {
            uint32_t bh[8], bl[8];
            uint32_t a = vhb + (uint32_t)(j * 8 * SK * 2);
            ldmat4(bh, a); ldmat4(bh + 4, a + 64);
            uint32_t a2 = vlb + (uint32_t)(j * 8 * SK * 2);
            ldmat4(bl, a2); ldmat4(bl + 4, a2 + 64);
            #pragma unroll
            for (int kc = 0; kc < 4; kc++) {
                mma16816(oacc[j], pah[kc], bh[2 * kc], bh[2 * kc + 1]);
                mma16816(oacc[j], pal[kc], bh[2 * kc], bh[2 * kc + 1]);
                mma16816(oacc[j], pah[kc], bl[2 * kc], bl[2 * kc + 1]);
            }
        }
    }

    __syncthreads();
    float* Kband = (float*)(sm + SM_BUF);
    float* Vband = Kband + 134 * BSW;
    for (int i = tid; i < 134 * 64; i += 256) {
        int rr = i >> 6, d = i & 63;
        int g = q0 - 3 + rr;
        float kv = 0.f, vv = 0.f;
        if (g >= 0) {
            size_t o = gq + (size_t)g * 64 + d;
            kv = __bfloat162float(g_Kh[o]) + __bfloat162float(g_Kl[o]);
            vv = g_Vf[o];
        }
        Kband[rr * BSW + d] = kv;
        Vband[rr * BSW + d] = vv;
    }
    __syncthreads();

    float bl[2][2];
    #pragma unroll
    for (int rh = 0; rh < 2; rh++) {
        int qlcl = w * 16 + lq + 8 * rh;
        int kk0 = c, kk1 = c + 4;
        float acc0 = 0.f, acc1 = 0.f;
        const float* kb0 = Kband + (qlcl + kk0) * BSW;
        const float* kb1 = Kband + (qlcl + kk1) * BSW;
        #pragma unroll 8
        for (int d = 0; d < 64; d++) {
            float qf = __bfloat162float(QhS[qlcl * SK + d]) + __bfloat162float(QlS[qlcl * SK + d]);
            acc0 += qf * kb0[d];
            if (kk1 < 7) acc1 += qf * kb1[d];
        }
        bl[rh][0] = acc0;
        bl[rh][1] = (kk1 < 7) ? acc1 : -NEGBIG;
    }

    {
        float rmx0 = fmaxf(bl[0][0], bl[0][1]);
        float rmx1 = fmaxf(bl[1][0], bl[1][1]);
        rmx0 = fmaxf(rmx0, __shfl_xor_sync(0xffffffffu, rmx0, 1));
        rmx0 = fmaxf(rmx0, __shfl_xor_sync(0xffffffffu, rmx0, 2));
        rmx1 = fmaxf(rmx1, __shfl_xor_sync(0xffffffffu, rmx1, 1));
        rmx1 = fmaxf(rmx1, __shfl_xor_sync(0xffffffffu, rmx1, 2));
        float mn0 = fmaxf(fmaxf(m0, rmx0), 0.f);
        float mn1 = fmaxf(fmaxf(m1, rmx1), 0.f);
        float a0 = exp2f(m0 - mn0), a1 = exp2f(m1 - mn1);
        m0 = mn0; m1 = mn1;
        float p00 = exp2f(bl[0][0] - mn0);
        float p01 = (c + 4 < 7) ? exp2f(bl[0][1] - mn0) : 0.f;
        float p10 = exp2f(bl[1][0] - mn1);
        float p11 = (c + 4 < 7) ? exp2f(bl[1][1] - mn1) : 0.f;
        float s0 = p00 + p01, s1 = p10 + p11;
        s0 += __shfl_xor_sync(0xffffffffu, s0, 1);
        s0 += __shfl_xor_sync(0xffffffffu, s0, 2);
        s1 += __shfl_xor_sync(0xffffffffu, s1, 1);
        s1 += __shfl_xor_sync(0xffffffffu, s1, 2);
        l0 = l0 * a0 + s0 + exp2f(-mn0);
        l1 = l1 * a1 + s1 + exp2f(-mn1);
        #pragma unroll
        for (int j = 0; j < 8; j++) {
            oacc[j][0] *= a0; oacc[j][1] *= a0;
            oacc[j][2] *= a1; oacc[j][3] *= a1;
        }

        int r0 = w * 16 + lq;
        #pragma unroll
        for (int kk = 0; kk < 7; kk++) {
            int src = (l & ~3) | (kk & 3);
            float pb0 = __shfl_sync(0xffffffffu, (kk < 4) ? p00 : p01, src);
            float pb1 = __shfl_sync(0xffffffffu, (kk < 4) ? p10 : p11, src);
            const float* v0 = Vband + (r0 + kk) * BSW + c * 2;
            const float* v1 = Vband + (r0 + 8 + kk) * BSW + c * 2;
            #pragma unroll
            for (int j = 0; j < 8; j++) {
                float2 a = *(const float2*)(v0 + j * 8);
                float2 bq = *(const float2*)(v1 + j * 8);
                oacc[j][0] += pb0 * a.x; oacc[j][1] += pb0 * a.y;
                oacc[j][2] += pb1 * bq.x; oacc[j][3] += pb1 * bq.y;
            }
        }
    }

    const int b = combo >> 5;
    const int h = (combo >> 2) & 7;
    const int r = combo & 3;
    float inv0 = 1.f / l0, inv1 = 1.f / l1;
    int qg = q0 + w * 16 + lq;
    size_t o0 = ((size_t)(b * SEQL + qg * 4 + r)) * OUTD + h * 64 + c * 2;
    size_t o1 = ((size_t)(b * SEQL + (qg + 8) * 4 + r)) * OUTD + h * 64 + c * 2;
    #pragma unroll
    for (int j = 0; j < 8; j++) {
        *(float2*)(out + o0 + j * 8) = make_float2(oacc[j][0] * inv0, oacc[j][1] * inv0);
        *(float2*)(out + o1 + j * 8) = make_float2(oacc[j][2] * inv1, oacc[j][3] * inv1);
    }
}

// ---------------------------------------------------------------------------
extern "C" void kernel_launch(void* const* d_in, const int* in_sizes, int n_in,
                              void* d_out, int out_size)
{
    const float* x  = (const float*)d_in[0];
    const float* Wq = (const float*)d_in[1];
    const float* Wk = (const float*)d_in[2];
    const float* Wv = (const float*)d_in[3];
    float* out = (float*)d_out;

    cudaFuncSetAttribute(attn_kernel, cudaFuncAttributeMaxDynamicSharedMemorySize, SMEM_BYTES);
    cudaFuncSetAttribute(proj_tc_kernel, cudaFuncAttributeMaxDynamicSharedMemorySize, P_SMEM_BYTES);

    splitx_kernel<<<(BATCH * SEQL * OUTD / 4) / 256, 256>>>(x);
    splitw_kernel<<<dim3(OUTD, 3), 256>>>(Wq, Wk, Wv);

    dim3 pgrid(3, NHEAD / 2, MXP / 128);        // z, head-pair, m-tile
    proj_tc_kernel<<<pgrid, 256, P_SMEM_BYTES>>>();

    dim3 agrid(SEQL / RATE / BQ, NCOMBO);
    attn_kernel<<<agrid, 256, SMEM_BYTES>>>(out);
}

// round 11
// speedup vs baseline: 1.0443x; 1.0081x over previous
#include <cuda_runtime.h>
#include <cuda_bf16.h>
#include <cstdint>

#define BATCH 2
#define SEQL  4096
#define OUTD  512
#define NHEAD 8
#define RATE  4
#define NSUB  1025
#define NSUBP 1088
#define NCOMBO 64
#define SCALE 0.125f
#define LOG2E 1.44269504088896340736f
#define NEGBIG 1e30f

#define MPB   4160
#define MXP   (2 * MPB)     // 8320 = 65 * 128

#define BQ 128
#define SK 72
#define BSW 68

typedef __nv_bfloat16 bf16;

__device__ bf16 g_Qh[(size_t)NCOMBO * NSUBP * 64];
__device__ bf16 g_Ql[(size_t)NCOMBO * NSUBP * 64];
__device__ bf16 g_Kh[(size_t)NCOMBO * NSUBP * 64];
__device__ bf16 g_Kl[(size_t)NCOMBO * NSUBP * 64];
__device__ bf16 g_VTh[(size_t)NCOMBO * 64 * NSUBP];
__device__ bf16 g_VTl[(size_t)NCOMBO * 64 * NSUBP];
__device__ float g_Vf[(size_t)NCOMBO * NSUBP * 64];
__device__ bf16 g_xh[(size_t)MXP * OUTD];
__device__ bf16 g_xl[(size_t)MXP * OUTD];
__device__ bf16 g_WhT[3][OUTD * OUTD];
__device__ bf16 g_WlT[3][OUTD * OUTD];

__device__ __forceinline__ uint32_t packbf(float hi, float lo) {
    uint32_t r; asm("cvt.rn.bf16x2.f32 %0, %1, %2;" : "=r"(r) : "f"(hi), "f"(lo)); return r;
}
__device__ __forceinline__ void cpasync16(uint32_t s, const void* g) {
    asm volatile("cp.async.cg.shared.global [%0], [%1], 16;\n" :: "r"(s), "l"(g));
}
__device__ __forceinline__ void cpcommit() { asm volatile("cp.async.commit_group;\n"); }
__device__ __forceinline__ void cpwait0()  { asm volatile("cp.async.wait_group 0;\n"); }
__device__ __forceinline__ void cpwait1()  { asm volatile("cp.async.wait_group 1;\n"); }

__device__ __forceinline__ void mma16816(float* d, const uint32_t* a, uint32_t b0, uint32_t b1) {
    asm volatile("mma.sync.aligned.m16n8k16.row.col.f32.bf16.bf16.f32 "
        "{%0,%1,%2,%3}, {%4,%5,%6,%7}, {%8,%9}, {%0,%1,%2,%3};"
        : "+f"(d[0]), "+f"(d[1]), "+f"(d[2]), "+f"(d[3])
        : "r"(a[0]), "r"(a[1]), "r"(a[2]), "r"(a[3]), "r"(b0), "r"(b1));
}
__device__ __forceinline__ void ldmat4(uint32_t* r, uint32_t addr) {
    asm volatile("ldmatrix.sync.aligned.m8n8.x4.shared.b16 {%0,%1,%2,%3}, [%4];"
        : "=r"(r[0]), "=r"(r[1]), "=r"(r[2]), "=r"(r[3]) : "r"(addr));
}

// ---------------------------------------------------------------------------
__global__ __launch_bounds__(256) void splitx_kernel(const float* __restrict__ x)
{
    int idx = blockIdx.x * 256 + threadIdx.x;
    int flat = idx * 4;
    int b = flat / (SEQL * OUTD);
    int rem = flat - b * (SEQL * OUTD);
    int t = rem / OUTD;
    int k = rem - t * OUTD;
    float4 v = *(const float4*)(x + (size_t)flat);
    size_t o = ((size_t)(b * MPB + t)) * OUTD + k;
    float hx = __bfloat162float(__float2bfloat16(v.x));
    float hy = __bfloat162float(__float2bfloat16(v.y));
    float hz = __bfloat162float(__float2bfloat16(v.z));
    float hw = __bfloat162float(__float2bfloat16(v.w));
    *(uint2*)(g_xh + o) = make_uint2(packbf(hy, hx), packbf(hw, hz));
    *(uint2*)(g_xl + o) = make_uint2(packbf(v.y - hy, v.x - hx), packbf(v.w - hw, v.z - hz));
}

__global__ __launch_bounds__(256) void splitw_kernel(
    const float* __restrict__ Wq, const float* __restrict__ Wk, const float* __restrict__ Wv)
{
    int k = blockIdx.x, z = blockIdx.y;
    const float* W = (z == 0) ? Wq : (z == 1) ? Wk : Wv;
    #pragma unroll
    for (int half = 0; half < 2; half++) {
        int n = threadIdx.x + half * 256;
        float v = W[(size_t)k * OUTD + n];
        bf16 h = __float2bfloat16(v);
        g_WhT[z][(size_t)n * OUTD + k] = h;
        g_WlT[z][(size_t)n * OUTD + k] = __float2bfloat16(v - __bfloat162float(h));
    }
}

// ---------------------------------------------------------------------------
// Tensor-core projection: per CTA M=128, N=128 (2 heads), K=512 (mma.sync).
// B fragments now loaded with ldmat4 over nb-pairs (24 LDSM/warp/kt, was 48).
// ---------------------------------------------------------------------------
#define KT 32
#define SA 40
#define P_AH 0
#define P_AL (2 * 128 * SA)
#define P_BH (4 * 128 * SA)
#define P_BL (6 * 128 * SA)
#define SC 132
#define P_SMEM_BYTES 81920

__global__ __launch_bounds__(256, 2) void proj_tc_kernel()
{
    extern __shared__ __align__(16) bf16 psm[];
    const int tid = threadIdx.x;
    const int w = tid >> 5, l = tid & 31;
    const int lq = l >> 2, c = l & 3;
    const int wm = w & 3, wn = w >> 2;
    const int z  = blockIdx.x;
    const int hp = blockIdx.y;
    const int m0 = blockIdx.z * 128;
    const int n0 = hp * 128;
    const uint32_t su = (uint32_t)__cvta_generic_to_shared(psm);

    const bf16* WhT = g_WhT[z] + (size_t)n0 * OUTD;
    const bf16* WlT = g_WlT[z] + (size_t)n0 * OUTD;

    auto stage = [&](int kt, int bi) {
        const int k0 = kt * KT;
        #pragma unroll
        for (int it = 0; it < 4; it++) {
            int cid = tid + it * 256;
            int sp = cid >> 9, rem = cid & 511;
            int row = rem >> 2, seg = rem & 3;
            uint32_t dst = su + (uint32_t)(((sp ? P_AL : P_AH) + bi * 128 * SA + row * SA + seg * 8) * 2);
            const bf16* src = (sp ? g_xl : g_xh) + (size_t)(m0 + row) * OUTD + k0 + seg * 8;
            cpasync16(dst, src);
        }
        #pragma unroll
        for (int it = 0; it < 4; it++) {
            int cid = tid + it * 256;
            int sp = cid >> 9, rem = cid & 511;
            int row = rem >> 2, seg = rem & 3;
            uint32_t dst = su + (uint32_t)(((sp ? P_BL : P_BH) + bi * 128 * SA + row * SA + seg * 8) * 2);
            const bf16* src = (sp ? WlT : WhT) + (size_t)row * OUTD + k0 + seg * 8;
            cpasync16(dst, src);
        }
        cpcommit();
    };

    stage(0, 0);

    float acc[2][8][4];
    #pragma unroll
    for (int i = 0; i < 2; i++)
        #pragma unroll
        for (int j = 0; j < 8; j++)
            #pragma unroll
            for (int t = 0; t < 4; t++) acc[i][j][t] = 0.f;

    // ldmatrix lane mapping
    const int la16 = l & 15;            // A rows
    const int la8  = l >> 4;            // A k-half
    const int rB   = ((l >> 4) << 3) + (l & 7);   // B row offset within nbp pair
    const int cB8  = ((l >> 3) & 1) * 8;          // B k-half offset

    for (int kt = 0; kt < OUTD / KT; kt++) {
        if (kt < OUTD / KT - 1) { stage(kt + 1, (kt + 1) & 1); cpwait1(); }
        else cpwait0();
        __syncthreads();
        const int bi = kt & 1;
        const uint32_t ahb = su + (uint32_t)((P_AH + bi * 128 * SA) * 2);
        const uint32_t alb = su + (uint32_t)((P_AL + bi * 128 * SA) * 2);
        const uint32_t bhb = su + (uint32_t)((P_BH + bi * 128 * SA) * 2);
        const uint32_t blb = su + (uint32_t)((P_BL + bi * 128 * SA) * 2);

        #pragma unroll
        for (int hh = 0; hh < 2; hh++) {
            const int kb = hh * 16;
            uint32_t ah[2][4], al[2][4];
            #pragma unroll
            for (int mb = 0; mb < 2; mb++) {
                uint32_t off = (uint32_t)((wm * 32 + mb * 16 + la16) * SA * 2 + (kb + la8 * 8) * 2);
                ldmat4(ah[mb], ahb + off);
                ldmat4(al[mb], alb + off);
            }
            #pragma unroll
            for (int nbp = 0; nbp < 4; nbp++) {
                uint32_t off = (uint32_t)((wn * 64 + nbp * 16 + rB) * SA * 2 + (kb + cB8) * 2);
                uint32_t bh4[4], bl4[4];
                ldmat4(bh4, bhb + off);
                ldmat4(bl4, blb + off);
                #pragma unroll
                for (int half = 0; half < 2; half++) {
                    int nb = nbp * 2 + half;
                    #pragma unroll
                    for (int mb = 0; mb < 2; mb++) {
                        mma16816(acc[mb][nb], ah[mb], bh4[2 * half], bh4[2 * half + 1]);
                        mma16816(acc[mb][nb], al[mb], bh4[2 * half], bh4[2 * half + 1]);
                        mma16816(acc[mb][nb], ah[mb], bl4[2 * half], bl4[2 * half + 1]);
                    }
                }
            }
        }
        __syncthreads();
    }

    if (z <= 1) {
        // ---- direct-from-fragment epilogue for Q (z=0) / K (z=1) ----
        bf16* GH = z ? g_Kh : g_Qh;
        bf16* GL = z ? g_Kl : g_Ql;
        const float fac = z ? 1.f : (SCALE * LOG2E);
        #pragma unroll
        for (int mb = 0; mb < 2; mb++) {
            #pragma unroll
            for (int rh = 0; rh < 2; rh++) {
                int r = wm * 32 + mb * 16 + lq + rh * 8;
                int m = m0 + r;
                int b = m / MPB;
                int t = m - b * MPB;
                if (t >= SEQL) continue;
                int iq = t >> 2, r4 = t & 3;
                #pragma unroll
                for (int nb = 0; nb < 8; nb++) {
                    int col = wn * 64 + nb * 8 + c * 2;
                    int head = hp * 2 + (col >> 6);
                    int d = col & 63;
                    int combo = (b * NHEAD + head) * RATE + r4;
                    size_t o = ((size_t)combo * NSUBP + iq) * 64 + d;
                    float v0 = acc[mb][nb][rh * 2 + 0] * fac;
                    float v1 = acc[mb][nb][rh * 2 + 1] * fac;
                    float h0 = __bfloat162float(__float2bfloat16(v0));
                    float h1 = __bfloat162float(__float2bfloat16(v1));
                    *(uint32_t*)(GH + o) = packbf(h1, h0);
                    *(uint32_t*)(GL + o) = packbf(v1 - h1, v0 - h0);
                }
            }
        }
        return;
    }

    // ---- z==2: stage C in smem, then Vf row-major + VT transposed ----
    float* C = (float*)psm;
    #pragma unroll
    for (int mb = 0; mb < 2; mb++) {
        int r0 = wm * 32 + mb * 16 + lq;
        #pragma unroll
        for (int nb = 0; nb < 8; nb++) {
            int col = wn * 64 + nb * 8 + c * 2;
            *(float2*)(C + r0 * SC + col)       = make_float2(acc[mb][nb][0], acc[mb][nb][1]);
            *(float2*)(C + (r0 + 8) * SC + col) = make_float2(acc[mb][nb][2], acc[mb][nb][3]);
        }
    }
    __syncthreads();

    const int bb = m0 / MPB;
    const int t0 = m0 - bb * MPB;
    const bool fast = ((m0 + 127) / MPB == bb) && (t0 + 128 <= SEQL);

    if (fast) {
        const int iq0 = t0 >> 2;
        {
            int r = tid >> 1, hh2 = tid & 1;
            int head = hp * 2 + hh2;
            int t = t0 + r;
            int iq = t >> 2, r4 = t & 3;
            int combo = (bb * NHEAD + head) * RATE + r4;
            size_t orow = ((size_t)combo * NSUBP + iq) * 64;
            #pragma unroll
            for (int j = 0; j < 16; j++)
                *(float4*)(g_Vf + orow + j * 4) = *(const float4*)(C + r * SC + hh2 * 64 + j * 4);
        }
        {
            int hh2 = tid & 1;
            int head = hp * 2 + hh2;
            int tid2 = tid >> 1;
            int g = tid2 & 7, r4 = (tid2 >> 3) & 3, dl = tid2 >> 5;
            int combo = (bb * NHEAD + head) * RATE + r4;
            #pragma unroll
            for (int it = 0; it < 16; it++) {
                int d = it * 4 + dl;
                float v[4], hi[4];
                #pragma unroll
                for (int j = 0; j < 4; j++) {
                    int r = (g * 4 + j) * 4 + r4;
                    v[j] = C[r * SC + hh2 * 64 + d];
                    hi[j] = __bfloat162float(__float2bfloat16(v[j]));
                }
                uint2 uh = make_uint2(packbf(hi[1], hi[0]), packbf(hi[3], hi[2]));
                uint2 ul = make_uint2(packbf(v[1] - hi[1], v[0] - hi[0]),
                                      packbf(v[3] - hi[3], v[2] - hi[2]));
                size_t o = ((size_t)combo * 64 + d) * NSUBP + iq0 + g * 4;
                *(uint2*)(g_VTh + o) = uh;
                *(uint2*)(g_VTl + o) = ul;
            }
        }
    } else {
        int r = tid >> 1, hh2 = tid & 1;
        int head = hp * 2 + hh2;
        int m = m0 + r;
        int b = m / MPB;
        int t = m - b * MPB;
        if (t < SEQL) {
            int iq = t >> 2, r4 = t & 3;
            int combo = (b * NHEAD + head) * RATE + r4;
            size_t orow = ((size_t)combo * NSUBP + iq) * 64;
            #pragma unroll
            for (int j = 0; j < 16; j++) {
                int d = j * 4;
                float4 v = *(const float4*)(C + r * SC + hh2 * 64 + d);
                float vf[4] = {v.x, v.y, v.z, v.w};
                float h0 = __bfloat162float(__float2bfloat16(vf[0]));
                float h1 = __bfloat162float(__float2bfloat16(vf[1]));
                float h2 = __bfloat162float(__float2bfloat16(vf[2]));
                float h3 = __bfloat162float(__float2bfloat16(vf[3]));
                *(float4*)(g_Vf + orow + d) = v;
                float hs[4] = {h0, h1, h2, h3};
                #pragma unroll
                for (int e = 0; e < 4; e++) {
                    size_t ot = ((size_t)combo * 64 + d + e) * NSUBP + iq;
                    g_VTh[ot] = __float2bfloat16(hs[e]);
                    g_VTl[ot] = __float2bfloat16(vf[e] - hs[e]);
                }
            }
        }
    }
}

// ---------------------------------------------------------------------------
// Flash attention: R7 version (best measured).
// ---------------------------------------------------------------------------
#define SM_QH 0
#define SM_QL (BQ * SK)
#define SM_BUF (2 * BQ * SK)
#define BUF_SZ (4 * 64 * SK)
#define SMEM_BYTES ((SM_BUF + 2 * BUF_SZ) * 2)   // 110592

__global__ __launch_bounds__(256, 2) void attn_kernel(float* __restrict__ out)
{
    extern __shared__ __align__(16) bf16 sm[];
    bf16* QhS = sm + SM_QH;
    bf16* QlS = sm + SM_QL;

    const int tid = threadIdx.x;
    const int w = tid >> 5, l = tid & 31;
    const int lq = l >> 2;
    const int c  = l & 3;
    const int combo = blockIdx.y;
    const int q0 = blockIdx.x * BQ;
    const uint32_t smem_u32 = (uint32_t)__cvta_generic_to_shared(sm);

    const size_t gq = (size_t)combo * NSUBP * 64;
    const size_t gvt = (size_t)combo * 64 * NSUBP;

    #pragma unroll
    for (int it = 0; it < 8; it++) {
        int cid = tid + it * 256;
        int arr = cid >> 10;
        int rem = cid & 1023;
        int row = rem >> 3, seg = rem & 7;
        uint32_t dst = smem_u32 + (uint32_t)(((arr ? SM_QL : SM_QH) + row * SK) * 2 + seg * 16);
        const bf16* src = (arr ? g_Ql : g_Qh) + gq + (size_t)(q0 + row) * 64 + seg * 8;
        cpasync16(dst, src);
    }
    cpcommit();

    {
        #pragma unroll
        for (int it = 0; it < 8; it++) {
            int cid = tid + it * 256;
            int arr = cid >> 9;
            int rem = cid & 511;
            int row = rem >> 3, seg = rem & 7;
            uint32_t dst = smem_u32 + (uint32_t)((SM_BUF + arr * 64 * SK + row * SK) * 2 + seg * 16);
            const bf16* src;
            if (arr == 0)      src = g_Kh + gq + (size_t)row * 64 + seg * 8;
            else if (arr == 1) src = g_Kl + gq + (size_t)row * 64 + seg * 8;
            else if (arr == 2) src = g_VTh + gvt + (size_t)row * NSUBP + seg * 8;
            else               src = g_VTl + gvt + (size_t)row * NSUBP + seg * 8;
            cpasync16(dst, src);
        }
        cpcommit();
    }
    cpwait0();
    __syncthreads();

    uint32_t qh[4][4], ql[4][4];
    {
        const int la16 = l & 15, la8 = l >> 4;
        uint32_t qhb = smem_u32 + (uint32_t)((SM_QH + (w * 16 + la16) * SK) * 2);
        uint32_t qlb = smem_u32 + (uint32_t)((SM_QL + (w * 16 + la16) * SK) * 2);
        #pragma unroll
        for (int kc = 0; kc < 4; kc++) {
            uint32_t off = (uint32_t)((kc * 16 + la8 * 8) * 2);
            ldmat4(qh[kc], qhb + off);
            ldmat4(ql[kc], qlb + off);
        }
    }

    float oacc[8][4];
    #pragma unroll
    for (int j = 0; j < 8; j++)
        #pragma unroll
        for (int t = 0; t < 4; t++) oacc[j][t] = 0.f;
    float m0 = -NEGBIG, m1 = -NEGBIG, l0 = 0.f, l1 = 0.f;

    const int lrow8 = l & 7;
    const int lcol8 = l >> 3;
    const uint32_t boff_lane = (uint32_t)(lrow8 * SK * 2 + lcol8 * 16);

    for (int kt = 0; kt < 16; kt++) {
        __syncthreads();
        if (kt < 15) {
            const int ks = (kt + 1) * 64;
            const int boff = SM_BUF + ((kt + 1) & 1) * BUF_SZ;
            #pragma unroll
            for (int it = 0; it < 8; it++) {
                int cid = tid + it * 256;
                int arr = cid >> 9;
                int rem = cid & 511;
                int row = rem >> 3, seg = rem & 7;
                uint32_t dst = smem_u32 + (uint32_t)((boff + arr * 64 * SK + row * SK) * 2 + seg * 16);
                const bf16* src;
                if (arr == 0)      src = g_Kh + gq + (size_t)(ks + row) * 64 + seg * 8;
                else if (arr == 1) src = g_Kl + gq + (size_t)(ks + row) * 64 + seg * 8;
                else if (arr == 2) src = g_VTh + gvt + (size_t)row * NSUBP + ks + seg * 8;
                else               src = g_VTl + gvt + (size_t)row * NSUBP + ks + seg * 8;
                cpasync16(dst, src);
            }
            cpcommit();
            cpwait1();
        } else {
            cpwait0();
        }
        __syncthreads();

        const int bufbase = SM_BUF + (kt & 1) * BUF_SZ;
        const uint32_t khb = smem_u32 + (uint32_t)((bufbase) * 2) + boff_lane;
        const uint32_t klb = smem_u32 + (uint32_t)((bufbase + 64 * SK) * 2) + boff_lane;
        const uint32_t vhb = smem_u32 + (uint32_t)((bufbase + 2 * 64 * SK) * 2) + boff_lane;
        const uint32_t vlb = smem_u32 + (uint32_t)((bufbase + 3 * 64 * SK) * 2) + boff_lane;

        float sacc[8][4];
        #pragma unroll
        for (int j = 0; j < 8; j++) {
            #pragma unroll
            for (int t = 0; t < 4; t++) sacc[j][t] = 0.f;
            uint32_t bh[8], bl[8];
            uint32_t a = khb + (uint32_t)(j * 8 * SK * 2);
            ldmat4(bh, a); ldmat4(bh + 4, a + 64);
            uint32_t a2 = klb + (uint32_t)(j * 8 * SK * 2);
            ldmat4(bl, a2); ldmat4(bl + 4, a2 + 64);
            #pragma unroll
            for (int kc = 0; kc < 4; kc++) {
                mma16816(sacc[j], qh[kc], bh[2 * kc], bh[2 * kc + 1]);
                mma16816(sacc[j], ql[kc], bh[2 * kc], bh[2 * kc + 1]);
                mma16816(sacc[j], qh[kc], bl[2 * kc], bl[2 * kc + 1]);
            }
        }

        float rmx0 = -NEGBIG, rmx1 = -NEGBIG;
        #pragma unroll
        for (int j = 0; j < 8; j++) {
            rmx0 = fmaxf(rmx0, fmaxf(sacc[j][0], sacc[j][1]));
            rmx1 = fmaxf(rmx1, fmaxf(sacc[j][2], sacc[j][3]));
        }
        rmx0 = fmaxf(rmx0, __shfl_xor_sync(0xffffffffu, rmx0, 1));
        rmx0 = fmaxf(rmx0, __shfl_xor_sync(0xffffffffu, rmx0, 2));
        rmx1 = fmaxf(rmx1, __shfl_xor_sync(0xffffffffu, rmx1, 1));
        rmx1 = fmaxf(rmx1, __shfl_xor_sync(0xffffffffu, rmx1, 2));

        float mn0 = fmaxf(m0, rmx0), mn1 = fmaxf(m1, rmx1);
        float a0 = exp2f(m0 - mn0), a1 = exp2f(m1 - mn1);
        m0 = mn0; m1 = mn1;
        float s0 = 0.f, s1 = 0.f;
        #pragma unroll
        for (int j = 0; j < 8; j++) {
            sacc[j][0] = exp2f(sacc[j][0] - mn0);
            sacc[j][1] = exp2f(sacc[j][1] - mn0);
            sacc[j][2] = exp2f(sacc[j][2] - mn1);
            sacc[j][3] = exp2f(sacc[j][3] - mn1);
            s0 += sacc[j][0] + sacc[j][1];
            s1 += sacc[j][2] + sacc[j][3];
        }
        s0 += __shfl_xor_sync(0xffffffffu, s0, 1);
        s0 += __shfl_xor_sync(0xffffffffu, s0, 2);
        s1 += __shfl_xor_sync(0xffffffffu, s1, 1);
        s1 += __shfl_xor_sync(0xffffffffu, s1, 2);
        l0 = l0 * a0 + s0;
        l1 = l1 * a1 + s1;
        #pragma unroll
        for (int j = 0; j < 8; j++) {
            oacc[j][0] *= a0; oacc[j][1] *= a0;
            oacc[j][2] *= a1; oacc[j][3] *= a1;
        }

        uint32_t pah[4][4], pal[4][4];
        #pragma unroll
        for (int kc = 0; kc < 4; kc++) {
            int j0 = 2 * kc, j1 = 2 * kc + 1;
            uint32_t h;
            h = packbf(sacc[j0][1], sacc[j0][0]); pah[kc][0] = h;
            pal[kc][0] = packbf(sacc[j0][1] - __uint_as_float(h & 0xffff0000u),
                                sacc[j0][0] - __uint_as_float(h << 16));
            h = packbf(sacc[j0][3], sacc[j0][2]); pah[kc][1] = h;
            pal[kc][1] = packbf(sacc[j0][3] - __uint_as_float(h & 0xffff0000u),
                                sacc[j0][2] - __uint_as_float(h << 16));
            h = packbf(sacc[j1][1], sacc[j1][0]); pah[kc][2] = h;
            pal[kc][2] = packbf(sacc[j1][1] - __uint_as_float(h & 0xffff0000u),
                                sacc[j1][0] - __uint_as_float(h << 16));
            h = packbf(sacc[j1][3], sacc[j1][2]); pah[kc][3] = h;
            pal[kc][3] = packbf(sacc[j1][3] - __uint_as_float(h & 0xffff0000u),
                                sacc[j1][2] - __uint_as_float(h << 16));
        }

        #pragma unroll
        for (int j = 0; j < 8; j++) {
            uint32_t bh[8], bl[8];
            uint32_t a = vhb + (uint32_t)(j * 8 * SK * 2);
            ldmat4(bh, a); ldmat4(bh + 4, a + 64);
            uint32_t a2 = vlb + (uint32_t)(j * 8 * SK * 2);
            ldmat4(bl, a2); ldmat4(bl + 4, a2 + 64);
            #pragma unroll
            for (int kc = 0; kc < 4; kc++) {
                mma16816(oacc[j], pah[kc], bh[2 * kc], bh[2 * kc + 1]);
                mma16816(oacc[j], pal[kc], bh[2 * kc], bh[2 * kc + 1]);
                mma16816(oacc[j], pah[kc], bl[2 * kc], bl[2 * kc + 1]);
            }
        }
    }

    __syncthreads();
    float* Kband = (float*)(sm + SM_BUF);
    float* Vband = Kband + 134 * BSW;
    for (int i = tid; i < 134 * 64; i += 256) {
        int rr = i >> 6, d = i & 63;
        int g = q0 - 3 + rr;
        float kv = 0.f, vv = 0.f;
        if (g >= 0) {
            size_t o = gq + (size_t)g * 64 + d;
            kv = __bfloat162float(g_Kh[o]) + __bfloat162float(g_Kl[o]);
            vv = g_Vf[o];
        }
        Kband[rr * BSW + d] = kv;
        Vband[rr * BSW + d] = vv;
    }
    __syncthreads();

    float bl[2][2];
    #pragma unroll
    for (int rh = 0; rh < 2; rh++) {
        int qlcl = w * 16 + lq + 8 * rh;
        int kk0 = c, kk1 = c + 4;
        float acc0 = 0.f, acc1 = 0.f;
        const float* kb0 = Kband + (qlcl + kk0) * BSW;
        const float* kb1 = Kband + (qlcl + kk1) * BSW;
        #pragma unroll 8
        for (int d = 0; d < 64; d++) {
            float qf = __bfloat162float(QhS[qlcl * SK + d]) + __bfloat162float(QlS[qlcl * SK + d]);
            acc0 += qf * kb0[d];
            if (kk1 < 7) acc1 += qf * kb1[d];
        }
        bl[rh][0] = acc0;
        bl[rh][1] = (kk1 < 7) ? acc1 : -NEGBIG;
    }

    {
        float rmx0 = fmaxf(bl[0][0], bl[0][1]);
        float rmx1 = fmaxf(bl[1][0], bl[1][1]);
        rmx0 = fmaxf(rmx0, __shfl_xor_sync(0xffffffffu, rmx0, 1));
        rmx0 = fmaxf(rmx0, __shfl_xor_sync(0xffffffffu, rmx0, 2));
        rmx1 = fmaxf(rmx1, __shfl_xor_sync(0xffffffffu, rmx1, 1));
        rmx1 = fmaxf(rmx1, __shfl_xor_sync(0xffffffffu, rmx1, 2));
        float mn0 = fmaxf(fmaxf(m0, rmx0), 0.f);
        float mn1 = fmaxf(fmaxf(m1, rmx1), 0.f);
        float a0 = exp2f(m0 - mn0), a1 = exp2f(m1 - mn1);
        m0 = mn0; m1 = mn1;
        float p00 = exp2f(bl[0][0] - mn0);
        float p01 = (c + 4 < 7) ? exp2f(bl[0][1] - mn0) : 0.f;
        float p10 = exp2f(bl[1][0] - mn1);
        float p11 = (c + 4 < 7) ? exp2f(bl[1][1] - mn1) : 0.f;
        float s0 = p00 + p01, s1 = p10 + p11;
        s0 += __shfl_xor_sync(0xffffffffu, s0, 1);
        s0 += __shfl_xor_sync(0xffffffffu, s0, 2);
        s1 += __shfl_xor_sync(0xffffffffu, s1, 1);
        s1 += __shfl_xor_sync(0xffffffffu, s1, 2);
        l0 = l0 * a0 + s0 + exp2f(-mn0);
        l1 = l1 * a1 + s1 + exp2f(-mn1);
        #pragma unroll
        for (int j = 0; j < 8; j++) {
            oacc[j][0] *= a0; oacc[j][1] *= a0;
            oacc[j][2] *= a1; oacc[j][3] *= a1;
        }

        int r0 = w * 16 + lq;
        #pragma unroll
        for (int kk = 0; kk < 7; kk++) {
            int src = (l & ~3) | (kk & 3);
            float pb0 = __shfl_sync(0xffffffffu, (kk < 4) ? p00 : p01, src);
            float pb1 = __shfl_sync(0xffffffffu, (kk < 4) ? p10 : p11, src);
            const float* v0 = Vband + (r0 + kk) * BSW + c * 2;
            const float* v1 = Vband + (r0 + 8 + kk) * BSW + c * 2;
            #pragma unroll
            for (int j = 0; j < 8; j++) {
                float2 a = *(const float2*)(v0 + j * 8);
                float2 bq = *(const float2*)(v1 + j * 8);
                oacc[j][0] += pb0 * a.x; oacc[j][1] += pb0 * a.y;
                oacc[j][2] += pb1 * bq.x; oacc[j][3] += pb1 * bq.y;
            }
        }
    }

    const int b = combo >> 5;
    const int h = (combo >> 2) & 7;
    const int r = combo & 3;
    float inv0 = 1.f / l0, inv1 = 1.f / l1;
    int qg = q0 + w * 16 + lq;
    size_t o0 = ((size_t)(b * SEQL + qg * 4 + r)) * OUTD + h * 64 + c * 2;
    size_t o1 = ((size_t)(b * SEQL + (qg + 8) * 4 + r)) * OUTD + h * 64 + c * 2;
    #pragma unroll
    for (int j = 0; j < 8; j++) {
        *(float2*)(out + o0 + j * 8) = make_float2(oacc[j][0] * inv0, oacc[j][1] * inv0);
        *(float2*)(out + o1 + j * 8) = make_float2(oacc[j][2] * inv1, oacc[j][3] * inv1);
    }
}

// ---------------------------------------------------------------------------
extern "C" void kernel_launch(void* const* d_in, const int* in_sizes, int n_in,
                              void* d_out, int out_size)
{
    const float* x  = (const float*)d_in[0];
    const float* Wq = (const float*)d_in[1];
    const float* Wk = (const float*)d_in[2];
    const float* Wv = (const float*)d_in[3];
    float* out = (float*)d_out;

    cudaFuncSetAttribute(attn_kernel, cudaFuncAttributeMaxDynamicSharedMemorySize, SMEM_BYTES);
    cudaFuncSetAttribute(proj_tc_kernel, cudaFuncAttributeMaxDynamicSharedMemorySize, P_SMEM_BYTES);

    splitx_kernel<<<(BATCH * SEQL * OUTD / 4) / 256, 256>>>(x);
    splitw_kernel<<<dim3(OUTD, 3), 256>>>(Wq, Wk, Wv);

    dim3 pgrid(3, NHEAD / 2, MXP / 128);        // z, head-pair, m-tile
    proj_tc_kernel<<<pgrid, 256, P_SMEM_BYTES>>>();

    dim3 agrid(SEQL / RATE / BQ, NCOMBO);
    attn_kernel<<<agrid, 256, SMEM_BYTES>>>(out);
}

// round 12
// speedup vs baseline: 1.0817x; 1.0359x over previous
#include <cuda_runtime.h>
#include <cuda_bf16.h>
#include <cstdint>

#define BATCH 2
#define SEQL  4096
#define OUTD  512
#define NHEAD 8
#define RATE  4
#define NSUB  1025
#define NSUBP 1088
#define NCOMBO 64
#define SCALE 0.125f
#define LOG2E 1.44269504088896340736f
#define NEGBIG 1e30f

#define MPB   4160
#define MXP   (2 * MPB)     // 8320 = 65 * 128

#define BQ 128
#define SK 72
#define BSW 68

typedef __nv_bfloat16 bf16;

__device__ bf16 g_Qh[(size_t)NCOMBO * NSUBP * 64];
__device__ bf16 g_Ql[(size_t)NCOMBO * NSUBP * 64];
__device__ bf16 g_Kh[(size_t)NCOMBO * NSUBP * 64];
__device__ bf16 g_Kl[(size_t)NCOMBO * NSUBP * 64];
__device__ bf16 g_VTh[(size_t)NCOMBO * 64 * NSUBP];
__device__ bf16 g_VTl[(size_t)NCOMBO * 64 * NSUBP];
__device__ float g_Vf[(size_t)NCOMBO * NSUBP * 64];
__device__ bf16 g_xh[(size_t)MXP * OUTD];
__device__ bf16 g_xl[(size_t)MXP * OUTD];
__device__ bf16 g_WhT[3][OUTD * OUTD];
__device__ bf16 g_WlT[3][OUTD * OUTD];

__device__ __forceinline__ uint32_t packbf(float hi, float lo) {
    uint32_t r; asm("cvt.rn.bf16x2.f32 %0, %1, %2;" : "=r"(r) : "f"(hi), "f"(lo)); return r;
}
__device__ __forceinline__ void cpasync16(uint32_t s, const void* g) {
    asm volatile("cp.async.cg.shared.global [%0], [%1], 16;\n" :: "r"(s), "l"(g));
}
__device__ __forceinline__ void cpcommit() { asm volatile("cp.async.commit_group;\n"); }
__device__ __forceinline__ void cpwait0()  { asm volatile("cp.async.wait_group 0;\n"); }
__device__ __forceinline__ void cpwait1()  { asm volatile("cp.async.wait_group 1;\n"); }

__device__ __forceinline__ void mma16816(float* d, const uint32_t* a, uint32_t b0, uint32_t b1) {
    asm volatile("mma.sync.aligned.m16n8k16.row.col.f32.bf16.bf16.f32 "
        "{%0,%1,%2,%3}, {%4,%5,%6,%7}, {%8,%9}, {%0,%1,%2,%3};"
        : "+f"(d[0]), "+f"(d[1]), "+f"(d[2]), "+f"(d[3])
        : "r"(a[0]), "r"(a[1]), "r"(a[2]), "r"(a[3]), "r"(b0), "r"(b1));
}
__device__ __forceinline__ void ldmat4(uint32_t* r, uint32_t addr) {
    asm volatile("ldmatrix.sync.aligned.m8n8.x4.shared.b16 {%0,%1,%2,%3}, [%4];"
        : "=r"(r[0]), "=r"(r[1]), "=r"(r[2]), "=r"(r[3]) : "r"(addr));
}

// ---------------------------------------------------------------------------
__global__ __launch_bounds__(256) void splitx_kernel(const float* __restrict__ x)
{
    int idx = blockIdx.x * 256 + threadIdx.x;
    int flat = idx * 4;
    int b = flat / (SEQL * OUTD);
    int rem = flat - b * (SEQL * OUTD);
    int t = rem / OUTD;
    int k = rem - t * OUTD;
    float4 v = *(const float4*)(x + (size_t)flat);
    size_t o = ((size_t)(b * MPB + t)) * OUTD + k;
    float hx = __bfloat162float(__float2bfloat16(v.x));
    float hy = __bfloat162float(__float2bfloat16(v.y));
    float hz = __bfloat162float(__float2bfloat16(v.z));
    float hw = __bfloat162float(__float2bfloat16(v.w));
    *(uint2*)(g_xh + o) = make_uint2(packbf(hy, hx), packbf(hw, hz));
    *(uint2*)(g_xl + o) = make_uint2(packbf(v.y - hy, v.x - hx), packbf(v.w - hw, v.z - hz));
}

__global__ __launch_bounds__(256) void splitw_kernel(
    const float* __restrict__ Wq, const float* __restrict__ Wk, const float* __restrict__ Wv)
{
    int k = blockIdx.x, z = blockIdx.y;
    const float* W = (z == 0) ? Wq : (z == 1) ? Wk : Wv;
    #pragma unroll
    for (int half = 0; half < 2; half++) {
        int n = threadIdx.x + half * 256;
        float v = W[(size_t)k * OUTD + n];
        bf16 h = __float2bfloat16(v);
        g_WhT[z][(size_t)n * OUTD + k] = h;
        g_WlT[z][(size_t)n * OUTD + k] = __float2bfloat16(v - __bfloat162float(h));
    }
}

// ---------------------------------------------------------------------------
// Tensor-core projection (unchanged from R11 best).
// ---------------------------------------------------------------------------
#define KT 32
#define SA 40
#define P_AH 0
#define P_AL (2 * 128 * SA)
#define P_BH (4 * 128 * SA)
#define P_BL (6 * 128 * SA)
#define SC 132
#define P_SMEM_BYTES 81920

__global__ __launch_bounds__(256, 2) void proj_tc_kernel()
{
    extern __shared__ __align__(16) bf16 psm[];
    const int tid = threadIdx.x;
    const int w = tid >> 5, l = tid & 31;
    const int lq = l >> 2, c = l & 3;
    const int wm = w & 3, wn = w >> 2;
    const int z  = blockIdx.x;
    const int hp = blockIdx.y;
    const int m0 = blockIdx.z * 128;
    const int n0 = hp * 128;
    const uint32_t su = (uint32_t)__cvta_generic_to_shared(psm);

    const bf16* WhT = g_WhT[z] + (size_t)n0 * OUTD;
    const bf16* WlT = g_WlT[z] + (size_t)n0 * OUTD;

    auto stage = [&](int kt, int bi) {
        const int k0 = kt * KT;
        #pragma unroll
        for (int it = 0; it < 4; it++) {
            int cid = tid + it * 256;
            int sp = cid >> 9, rem = cid & 511;
            int row = rem >> 2, seg = rem & 3;
            uint32_t dst = su + (uint32_t)(((sp ? P_AL : P_AH) + bi * 128 * SA + row * SA + seg * 8) * 2);
            const bf16* src = (sp ? g_xl : g_xh) + (size_t)(m0 + row) * OUTD + k0 + seg * 8;
            cpasync16(dst, src);
        }
        #pragma unroll
        for (int it = 0; it < 4; it++) {
            int cid = tid + it * 256;
            int sp = cid >> 9, rem = cid & 511;
            int row = rem >> 2, seg = rem & 3;
            uint32_t dst = su + (uint32_t)(((sp ? P_BL : P_BH) + bi * 128 * SA + row * SA + seg * 8) * 2);
            const bf16* src = (sp ? WlT : WhT) + (size_t)row * OUTD + k0 + seg * 8;
            cpasync16(dst, src);
        }
        cpcommit();
    };

    stage(0, 0);

    float acc[2][8][4];
    #pragma unroll
    for (int i = 0; i < 2; i++)
        #pragma unroll
        for (int j = 0; j < 8; j++)
            #pragma unroll
            for (int t = 0; t < 4; t++) acc[i][j][t] = 0.f;

    const int la16 = l & 15;
    const int la8  = l >> 4;
    const int rB   = ((l >> 4) << 3) + (l & 7);
    const int cB8  = ((l >> 3) & 1) * 8;

    for (int kt = 0; kt < OUTD / KT; kt++) {
        if (kt < OUTD / KT - 1) { stage(kt + 1, (kt + 1) & 1); cpwait1(); }
        else cpwait0();
        __syncthreads();
        const int bi = kt & 1;
        const uint32_t ahb = su + (uint32_t)((P_AH + bi * 128 * SA) * 2);
        const uint32_t alb = su + (uint32_t)((P_AL + bi * 128 * SA) * 2);
        const uint32_t bhb = su + (uint32_t)((P_BH + bi * 128 * SA) * 2);
        const uint32_t blb = su + (uint32_t)((P_BL + bi * 128 * SA) * 2);

        #pragma unroll
        for (int hh = 0; hh < 2; hh++) {
            const int kb = hh * 16;
            uint32_t ah[2][4], al[2][4];
            #pragma unroll
            for (int mb = 0; mb < 2; mb++) {
                uint32_t off = (uint32_t)((wm * 32 + mb * 16 + la16) * SA * 2 + (kb + la8 * 8) * 2);
                ldmat4(ah[mb], ahb + off);
                ldmat4(al[mb], alb + off);
            }
            #pragma unroll
            for (int nbp = 0; nbp < 4; nbp++) {
                uint32_t off = (uint32_t)((wn * 64 + nbp * 16 + rB) * SA * 2 + (kb + cB8) * 2);
                uint32_t bh4[4], bl4[4];
                ldmat4(bh4, bhb + off);
                ldmat4(bl4, blb + off);
                #pragma unroll
                for (int half = 0; half < 2; half++) {
                    int nb = nbp * 2 + half;
                    #pragma unroll
                    for (int mb = 0; mb < 2; mb++) {
                        mma16816(acc[mb][nb], ah[mb], bh4[2 * half], bh4[2 * half + 1]);
                        mma16816(acc[mb][nb], al[mb], bh4[2 * half], bh4[2 * half + 1]);
                        mma16816(acc[mb][nb], ah[mb], bl4[2 * half], bl4[2 * half + 1]);
                    }
                }
            }
        }
        __syncthreads();
    }

    if (z <= 1) {
        bf16* GH = z ? g_Kh : g_Qh;
        bf16* GL = z ? g_Kl : g_Ql;
        const float fac = z ? 1.f : (SCALE * LOG2E);
        #pragma unroll
        for (int mb = 0; mb < 2; mb++) {
            #pragma unroll
            for (int rh = 0; rh < 2; rh++) {
                int r = wm * 32 + mb * 16 + lq + rh * 8;
                int m = m0 + r;
                int b = m / MPB;
                int t = m - b * MPB;
                if (t >= SEQL) continue;
                int iq = t >> 2, r4 = t & 3;
                #pragma unroll
                for (int nb = 0; nb < 8; nb++) {
                    int col = wn * 64 + nb * 8 + c * 2;
                    int head = hp * 2 + (col >> 6);
                    int d = col & 63;
                    int combo = (b * NHEAD + head) * RATE + r4;
                    size_t o = ((size_t)combo * NSUBP + iq) * 64 + d;
                    float v0 = acc[mb][nb][rh * 2 + 0] * fac;
                    float v1 = acc[mb][nb][rh * 2 + 1] * fac;
                    float h0 = __bfloat162float(__float2bfloat16(v0));
                    float h1 = __bfloat162float(__float2bfloat16(v1));
                    *(uint32_t*)(GH + o) = packbf(h1, h0);
                    *(uint32_t*)(GL + o) = packbf(v1 - h1, v0 - h0);
                }
            }
        }
        return;
    }

    float* C = (float*)psm;
    #pragma unroll
    for (int mb = 0; mb < 2; mb++) {
        int r0 = wm * 32 + mb * 16 + lq;
        #pragma unroll
        for (int nb = 0; nb < 8; nb++) {
            int col = wn * 64 + nb * 8 + c * 2;
            *(float2*)(C + r0 * SC + col)       = make_float2(acc[mb][nb][0], acc[mb][nb][1]);
            *(float2*)(C + (r0 + 8) * SC + col) = make_float2(acc[mb][nb][2], acc[mb][nb][3]);
        }
    }
    __syncthreads();

    const int bb = m0 / MPB;
    const int t0 = m0 - bb * MPB;
    const bool fast = ((m0 + 127) / MPB == bb) && (t0 + 128 <= SEQL);

    if (fast) {
        const int iq0 = t0 >> 2;
        {
            int r = tid >> 1, hh2 = tid & 1;
            int head = hp * 2 + hh2;
            int t = t0 + r;
            int iq = t >> 2, r4 = t & 3;
            int combo = (bb * NHEAD + head) * RATE + r4;
            size_t orow = ((size_t)combo * NSUBP + iq) * 64;
            #pragma unroll
            for (int j = 0; j < 16; j++)
                *(float4*)(g_Vf + orow + j * 4) = *(const float4*)(C + r * SC + hh2 * 64 + j * 4);
        }
        {
            int hh2 = tid & 1;
            int head = hp * 2 + hh2;
            int tid2 = tid >> 1;
            int g = tid2 & 7, r4 = (tid2 >> 3) & 3, dl = tid2 >> 5;
            int combo = (bb * NHEAD + head) * RATE + r4;
            #pragma unroll
            for (int it = 0; it < 16; it++) {
                int d = it * 4 + dl;
                float v[4], hi[4];
                #pragma unroll
                for (int j = 0; j < 4; j++) {
                    int r = (g * 4 + j) * 4 + r4;
                    v[j] = C[r * SC + hh2 * 64 + d];
                    hi[j] = __bfloat162float(__float2bfloat16(v[j]));
                }
                uint2 uh = make_uint2(packbf(hi[1], hi[0]), packbf(hi[3], hi[2]));
                uint2 ul = make_uint2(packbf(v[1] - hi[1], v[0] - hi[0]),
                                      packbf(v[3] - hi[3], v[2] - hi[2]));
                size_t o = ((size_t)combo * 64 + d) * NSUBP + iq0 + g * 4;
                *(uint2*)(g_VTh + o) = uh;
                *(uint2*)(g_VTl + o) = ul;
            }
        }
    } else {
        int r = tid >> 1, hh2 = tid & 1;
        int head = hp * 2 + hh2;
        int m = m0 + r;
        int b = m / MPB;
        int t = m - b * MPB;
        if (t < SEQL) {
            int iq = t >> 2, r4 = t & 3;
            int combo = (b * NHEAD + head) * RATE + r4;
            size_t orow = ((size_t)combo * NSUBP + iq) * 64;
            #pragma unroll
            for (int j = 0; j < 16; j++) {
                int d = j * 4;
                float4 v = *(const float4*)(C + r * SC + hh2 * 64 + d);
                float vf[4] = {v.x, v.y, v.z, v.w};
                float h0 = __bfloat162float(__float2bfloat16(vf[0]));
                float h1 = __bfloat162float(__float2bfloat16(vf[1]));
                float h2 = __bfloat162float(__float2bfloat16(vf[2]));
                float h3 = __bfloat162float(__float2bfloat16(vf[3]));
                *(float4*)(g_Vf + orow + d) = v;
                float hs[4] = {h0, h1, h2, h3};
                #pragma unroll
                for (int e = 0; e < 4; e++) {
                    size_t ot = ((size_t)combo * 64 + d + e) * NSUBP + iq;
                    g_VTh[ot] = __float2bfloat16(hs[e]);
                    g_VTl[ot] = __float2bfloat16(vf[e] - hs[e]);
                }
            }
        }
    }
}

// ---------------------------------------------------------------------------
// Flash attention with FIXED max (0): no online-softmax rescaling at all.
// p = exp2(logit); l accumulated per-lane, quad-reduced in epilogue;
// zero pad key contributes exactly 1.0 to l.
// ---------------------------------------------------------------------------
#define SM_QH 0
#define SM_QL (BQ * SK)
#define SM_BUF (2 * BQ * SK)
#define BUF_SZ (4 * 64 * SK)
#define SMEM_BYTES ((SM_BUF + 2 * BUF_SZ) * 2)   // 110592

__global__ __launch_bounds__(256, 2) void attn_kernel(float* __restrict__ out)
{
    extern __shared__ __align__(16) bf16 sm[];
    bf16* QhS = sm + SM_QH;
    bf16* QlS = sm + SM_QL;

    const int tid = threadIdx.x;
    const int w = tid >> 5, l = tid & 31;
    const int lq = l >> 2;
    const int c  = l & 3;
    const int combo = blockIdx.y;
    const int q0 = blockIdx.x * BQ;
    const uint32_t smem_u32 = (uint32_t)__cvta_generic_to_shared(sm);

    const size_t gq = (size_t)combo * NSUBP * 64;
    const size_t gvt = (size_t)combo * 64 * NSUBP;

    #pragma unroll
    for (int it = 0; it < 8; it++) {
        int cid = tid + it * 256;
        int arr = cid >> 10;
        int rem = cid & 1023;
        int row = rem >> 3, seg = rem & 7;
        uint32_t dst = smem_u32 + (uint32_t)(((arr ? SM_QL : SM_QH) + row * SK) * 2 + seg * 16);
        const bf16* src = (arr ? g_Ql : g_Qh) + gq + (size_t)(q0 + row) * 64 + seg * 8;
        cpasync16(dst, src);
    }
    cpcommit();

    {
        #pragma unroll
        for (int it = 0; it < 8; it++) {
            int cid = tid + it * 256;
            int arr = cid >> 9;
            int rem = cid & 511;
            int row = rem >> 3, seg = rem & 7;
            uint32_t dst = smem_u32 + (uint32_t)((SM_BUF + arr * 64 * SK + row * SK) * 2 + seg * 16);
            const bf16* src;
            if (arr == 0)      src = g_Kh + gq + (size_t)row * 64 + seg * 8;
            else if (arr == 1) src = g_Kl + gq + (size_t)row * 64 + seg * 8;
            else if (arr == 2) src = g_VTh + gvt + (size_t)row * NSUBP + seg * 8;
            else               src = g_VTl + gvt + (size_t)row * NSUBP + seg * 8;
            cpasync16(dst, src);
        }
        cpcommit();
    }
    cpwait0();
    __syncthreads();

    uint32_t qh[4][4], ql[4][4];
    {
        const int la16 = l & 15, la8 = l >> 4;
        uint32_t qhb = smem_u32 + (uint32_t)((SM_QH + (w * 16 + la16) * SK) * 2);
        uint32_t qlb = smem_u32 + (uint32_t)((SM_QL + (w * 16 + la16) * SK) * 2);
        #pragma unroll
        for (int kc = 0; kc < 4; kc++) {
            uint32_t off = (uint32_t)((kc * 16 + la8 * 8) * 2);
            ldmat4(qh[kc], qhb + off);
            ldmat4(ql[kc], qlb + off);
        }
    }

    float oacc[8][4];
    #pragma unroll
    for (int j = 0; j < 8; j++)
        #pragma unroll
        for (int t = 0; t < 4; t++) oacc[j][t] = 0.f;
    float l0 = 0.f, l1 = 0.f;   // per-lane partial denominators

    const int lrow8 = l & 7;
    const int lcol8 = l >> 3;
    const uint32_t boff_lane = (uint32_t)(lrow8 * SK * 2 + lcol8 * 16);

    for (int kt = 0; kt < 16; kt++) {
        __syncthreads();
        if (kt < 15) {
            const int ks = (kt + 1) * 64;
            const int boff = SM_BUF + ((kt + 1) & 1) * BUF_SZ;
            #pragma unroll
            for (int it = 0; it < 8; it++) {
                int cid = tid + it * 256;
                int arr = cid >> 9;
                int rem = cid & 511;
                int row = rem >> 3, seg = rem & 7;
                uint32_t dst = smem_u32 + (uint32_t)((boff + arr * 64 * SK + row * SK) * 2 + seg * 16);
                const bf16* src;
                if (arr == 0)      src = g_Kh + gq + (size_t)(ks + row) * 64 + seg * 8;
                else if (arr == 1) src = g_Kl + gq + (size_t)(ks + row) * 64 + seg * 8;
                else if (arr == 2) src = g_VTh + gvt + (size_t)row * NSUBP + ks + seg * 8;
                else               src = g_VTl + gvt + (size_t)row * NSUBP + ks + seg * 8;
                cpasync16(dst, src);
            }
            cpcommit();
            cpwait1();
        } else {
            cpwait0();
        }
        __syncthreads();

        const int bufbase = SM_BUF + (kt & 1) * BUF_SZ;
        const uint32_t khb = smem_u32 + (uint32_t)((bufbase) * 2) + boff_lane;
        const uint32_t klb = smem_u32 + (uint32_t)((bufbase + 64 * SK) * 2) + boff_lane;
        const uint32_t vhb = smem_u32 + (uint32_t)((bufbase + 2 * 64 * SK) * 2) + boff_lane;
        const uint32_t vlb = smem_u32 + (uint32_t)((bufbase + 3 * 64 * SK) * 2) + boff_lane;

        // ---- S = Q K^T ----
        float sacc[8][4];
        #pragma unroll
        for (int j = 0; j < 8; j++) {
            #pragma unroll
            for (int t = 0; t < 4; t++) sacc[j][t] = 0.f;
            uint32_t bh[8], bl[8];
            uint32_t a = khb + (uint32_t)(j * 8 * SK * 2);
            ldmat4(bh, a); ldmat4(bh + 4, a + 64);
            uint32_t a2 = klb + (uint32_t)(j * 8 * SK * 2);
            ldmat4(bl, a2); ldmat4(bl + 4, a2 + 64);
            #pragma unroll
            for (int kc = 0; kc < 4; kc++) {
                mma16816(sacc[j], qh[kc], bh[2 * kc], bh[2 * kc + 1]);
                mma16816(sacc[j], ql[kc], bh[2 * kc], bh[2 * kc + 1]);
                mma16816(sacc[j], qh[kc], bl[2 * kc], bl[2 * kc + 1]);
            }
        }

        // ---- absolute softmax: p = exp2(logit), per-lane partial l ----
        #pragma unroll
        for (int j = 0; j < 8; j++) {
            sacc[j][0] = exp2f(sacc[j][0]);
            sacc[j][1] = exp2f(sacc[j][1]);
            sacc[j][2] = exp2f(sacc[j][2]);
            sacc[j][3] = exp2f(sacc[j][3]);
            l0 += sacc[j][0] + sacc[j][1];
            l1 += sacc[j][2] + sacc[j][3];
        }

        // ---- P fragments ----
        uint32_t pah[4][4], pal[4][4];
        #pragma unroll
        for (int kc = 0; kc < 4; kc++) {
            int j0 = 2 * kc, j1 = 2 * kc + 1;
            uint32_t h;
            h = packbf(sacc[j0][1], sacc[j0][0]); pah[kc][0] = h;
            pal[kc][0] = packbf(sacc[j0][1] - __uint_as_float(h & 0xffff0000u),
                                sacc[j0][0] - __uint_as_float(h << 16));
            h = packbf(sacc[j0][3], sacc[j0][2]); pah[kc][1] = h;
            pal[kc][1] = packbf(sacc[j0][3] - __uint_as_float(h & 0xffff0000u),
                                sacc[j0][2] - __uint_as_float(h << 16));
            h = packbf(sacc[j1][1], sacc[j1][0]); pah[kc][2] = h;
            pal[kc][2] = packbf(sacc[j1][1] - __uint_as_float(h & 0xffff0000u),
                                sacc[j1][0] - __uint_as_float(h << 16));
            h = packbf(sacc[j1][3], sacc[j1][2]); pah[kc][3] = h;
            pal[kc][3] = packbf(sacc[j1][3] - __uint_as_float(h & 0xffff0000u),
                                sacc[j1][2] - __uint_as_float(h << 16));
        }

        // ---- PV (no rescaling) ----
        #pragma unroll
        for (int j = 0; j < 8; j++) {
            uint32_t bh[8], bl[8];
            uint32_t a = vhb + (uint32_t)(j * 8 * SK * 2);
            ldmat4(bh, a); ldmat4(bh + 4, a + 64);
            uint32_t a2 = vlb + (uint32_t)(j * 8 * SK * 2);
            ldmat4(bl, a2); ldmat4(bl + 4, a2 + 64);
            #pragma unroll
            for (int kc = 0; kc < 4; kc++) {
                mma16816(oacc[j], pah[kc], bh[2 * kc], bh[2 * kc + 1]);
                mma16816(oacc[j], pal[kc], bh[2 * kc], bh[2 * kc + 1]);
                mma16816(oacc[j], pah[kc], bl[2 * kc], bl[2 * kc + 1]);
            }
        }
    }

    // ---- band pass (7 banded logits) + zero pad key (adds exactly 1 to l) ----
    __syncthreads();
    float* Kband = (float*)(sm + SM_BUF);
    float* Vband = Kband + 134 * BSW;
    for (int i = tid; i < 134 * 64; i += 256) {
        int rr = i >> 6, d = i & 63;
        int g = q0 - 3 + rr;
        float kv = 0.f, vv = 0.f;
        if (g >= 0) {
            size_t o = gq + (size_t)g * 64 + d;
            kv = __bfloat162float(g_Kh[o]) + __bfloat162float(g_Kl[o]);
            vv = g_Vf[o];
        }
        Kband[rr * BSW + d] = kv;
        Vband[rr * BSW + d] = vv;
    }
    __syncthreads();

    float bl[2][2];
    #pragma unroll
    for (int rh = 0; rh < 2; rh++) {
        int qlcl = w * 16 + lq + 8 * rh;
        int kk0 = c, kk1 = c + 4;
        float acc0 = 0.f, acc1 = 0.f;
        const float* kb0 = Kband + (qlcl + kk0) * BSW;
        const float* kb1 = Kband + (qlcl + kk1) * BSW;
        #pragma unroll 8
        for (int d = 0; d < 64; d++) {
            float qf = __bfloat162float(QhS[qlcl * SK + d]) + __bfloat162float(QlS[qlcl * SK + d]);
            acc0 += qf * kb0[d];
            if (kk1 < 7) acc1 += qf * kb1[d];
        }
        bl[rh][0] = acc0;
        bl[rh][1] = acc1;
    }

    {
        float p00 = exp2f(bl[0][0]);
        float p01 = (c + 4 < 7) ? exp2f(bl[0][1]) : 0.f;
        float p10 = exp2f(bl[1][0]);
        float p11 = (c + 4 < 7) ? exp2f(bl[1][1]) : 0.f;
        // zero-key term: logit 0 -> exp2(0) = 1, added once per row (lane c==0)
        l0 += p00 + p01 + ((c == 0) ? 1.f : 0.f);
        l1 += p10 + p11 + ((c == 0) ? 1.f : 0.f);

        int r0 = w * 16 + lq;
        #pragma unroll
        for (int kk = 0; kk < 7; kk++) {
            int src = (l & ~3) | (kk & 3);
            float pb0 = __shfl_sync(0xffffffffu, (kk < 4) ? p00 : p01, src);
            float pb1 = __shfl_sync(0xffffffffu, (kk < 4) ? p10 : p11, src);
            const float* v0 = Vband + (r0 + kk) * BSW + c * 2;
            const float* v1 = Vband + (r0 + 8 + kk) * BSW + c * 2;
            #pragma unroll
            for (int j = 0; j < 8; j++) {
                float2 a = *(const float2*)(v0 + j * 8);
                float2 bq = *(const float2*)(v1 + j * 8);
                oacc[j][0] += pb0 * a.x; oacc[j][1] += pb0 * a.y;
                oacc[j][2] += pb1 * bq.x; oacc[j][3] += pb1 * bq.y;
            }
        }
    }

    // ---- epilogue: quad-reduce l partials, normalize, store ----
    l0 += __shfl_xor_sync(0xffffffffu, l0, 1);
    l0 += __shfl_xor_sync(0xffffffffu, l0, 2);
    l1 += __shfl_xor_sync(0xffffffffu, l1, 1);
    l1 += __shfl_xor_sync(0xffffffffu, l1, 2);

    const int b = combo >> 5;
    const int h = (combo >> 2) & 7;
    const int r = combo & 3;
    float inv0 = 1.f / l0, inv1 = 1.f / l1;
    int qg = q0 + w * 16 + lq;
    size_t o0 = ((size_t)(b * SEQL + qg * 4 + r)) * OUTD + h * 64 + c * 2;
    size_t o1 = ((size_t)(b * SEQL + (qg + 8) * 4 + r)) * OUTD + h * 64 + c * 2;
    #pragma unroll
    for (int j = 0; j < 8; j++) {
        *(float2*)(out + o0 + j * 8) = make_float2(oacc[j][0] * inv0, oacc[j][1] * inv0);
        *(float2*)(out + o1 + j * 8) = make_float2(oacc[j][2] * inv1, oacc[j][3] * inv1);
    }
}

// ---------------------------------------------------------------------------
extern "C" void kernel_launch(void* const* d_in, const int* in_sizes, int n_in,
                              void* d_out, int out_size)
{
    const float* x  = (const float*)d_in[0];
    const float* Wq = (const float*)d_in[1];
    const float* Wk = (const float*)d_in[2];
    const float* Wv = (const float*)d_in[3];
    float* out = (float*)d_out;

    cudaFuncSetAttribute(attn_kernel, cudaFuncAttributeMaxDynamicSharedMemorySize, SMEM_BYTES);
    cudaFuncSetAttribute(proj_tc_kernel, cudaFuncAttributeMaxDynamicSharedMemorySize, P_SMEM_BYTES);

    splitx_kernel<<<(BATCH * SEQL * OUTD / 4) / 256, 256>>>(x);
    splitw_kernel<<<dim3(OUTD, 3), 256>>>(Wq, Wk, Wv);

    dim3 pgrid(3, NHEAD / 2, MXP / 128);        // z, head-pair, m-tile
    proj_tc_kernel<<<pgrid, 256, P_SMEM_BYTES>>>();

    dim3 agrid(SEQL / RATE / BQ, NCOMBO);
    attn_kernel<<<agrid, 256, SMEM_BYTES>>>(out);
}

// round 13
// speedup vs baseline: 1.3512x; 1.2491x over previous
#include <cuda_runtime.h>
#include <cuda_fp16.h>
#include <cstdint>

#define BATCH 2
#define SEQL  4096
#define OUTD  512
#define NHEAD 8
#define RATE  4
#define NSUB  1025
#define NSUBP 1088
#define NCOMBO 64
#define SCALE 0.125f
#define LOG2E 1.44269504088896340736f

#define MPB   4160
#define MXP   (2 * MPB)     // 8320 = 65 * 128

#define BQ 128
#define SK 72
#define BSW 68

typedef __half hf;

// fp16 scratch (zero-init; pad keys >= 1024 stay zero)
__device__ hf g_Qh[(size_t)NCOMBO * NSUBP * 64];
__device__ hf g_Ql[(size_t)NCOMBO * NSUBP * 64];
__device__ hf g_Kh[(size_t)NCOMBO * NSUBP * 64];            // fp16-single K
__device__ hf g_VTh[(size_t)NCOMBO * 64 * NSUBP];           // fp16-single V^T
__device__ float g_Vf[(size_t)NCOMBO * NSUBP * 64];
__device__ hf g_xh[(size_t)MXP * OUTD];
__device__ hf g_xl[(size_t)MXP * OUTD];
__device__ hf g_WhT[3][OUTD * OUTD];
__device__ hf g_WlT[3][OUTD * OUTD];

__device__ __forceinline__ uint32_t packhf(float hi, float lo) {
    uint32_t r; asm("cvt.rn.f16x2.f32 %0, %1, %2;" : "=r"(r) : "f"(hi), "f"(lo)); return r;
}
__device__ __forceinline__ float2 unpackhf(uint32_t u) {
    __half2 h = *reinterpret_cast<__half2*>(&u);
    return __half22float2(h);      // .x = low half, .y = high half
}
__device__ __forceinline__ void cpasync16(uint32_t s, const void* g) {
    asm volatile("cp.async.cg.shared.global [%0], [%1], 16;\n" :: "r"(s), "l"(g));
}
__device__ __forceinline__ void cpcommit() { asm volatile("cp.async.commit_group;\n"); }
__device__ __forceinline__ void cpwait0()  { asm volatile("cp.async.wait_group 0;\n"); }
__device__ __forceinline__ void cpwait1()  { asm volatile("cp.async.wait_group 1;\n"); }

__device__ __forceinline__ void mma16816h(float* d, const uint32_t* a, uint32_t b0, uint32_t b1) {
    asm volatile("mma.sync.aligned.m16n8k16.row.col.f32.f16.f16.f32 "
        "{%0,%1,%2,%3}, {%4,%5,%6,%7}, {%8,%9}, {%0,%1,%2,%3};"
        : "+f"(d[0]), "+f"(d[1]), "+f"(d[2]), "+f"(d[3])
        : "r"(a[0]), "r"(a[1]), "r"(a[2]), "r"(a[3]), "r"(b0), "r"(b1));
}
__device__ __forceinline__ void ldmat4(uint32_t* r, uint32_t addr) {
    asm volatile("ldmatrix.sync.aligned.m8n8.x4.shared.b16 {%0,%1,%2,%3}, [%4];"
        : "=r"(r[0]), "=r"(r[1]), "=r"(r[2]), "=r"(r[3]) : "r"(addr));
}

// ---------------------------------------------------------------------------
__global__ __launch_bounds__(256) void splitx_kernel(const float* __restrict__ x)
{
    int idx = blockIdx.x * 256 + threadIdx.x;
    int flat = idx * 4;
    int b = flat / (SEQL * OUTD);
    int rem = flat - b * (SEQL * OUTD);
    int t = rem / OUTD;
    int k = rem - t * OUTD;
    float4 v = *(const float4*)(x + (size_t)flat);
    size_t o = ((size_t)(b * MPB + t)) * OUTD + k;
    float hx = __half2float(__float2half_rn(v.x));
    float hy = __half2float(__float2half_rn(v.y));
    float hz = __half2float(__float2half_rn(v.z));
    float hw = __half2float(__float2half_rn(v.w));
    *(uint2*)(g_xh + o) = make_uint2(packhf(hy, hx), packhf(hw, hz));
    *(uint2*)(g_xl + o) = make_uint2(packhf(v.y - hy, v.x - hx), packhf(v.w - hw, v.z - hz));
}

__global__ __launch_bounds__(256) void splitw_kernel(
    const float* __restrict__ Wq, const float* __restrict__ Wk, const float* __restrict__ Wv)
{
    int k = blockIdx.x, z = blockIdx.y;
    const float* W = (z == 0) ? Wq : (z == 1) ? Wk : Wv;
    #pragma unroll
    for (int half = 0; half < 2; half++) {
        int n = threadIdx.x + half * 256;
        float v = W[(size_t)k * OUTD + n];
        float h = __half2float(__float2half_rn(v));
        g_WhT[z][(size_t)n * OUTD + k] = __float2half_rn(h);
        g_WlT[z][(size_t)n * OUTD + k] = __float2half_rn(v - h);
    }
}

// ---------------------------------------------------------------------------
// Tensor-core projection (fp16 3-split; structure unchanged from R11/R12).
// ---------------------------------------------------------------------------
#define KT 32
#define SA 40
#define P_AH 0
#define P_AL (2 * 128 * SA)
#define P_BH (4 * 128 * SA)
#define P_BL (6 * 128 * SA)
#define SC 132
#define P_SMEM_BYTES 81920

__global__ __launch_bounds__(256, 2) void proj_tc_kernel()
{
    extern __shared__ __align__(16) hf psm[];
    const int tid = threadIdx.x;
    const int w = tid >> 5, l = tid & 31;
    const int lq = l >> 2, c = l & 3;
    const int wm = w & 3, wn = w >> 2;
    const int z  = blockIdx.x;
    const int hp = blockIdx.y;
    const int m0 = blockIdx.z * 128;
    const int n0 = hp * 128;
    const uint32_t su = (uint32_t)__cvta_generic_to_shared(psm);

    const hf* WhT = g_WhT[z] + (size_t)n0 * OUTD;
    const hf* WlT = g_WlT[z] + (size_t)n0 * OUTD;

    auto stage = [&](int kt, int bi) {
        const int k0 = kt * KT;
        #pragma unroll
        for (int it = 0; it < 4; it++) {
            int cid = tid + it * 256;
            int sp = cid >> 9, rem = cid & 511;
            int row = rem >> 2, seg = rem & 3;
            uint32_t dst = su + (uint32_t)(((sp ? P_AL : P_AH) + bi * 128 * SA + row * SA + seg * 8) * 2);
            const hf* src = (sp ? g_xl : g_xh) + (size_t)(m0 + row) * OUTD + k0 + seg * 8;
            cpasync16(dst, src);
        }
        #pragma unroll
        for (int it = 0; it < 4; it++) {
            int cid = tid + it * 256;
            int sp = cid >> 9, rem = cid & 511;
            int row = rem >> 2, seg = rem & 3;
            uint32_t dst = su + (uint32_t)(((sp ? P_BL : P_BH) + bi * 128 * SA + row * SA + seg * 8) * 2);
            const hf* src = (sp ? WlT : WhT) + (size_t)row * OUTD + k0 + seg * 8;
            cpasync16(dst, src);
        }
        cpcommit();
    };

    stage(0, 0);

    float acc[2][8][4];
    #pragma unroll
    for (int i = 0; i < 2; i++)
        #pragma unroll
        for (int j = 0; j < 8; j++)
            #pragma unroll
            for (int t = 0; t < 4; t++) acc[i][j][t] = 0.f;

    const int la16 = l & 15;
    const int la8  = l >> 4;
    const int rB   = ((l >> 4) << 3) + (l & 7);
    const int cB8  = ((l >> 3) & 1) * 8;

    for (int kt = 0; kt < OUTD / KT; kt++) {
        if (kt < OUTD / KT - 1) { stage(kt + 1, (kt + 1) & 1); cpwait1(); }
        else cpwait0();
        __syncthreads();
        const int bi = kt & 1;
        const uint32_t ahb = su + (uint32_t)((P_AH + bi * 128 * SA) * 2);
        const uint32_t alb = su + (uint32_t)((P_AL + bi * 128 * SA) * 2);
        const uint32_t bhb = su + (uint32_t)((P_BH + bi * 128 * SA) * 2);
        const uint32_t blb = su + (uint32_t)((P_BL + bi * 128 * SA) * 2);

        #pragma unroll
        for (int hh = 0; hh < 2; hh++) {
            const int kb = hh * 16;
            uint32_t ah[2][4], al[2][4];
            #pragma unroll
            for (int mb = 0; mb < 2; mb++) {
                uint32_t off = (uint32_t)((wm * 32 + mb * 16 + la16) * SA * 2 + (kb + la8 * 8) * 2);
                ldmat4(ah[mb], ahb + off);
                ldmat4(al[mb], alb + off);
            }
            #pragma unroll
            for (int nbp = 0; nbp < 4; nbp++) {
                uint32_t off = (uint32_t)((wn * 64 + nbp * 16 + rB) * SA * 2 + (kb + cB8) * 2);
                uint32_t bh4[4], bl4[4];
                ldmat4(bh4, bhb + off);
                ldmat4(bl4, blb + off);
                #pragma unroll
                for (int half = 0; half < 2; half++) {
                    int nb = nbp * 2 + half;
                    #pragma unroll
                    for (int mb = 0; mb < 2; mb++) {
                        mma16816h(acc[mb][nb], ah[mb], bh4[2 * half], bh4[2 * half + 1]);
                        mma16816h(acc[mb][nb], al[mb], bh4[2 * half], bh4[2 * half + 1]);
                        mma16816h(acc[mb][nb], ah[mb], bl4[2 * half], bl4[2 * half + 1]);
                    }
                }
            }
        }
        __syncthreads();
    }

    if (z <= 1) {
        const float fac = z ? 1.f : (SCALE * LOG2E);
        #pragma unroll
        for (int mb = 0; mb < 2; mb++) {
            #pragma unroll
            for (int rh = 0; rh < 2; rh++) {
                int r = wm * 32 + mb * 16 + lq + rh * 8;
                int m = m0 + r;
                int b = m / MPB;
                int t = m - b * MPB;
                if (t >= SEQL) continue;
                int iq = t >> 2, r4 = t & 3;
                #pragma unroll
                for (int nb = 0; nb < 8; nb++) {
                    int col = wn * 64 + nb * 8 + c * 2;
                    int head = hp * 2 + (col >> 6);
                    int d = col & 63;
                    int combo = (b * NHEAD + head) * RATE + r4;
                    size_t o = ((size_t)combo * NSUBP + iq) * 64 + d;
                    float v0 = acc[mb][nb][rh * 2 + 0] * fac;
                    float v1 = acc[mb][nb][rh * 2 + 1] * fac;
                    if (z == 0) {
                        uint32_t uh = packhf(v1, v0);
                        float2 f = unpackhf(uh);
                        *(uint32_t*)(g_Qh + o) = uh;
                        *(uint32_t*)(g_Ql + o) = packhf(v1 - f.y, v0 - f.x);
                    } else {
                        *(uint32_t*)(g_Kh + o) = packhf(v1, v0);
                    }
                }
            }
        }
        return;
    }

    // z==2: stage C, then Vf (fp32, row-major) + VTh (fp16, transposed)
    float* C = (float*)psm;
    #pragma unroll
    for (int mb = 0; mb < 2; mb++) {
        int r0 = wm * 32 + mb * 16 + lq;
        #pragma unroll
        for (int nb = 0; nb < 8; nb++) {
            int col = wn * 64 + nb * 8 + c * 2;
            *(float2*)(C + r0 * SC + col)       = make_float2(acc[mb][nb][0], acc[mb][nb][1]);
            *(float2*)(C + (r0 + 8) * SC + col) = make_float2(acc[mb][nb][2], acc[mb][nb][3]);
        }
    }
    __syncthreads();

    const int bb = m0 / MPB;
    const int t0 = m0 - bb * MPB;
    const bool fast = ((m0 + 127) / MPB == bb) && (t0 + 128 <= SEQL);

    if (fast) {
        const int iq0 = t0 >> 2;
        {
            int r = tid >> 1, hh2 = tid & 1;
            int head = hp * 2 + hh2;
            int t = t0 + r;
            int iq = t >> 2, r4 = t & 3;
            int combo = (bb * NHEAD + head) * RATE + r4;
            size_t orow = ((size_t)combo * NSUBP + iq) * 64;
            #pragma unroll
            for (int j = 0; j < 16; j++)
                *(float4*)(g_Vf + orow + j * 4) = *(const float4*)(C + r * SC + hh2 * 64 + j * 4);
        }
        {
            int hh2 = tid & 1;
            int head = hp * 2 + hh2;
            int tid2 = tid >> 1;
            int g = tid2 & 7, r4 = (tid2 >> 3) & 3, dl = tid2 >> 5;
            int combo = (bb * NHEAD + head) * RATE + r4;
            #pragma unroll
            for (int it = 0; it < 16; it++) {
                int d = it * 4 + dl;
                float v[4];
                #pragma unroll
                for (int j = 0; j < 4; j++) {
                    int r = (g * 4 + j) * 4 + r4;
                    v[j] = C[r * SC + hh2 * 64 + d];
                }
                uint2 uh = make_uint2(packhf(v[1], v[0]), packhf(v[3], v[2]));
                size_t o = ((size_t)combo * 64 + d) * NSUBP + iq0 + g * 4;
                *(uint2*)(g_VTh + o) = uh;
            }
        }
    } else {
        int r = tid >> 1, hh2 = tid & 1;
        int head = hp * 2 + hh2;
        int m = m0 + r;
        int b = m / MPB;
        int t = m - b * MPB;
        if (t < SEQL) {
            int iq = t >> 2, r4 = t & 3;
            int combo = (b * NHEAD + head) * RATE + r4;
            size_t orow = ((size_t)combo * NSUBP + iq) * 64;
            #pragma unroll
            for (int j = 0; j < 16; j++) {
                int d = j * 4;
                float4 v = *(const float4*)(C + r * SC + hh2 * 64 + d);
                float vf[4] = {v.x, v.y, v.z, v.w};
                *(float4*)(g_Vf + orow + d) = v;
                #pragma unroll
                for (int e = 0; e < 4; e++) {
                    size_t ot = ((size_t)combo * 64 + d + e) * NSUBP + iq;
                    g_VTh[ot] = __float2half_rn(vf[e]);
                }
            }
        }
    }
}

// ---------------------------------------------------------------------------
// Flash attention: fp16, K/V single-precision-split dropped (2 MMAs per kc
// for both QK and PV), fixed-max softmax, deferred-l.
// ---------------------------------------------------------------------------
#define SM_QH 0
#define SM_QL (BQ * SK)
#define SM_BUF (2 * BQ * SK)
#define BUF_SZ (2 * 64 * SK)                    // Kh + VTh only
#define SMEM_BYTES 110592                       // band overlay still fits

__global__ __launch_bounds__(256, 2) void attn_kernel(float* __restrict__ out)
{
    extern __shared__ __align__(16) hf sm[];
    hf* QhS = sm + SM_QH;
    hf* QlS = sm + SM_QL;

    const int tid = threadIdx.x;
    const int w = tid >> 5, l = tid & 31;
    const int lq = l >> 2;
    const int c  = l & 3;
    const int combo = blockIdx.y;
    const int q0 = blockIdx.x * BQ;
    const uint32_t smem_u32 = (uint32_t)__cvta_generic_to_shared(sm);

    const size_t gq = (size_t)combo * NSUBP * 64;
    const size_t gvt = (size_t)combo * 64 * NSUBP;

    // Q hi/lo staging (2048 x 16B)
    #pragma unroll
    for (int it = 0; it < 8; it++) {
        int cid = tid + it * 256;
        int arr = cid >> 10;
        int rem = cid & 1023;
        int row = rem >> 3, seg = rem & 7;
        uint32_t dst = smem_u32 + (uint32_t)(((arr ? SM_QL : SM_QH) + row * SK) * 2 + seg * 16);
        const hf* src = (arr ? g_Ql : g_Qh) + gq + (size_t)(q0 + row) * 64 + seg * 8;
        cpasync16(dst, src);
    }
    cpcommit();

    // tile 0 staging (1024 x 16B: Kh + VTh)
    {
        #pragma unroll
        for (int it = 0; it < 4; it++) {
            int cid = tid + it * 256;
            int arr = cid >> 9;
            int rem = cid & 511;
            int row = rem >> 3, seg = rem & 7;
            uint32_t dst = smem_u32 + (uint32_t)((SM_BUF + arr * 64 * SK + row * SK) * 2 + seg * 16);
            const hf* src = (arr == 0) ? g_Kh + gq + (size_t)row * 64 + seg * 8
                                       : g_VTh + gvt + (size_t)row * NSUBP + seg * 8;
            cpasync16(dst, src);
        }
        cpcommit();
    }
    cpwait0();
    __syncthreads();

    uint32_t qh[4][4], ql[4][4];
    {
        const int la16 = l & 15, la8 = l >> 4;
        uint32_t qhb = smem_u32 + (uint32_t)((SM_QH + (w * 16 + la16) * SK) * 2);
        uint32_t qlb = smem_u32 + (uint32_t)((SM_QL + (w * 16 + la16) * SK) * 2);
        #pragma unroll
        for (int kc = 0; kc < 4; kc++) {
            uint32_t off = (uint32_t)((kc * 16 + la8 * 8) * 2);
            ldmat4(qh[kc], qhb + off);
            ldmat4(ql[kc], qlb + off);
        }
    }

    float oacc[8][4];
    #pragma unroll
    for (int j = 0; j < 8; j++)
        #pragma unroll
        for (int t = 0; t < 4; t++) oacc[j][t] = 0.f;
    float l0 = 0.f, l1 = 0.f;

    const int lrow8 = l & 7;
    const int lcol8 = l >> 3;
    const uint32_t boff_lane = (uint32_t)(lrow8 * SK * 2 + lcol8 * 16);

    for (int kt = 0; kt < 16; kt++) {
        __syncthreads();
        if (kt < 15) {
            const int ks = (kt + 1) * 64;
            const int boff = SM_BUF + ((kt + 1) & 1) * BUF_SZ;
            #pragma unroll
            for (int it = 0; it < 4; it++) {
                int cid = tid + it * 256;
                int arr = cid >> 9;
                int rem = cid & 511;
                int row = rem >> 3, seg = rem & 7;
                uint32_t dst = smem_u32 + (uint32_t)((boff + arr * 64 * SK + row * SK) * 2 + seg * 16);
                const hf* src = (arr == 0) ? g_Kh + gq + (size_t)(ks + row) * 64 + seg * 8
                                           : g_VTh + gvt + (size_t)row * NSUBP + ks + seg * 8;
                cpasync16(dst, src);
            }
            cpcommit();
            cpwait1();
        } else {
            cpwait0();
        }
        __syncthreads();

        const int bufbase = SM_BUF + (kt & 1) * BUF_SZ;
        const uint32_t khb = smem_u32 + (uint32_t)((bufbase) * 2) + boff_lane;
        const uint32_t vhb = smem_u32 + (uint32_t)((bufbase + 64 * SK) * 2) + boff_lane;

        // ---- S = Q K^T : (qh + ql) x kh ----
        float sacc[8][4];
        #pragma unroll
        for (int j = 0; j < 8; j++) {
            #pragma unroll
            for (int t = 0; t < 4; t++) sacc[j][t] = 0.f;
            uint32_t bh[8];
            uint32_t a = khb + (uint32_t)(j * 8 * SK * 2);
            ldmat4(bh, a); ldmat4(bh + 4, a + 64);
            #pragma unroll
            for (int kc = 0; kc < 4; kc++) {
                mma16816h(sacc[j], qh[kc], bh[2 * kc], bh[2 * kc + 1]);
                mma16816h(sacc[j], ql[kc], bh[2 * kc], bh[2 * kc + 1]);
            }
        }

        // ---- absolute softmax (fixed max 0), per-lane partial l ----
        #pragma unroll
        for (int j = 0; j < 8; j++) {
            sacc[j][0] = exp2f(sacc[j][0]);
            sacc[j][1] = exp2f(sacc[j][1]);
            sacc[j][2] = exp2f(sacc[j][2]);
            sacc[j][3] = exp2f(sacc[j][3]);
            l0 += sacc[j][0] + sacc[j][1];
            l1 += sacc[j][2] + sacc[j][3];
        }

        // ---- P fragments: fp16 hi + residual ----
        uint32_t pah[4][4], pal[4][4];
        #pragma unroll
        for (int kc = 0; kc < 4; kc++) {
            int j0 = 2 * kc, j1 = 2 * kc + 1;
            uint32_t u; float2 f;
            u = packhf(sacc[j0][1], sacc[j0][0]); pah[kc][0] = u;
            f = unpackhf(u); pal[kc][0] = packhf(sacc[j0][1] - f.y, sacc[j0][0] - f.x);
            u = packhf(sacc[j0][3], sacc[j0][2]); pah[kc][1] = u;
            f = unpackhf(u); pal[kc][1] = packhf(sacc[j0][3] - f.y, sacc[j0][2] - f.x);
            u = packhf(sacc[j1][1], sacc[j1][0]); pah[kc][2] = u;
            f = unpackhf(u); pal[kc][2] = packhf(sacc[j1][1] - f.y, sacc[j1][0] - f.x);
            u = packhf(sacc[j1][3], sacc[j1][2]); pah[kc][3] = u;
            f = unpackhf(u); pal[kc][3] = packhf(sacc[j1][3] - f.y, sacc[j1][2] - f.x);
        }

        // ---- PV : (ph + pl) x vh ----
        #pragma unroll
        for (int j = 0; j < 8; j++) {
            uint32_t bh[8];
            uint32_t a = vhb + (uint32_t)(j * 8 * SK * 2);
            ldmat4(bh, a); ldmat4(bh + 4, a + 64);
            #pragma unroll
            for (int kc = 0; kc < 4; kc++) {
                mma16816h(oacc[j], pah[kc], bh[2 * kc], bh[2 * kc + 1]);
                mma16816h(oacc[j], pal[kc], bh[2 * kc], bh[2 * kc + 1]);
            }
        }
    }

    // ---- band pass (7 banded logits) + zero pad key (adds 1 to l) ----
    __syncthreads();
    float* Kband = (float*)(sm + SM_BUF);
    float* Vband = Kband + 134 * BSW;
    for (int i = tid; i < 134 * 64; i += 256) {
        int rr = i >> 6, d = i & 63;
        int g = q0 - 3 + rr;
        float kv = 0.f, vv = 0.f;
        if (g >= 0) {
            size_t o = gq + (size_t)g * 64 + d;
            kv = __half2float(g_Kh[o]);
            vv = g_Vf[o];
        }
        Kband[rr * BSW + d] = kv;
        Vband[rr * BSW + d] = vv;
    }
    __syncthreads();

    float bl[2][2];
    #pragma unroll
    for (int rh = 0; rh < 2; rh++) {
        int qlcl = w * 16 + lq + 8 * rh;
        int kk0 = c, kk1 = c + 4;
        float acc0 = 0.f, acc1 = 0.f;
        const float* kb0 = Kband + (qlcl + kk0) * BSW;
        const float* kb1 = Kband + (qlcl + kk1) * BSW;
        #pragma unroll 8
        for (int d = 0; d < 64; d++) {
            float qf = __half2float(QhS[qlcl * SK + d]) + __half2float(QlS[qlcl * SK + d]);
            acc0 += qf * kb0[d];
            if (kk1 < 7) acc1 += qf * kb1[d];
        }
        bl[rh][0] = acc0;
        bl[rh][1] = acc1;
    }

    {
        float p00 = exp2f(bl[0][0]);
        float p01 = (c + 4 < 7) ? exp2f(bl[0][1]) : 0.f;
        float p10 = exp2f(bl[1][0]);
        float p11 = (c + 4 < 7) ? exp2f(bl[1][1]) : 0.f;
        l0 += p00 + p01 + ((c == 0) ? 1.f : 0.f);
        l1 += p10 + p11 + ((c == 0) ? 1.f : 0.f);

        int r0 = w * 16 + lq;
        #pragma unroll
        for (int kk = 0; kk < 7; kk++) {
            int src = (l & ~3) | (kk & 3);
            float pb0 = __shfl_sync(0xffffffffu, (kk < 4) ? p00 : p01, src);
            float pb1 = __shfl_sync(0xffffffffu, (kk < 4) ? p10 : p11, src);
            const float* v0 = Vband + (r0 + kk) * BSW + c * 2;
            const float* v1 = Vband + (r0 + 8 + kk) * BSW + c * 2;
            #pragma unroll
            for (int j = 0; j < 8; j++) {
                float2 a = *(const float2*)(v0 + j * 8);
                float2 bq = *(const float2*)(v1 + j * 8);
                oacc[j][0] += pb0 * a.x; oacc[j][1] += pb0 * a.y;
                oacc[j][2] += pb1 * bq.x; oacc[j][3] += pb1 * bq.y;
            }
        }
    }

    // ---- epilogue: quad-reduce l, normalize, store ----
    l0 += __shfl_xor_sync(0xffffffffu, l0, 1);
    l0 += __shfl_xor_sync(0xffffffffu, l0, 2);
    l1 += __shfl_xor_sync(0xffffffffu, l1, 1);
    l1 += __shfl_xor_sync(0xffffffffu, l1, 2);

    const int b = combo >> 5;
    const int h = (combo >> 2) & 7;
    const int r = combo & 3;
    float inv0 = 1.f / l0, inv1 = 1.f / l1;
    int qg = q0 + w * 16 + lq;
    size_t o0 = ((size_t)(b * SEQL + qg * 4 + r)) * OUTD + h * 64 + c * 2;
    size_t o1 = ((size_t)(b * SEQL + (qg + 8) * 4 + r)) * OUTD + h * 64 + c * 2;
    #pragma unroll
    for (int j = 0; j < 8; j++) {
        *(float2*)(out + o0 + j * 8) = make_float2(oacc[j][0] * inv0, oacc[j][1] * inv0);
        *(float2*)(out + o1 + j * 8) = make_float2(oacc[j][2] * inv1, oacc[j][3] * inv1);
    }
}

// ---------------------------------------------------------------------------
extern "C" void kernel_launch(void* const* d_in, const int* in_sizes, int n_in,
                              void* d_out, int out_size)
{
    const float* x  = (const float*)d_in[0];
    const float* Wq = (const float*)d_in[1];
    const float* Wk = (const float*)d_in[2];
    const float* Wv = (const float*)d_in[3];
    float* out = (float*)d_out;

    cudaFuncSetAttribute(attn_kernel, cudaFuncAttributeMaxDynamicSharedMemorySize, SMEM_BYTES);
    cudaFuncSetAttribute(proj_tc_kernel, cudaFuncAttributeMaxDynamicSharedMemorySize, P_SMEM_BYTES);

    splitx_kernel<<<(BATCH * SEQL * OUTD / 4) / 256, 256>>>(x);
    splitw_kernel<<<dim3(OUTD, 3), 256>>>(Wq, Wk, Wv);

    dim3 pgrid(3, NHEAD / 2, MXP / 128);        // z, head-pair, m-tile
    proj_tc_kernel<<<pgrid, 256, P_SMEM_BYTES>>>();

    dim3 agrid(SEQL / RATE / BQ, NCOMBO);
    attn_kernel<<<agrid, 256, SMEM_BYTES>>>(out);
}

// round 14
// speedup vs baseline: 1.7044x; 1.2614x over previous
#include <cuda_runtime.h>
#include <cuda_fp16.h>
#include <cstdint>

#define BATCH 2
#define SEQL  4096
#define OUTD  512
#define NHEAD 8
#define RATE  4
#define NSUB  1025
#define NSUBP 1088
#define NCOMBO 64
#define SCALE 0.125f
#define LOG2E 1.44269504088896340736f

#define MPB   4160
#define MXP   (2 * MPB)     // 8320 = 65 * 128

#define BQ 128
#define SK 72
#define BSW 68

typedef __half hf;

// fp16 scratch (zero-init; pad keys >= 1024 stay zero)
__device__ hf g_Qh[(size_t)NCOMBO * NSUBP * 64];
__device__ hf g_Ql[(size_t)NCOMBO * NSUBP * 64];
__device__ hf g_Kh[(size_t)NCOMBO * NSUBP * 64];
__device__ hf g_VTh[(size_t)NCOMBO * 64 * NSUBP];
__device__ float g_Vf[(size_t)NCOMBO * NSUBP * 64];
__device__ hf g_xh[(size_t)MXP * OUTD];
__device__ hf g_xl[(size_t)MXP * OUTD];
__device__ hf g_WhT[3][OUTD * OUTD];

__device__ __forceinline__ uint32_t packhf(float hi, float lo) {
    uint32_t r; asm("cvt.rn.f16x2.f32 %0, %1, %2;" : "=r"(r) : "f"(hi), "f"(lo)); return r;
}
__device__ __forceinline__ float2 unpackhf(uint32_t u) {
    __half2 h = *reinterpret_cast<__half2*>(&u);
    return __half22float2(h);
}
__device__ __forceinline__ void cpasync16(uint32_t s, const void* g) {
    asm volatile("cp.async.cg.shared.global [%0], [%1], 16;\n" :: "r"(s), "l"(g));
}
__device__ __forceinline__ void cpcommit() { asm volatile("cp.async.commit_group;\n"); }
__device__ __forceinline__ void cpwait0()  { asm volatile("cp.async.wait_group 0;\n"); }
__device__ __forceinline__ void cpwait1()  { asm volatile("cp.async.wait_group 1;\n"); }

__device__ __forceinline__ void mma16816h(float* d, const uint32_t* a, uint32_t b0, uint32_t b1) {
    asm volatile("mma.sync.aligned.m16n8k16.row.col.f32.f16.f16.f32 "
        "{%0,%1,%2,%3}, {%4,%5,%6,%7}, {%8,%9}, {%0,%1,%2,%3};"
        : "+f"(d[0]), "+f"(d[1]), "+f"(d[2]), "+f"(d[3])
        : "r"(a[0]), "r"(a[1]), "r"(a[2]), "r"(a[3]), "r"(b0), "r"(b1));
}
__device__ __forceinline__ void ldmat4(uint32_t* r, uint32_t addr) {
    asm volatile("ldmatrix.sync.aligned.m8n8.x4.shared.b16 {%0,%1,%2,%3}, [%4];"
        : "=r"(r[0]), "=r"(r[1]), "=r"(r[2]), "=r"(r[3]) : "r"(addr));
}

// ---------------------------------------------------------------------------
__global__ __launch_bounds__(256) void splitx_kernel(const float* __restrict__ x)
{
    int idx = blockIdx.x * 256 + threadIdx.x;
    int flat = idx * 4;
    int b = flat / (SEQL * OUTD);
    int rem = flat - b * (SEQL * OUTD);
    int t = rem / OUTD;
    int k = rem - t * OUTD;
    float4 v = *(const float4*)(x + (size_t)flat);
    size_t o = ((size_t)(b * MPB + t)) * OUTD + k;
    float hx = __half2float(__float2half_rn(v.x));
    float hy = __half2float(__float2half_rn(v.y));
    float hz = __half2float(__float2half_rn(v.z));
    float hw = __half2float(__float2half_rn(v.w));
    *(uint2*)(g_xh + o) = make_uint2(packhf(hy, hx), packhf(hw, hz));
    *(uint2*)(g_xl + o) = make_uint2(packhf(v.y - hy, v.x - hx), packhf(v.w - hw, v.z - hz));
}

__global__ __launch_bounds__(256) void splitw_kernel(
    const float* __restrict__ Wq, const float* __restrict__ Wk, const float* __restrict__ Wv)
{
    int k = blockIdx.x, z = blockIdx.y;
    const float* W = (z == 0) ? Wq : (z == 1) ? Wk : Wv;
    #pragma unroll
    for (int half = 0; half < 2; half++) {
        int n = threadIdx.x + half * 256;
        g_WhT[z][(size_t)n * OUTD + k] = __float2half_rn(W[(size_t)k * OUTD + n]);
    }
}

// ---------------------------------------------------------------------------
// Tensor-core projection: fp16 2-term split ((xh + xl) * Wh).
// ---------------------------------------------------------------------------
#define KT 32
#define SA 40
#define P_AH 0
#define P_AL (2 * 128 * SA)
#define P_BH (4 * 128 * SA)
#define SC 132
#define P_SMEM_BYTES 81920      // C epilogue (67584 B) dominates staging (61440 B)

__global__ __launch_bounds__(256, 2) void proj_tc_kernel()
{
    extern __shared__ __align__(16) hf psm[];
    const int tid = threadIdx.x;
    const int w = tid >> 5, l = tid & 31;
    const int lq = l >> 2, c = l & 3;
    const int wm = w & 3, wn = w >> 2;
    const int z  = blockIdx.x;
    const int hp = blockIdx.y;
    const int m0 = blockIdx.z * 128;
    const int n0 = hp * 128;
    const uint32_t su = (uint32_t)__cvta_generic_to_shared(psm);

    const hf* WhT = g_WhT[z] + (size_t)n0 * OUTD;

    auto stage = [&](int kt, int bi) {
        const int k0 = kt * KT;
        #pragma unroll
        for (int it = 0; it < 4; it++) {         // A: xh + xl, 1024 transfers
            int cid = tid + it * 256;
            int sp = cid >> 9, rem = cid & 511;
            int row = rem >> 2, seg = rem & 3;
            uint32_t dst = su + (uint32_t)(((sp ? P_AL : P_AH) + bi * 128 * SA + row * SA + seg * 8) * 2);
            const hf* src = (sp ? g_xl : g_xh) + (size_t)(m0 + row) * OUTD + k0 + seg * 8;
            cpasync16(dst, src);
        }
        #pragma unroll
        for (int it = 0; it < 2; it++) {         // B: Wh only, 512 transfers
            int cid = tid + it * 256;
            int row = cid >> 2, seg = cid & 3;
            uint32_t dst = su + (uint32_t)((P_BH + bi * 128 * SA + row * SA + seg * 8) * 2);
            const hf* src = WhT + (size_t)row * OUTD + k0 + seg * 8;
            cpasync16(dst, src);
        }
        cpcommit();
    };

    stage(0, 0);

    float acc[2][8][4];
    #pragma unroll
    for (int i = 0; i < 2; i++)
        #pragma unroll
        for (int j = 0; j < 8; j++)
            #pragma unroll
            for (int t = 0; t < 4; t++) acc[i][j][t] = 0.f;

    const int la16 = l & 15;
    const int la8  = l >> 4;
    const int rB   = ((l >> 4) << 3) + (l & 7);
    const int cB8  = ((l >> 3) & 1) * 8;

    for (int kt = 0; kt < OUTD / KT; kt++) {
        if (kt < OUTD / KT - 1) { stage(kt + 1, (kt + 1) & 1); cpwait1(); }
        else cpwait0();
        __syncthreads();
        const int bi = kt & 1;
        const uint32_t ahb = su + (uint32_t)((P_AH + bi * 128 * SA) * 2);
        const uint32_t alb = su + (uint32_t)((P_AL + bi * 128 * SA) * 2);
        const uint32_t bhb = su + (uint32_t)((P_BH + bi * 128 * SA) * 2);

        #pragma unroll
        for (int hh = 0; hh < 2; hh++) {
            const int kb = hh * 16;
            uint32_t ah[2][4], al[2][4];
            #pragma unroll
            for (int mb = 0; mb < 2; mb++) {
                uint32_t off = (uint32_t)((wm * 32 + mb * 16 + la16) * SA * 2 + (kb + la8 * 8) * 2);
                ldmat4(ah[mb], ahb + off);
                ldmat4(al[mb], alb + off);
            }
            #pragma unroll
            for (int nbp = 0; nbp < 4; nbp++) {
                uint32_t off = (uint32_t)((wn * 64 + nbp * 16 + rB) * SA * 2 + (kb + cB8) * 2);
                uint32_t bh4[4];
                ldmat4(bh4, bhb + off);
                #pragma unroll
                for (int half = 0; half < 2; half++) {
                    int nb = nbp * 2 + half;
                    #pragma unroll
                    for (int mb = 0; mb < 2; mb++) {
                        mma16816h(acc[mb][nb], ah[mb], bh4[2 * half], bh4[2 * half + 1]);
                        mma16816h(acc[mb][nb], al[mb], bh4[2 * half], bh4[2 * half + 1]);
                    }
                }
            }
        }
        __syncthreads();
    }

    if (z <= 1) {
        const float fac = z ? 1.f : (SCALE * LOG2E);
        #pragma unroll
        for (int mb = 0; mb < 2; mb++) {
            #pragma unroll
            for (int rh = 0; rh < 2; rh++) {
                int r = wm * 32 + mb * 16 + lq + rh * 8;
                int m = m0 + r;
                int b = m / MPB;
                int t = m - b * MPB;
                if (t >= SEQL) continue;
                int iq = t >> 2, r4 = t & 3;
                #pragma unroll
                for (int nb = 0; nb < 8; nb++) {
                    int col = wn * 64 + nb * 8 + c * 2;
                    int head = hp * 2 + (col >> 6);
                    int d = col & 63;
                    int combo = (b * NHEAD + head) * RATE + r4;
                    size_t o = ((size_t)combo * NSUBP + iq) * 64 + d;
                    float v0 = acc[mb][nb][rh * 2 + 0] * fac;
                    float v1 = acc[mb][nb][rh * 2 + 1] * fac;
                    if (z == 0) {
                        uint32_t uh = packhf(v1, v0);
                        float2 f = unpackhf(uh);
                        *(uint32_t*)(g_Qh + o) = uh;
                        *(uint32_t*)(g_Ql + o) = packhf(v1 - f.y, v0 - f.x);
                    } else {
                        *(uint32_t*)(g_Kh + o) = packhf(v1, v0);
                    }
                }
            }
        }
        return;
    }

    // z==2: stage C, then Vf (fp32, row-major) + VTh (fp16, transposed)
    float* C = (float*)psm;
    #pragma unroll
    for (int mb = 0; mb < 2; mb++) {
        int r0 = wm * 32 + mb * 16 + lq;
        #pragma unroll
        for (int nb = 0; nb < 8; nb++) {
            int col = wn * 64 + nb * 8 + c * 2;
            *(float2*)(C + r0 * SC + col)       = make_float2(acc[mb][nb][0], acc[mb][nb][1]);
            *(float2*)(C + (r0 + 8) * SC + col) = make_float2(acc[mb][nb][2], acc[mb][nb][3]);
        }
    }
    __syncthreads();

    const int bb = m0 / MPB;
    const int t0 = m0 - bb * MPB;
    const bool fast = ((m0 + 127) / MPB == bb) && (t0 + 128 <= SEQL);

    if (fast) {
        const int iq0 = t0 >> 2;
        {
            int r = tid >> 1, hh2 = tid & 1;
            int head = hp * 2 + hh2;
            int t = t0 + r;
            int iq = t >> 2, r4 = t & 3;
            int combo = (bb * NHEAD + head) * RATE + r4;
            size_t orow = ((size_t)combo * NSUBP + iq) * 64;
            #pragma unroll
            for (int j = 0; j < 16; j++)
                *(float4*)(g_Vf + orow + j * 4) = *(const float4*)(C + r * SC + hh2 * 64 + j * 4);
        }
        {
            int hh2 = tid & 1;
            int head = hp * 2 + hh2;
            int tid2 = tid >> 1;
            int g = tid2 & 7, r4 = (tid2 >> 3) & 3, dl = tid2 >> 5;
            int combo = (bb * NHEAD + head) * RATE + r4;
            #pragma unroll
            for (int it = 0; it < 16; it++) {
                int d = it * 4 + dl;
                float v[4];
                #pragma unroll
                for (int j = 0; j < 4; j++) {
                    int r = (g * 4 + j) * 4 + r4;
                    v[j] = C[r * SC + hh2 * 64 + d];
                }
                uint2 uh = make_uint2(packhf(v[1], v[0]), packhf(v[3], v[2]));
                size_t o = ((size_t)combo * 64 + d) * NSUBP + iq0 + g * 4;
                *(uint2*)(g_VTh + o) = uh;
            }
        }
    } else {
        int r = tid >> 1, hh2 = tid & 1;
        int head = hp * 2 + hh2;
        int m = m0 + r;
        int b = m / MPB;
        int t = m - b * MPB;
        if (t < SEQL) {
            int iq = t >> 2, r4 = t & 3;
            int combo = (b * NHEAD + head) * RATE + r4;
            size_t orow = ((size_t)combo * NSUBP + iq) * 64;
            #pragma unroll
            for (int j = 0; j < 16; j++) {
                int d = j * 4;
                float4 v = *(const float4*)(C + r * SC + hh2 * 64 + d);
                *(float4*)(g_Vf + orow + d) = v;
                float vf[4] = {v.x, v.y, v.z, v.w};
                #pragma unroll
                for (int e = 0; e < 4; e++) {
                    size_t ot = ((size_t)combo * 64 + d + e) * NSUBP + iq;
                    g_VTh[ot] = __float2half_rn(vf[e]);
                }
            }
        }
    }
}

// ---------------------------------------------------------------------------
// Flash attention: QK 2-term, PV 1-term (ph only), fixed-max softmax.
// ---------------------------------------------------------------------------
#define SM_QH 0
#define SM_QL (BQ * SK)
#define SM_BUF (2 * BQ * SK)
#define BUF_SZ (2 * 64 * SK)
#define SMEM_BYTES 110592

__global__ __launch_bounds__(256, 2) void attn_kernel(float* __restrict__ out)
{
    extern __shared__ __align__(16) hf sm[];
    hf* QhS = sm + SM_QH;
    hf* QlS = sm + SM_QL;

    const int tid = threadIdx.x;
    const int w = tid >> 5, l = tid & 31;
    const int lq = l >> 2;
    const int c  = l & 3;
    const int combo = blockIdx.y;
    const int q0 = blockIdx.x * BQ;
    const uint32_t smem_u32 = (uint32_t)__cvta_generic_to_shared(sm);

    const size_t gq = (size_t)combo * NSUBP * 64;
    const size_t gvt = (size_t)combo * 64 * NSUBP;

    #pragma unroll
    for (int it = 0; it < 8; it++) {
        int cid = tid + it * 256;
        int arr = cid >> 10;
        int rem = cid & 1023;
        int row = rem >> 3, seg = rem & 7;
        uint32_t dst = smem_u32 + (uint32_t)(((arr ? SM_QL : SM_QH) + row * SK) * 2 + seg * 16);
        const hf* src = (arr ? g_Ql : g_Qh) + gq + (size_t)(q0 + row) * 64 + seg * 8;
        cpasync16(dst, src);
    }
    cpcommit();

    {
        #pragma unroll
        for (int it = 0; it < 4; it++) {
            int cid = tid + it * 256;
            int arr = cid >> 9;
            int rem = cid & 511;
            int row = rem >> 3, seg = rem & 7;
            uint32_t dst = smem_u32 + (uint32_t)((SM_BUF + arr * 64 * SK + row * SK) * 2 + seg * 16);
            const hf* src = (arr == 0) ? g_Kh + gq + (size_t)row * 64 + seg * 8
                                       : g_VTh + gvt + (size_t)row * NSUBP + seg * 8;
            cpasync16(dst, src);
        }
        cpcommit();
    }
    cpwait0();
    __syncthreads();

    uint32_t qh[4][4], ql[4][4];
    {
        const int la16 = l & 15, la8 = l >> 4;
        uint32_t qhb = smem_u32 + (uint32_t)((SM_QH + (w * 16 + la16) * SK) * 2);
        uint32_t qlb = smem_u32 + (uint32_t)((SM_QL + (w * 16 + la16) * SK) * 2);
        #pragma unroll
        for (int kc = 0; kc < 4; kc++) {
            uint32_t off = (uint32_t)((kc * 16 + la8 * 8) * 2);
            ldmat4(qh[kc], qhb + off);
            ldmat4(ql[kc], qlb + off);
        }
    }

    float oacc[8][4];
    #pragma unroll
    for (int j = 0; j < 8; j++)
        #pragma unroll
        for (int t = 0; t < 4; t++) oacc[j][t] = 0.f;
    float l0 = 0.f, l1 = 0.f;

    const int lrow8 = l & 7;
    const int lcol8 = l >> 3;
    const uint32_t boff_lane = (uint32_t)(lrow8 * SK * 2 + lcol8 * 16);

    for (int kt = 0; kt < 16; kt++) {
        __syncthreads();
        if (kt < 15) {
            const int ks = (kt + 1) * 64;
            const int boff = SM_BUF + ((kt + 1) & 1) * BUF_SZ;
            #pragma unroll
            for (int it = 0; it < 4; it++) {
                int cid = tid + it * 256;
                int arr = cid >> 9;
                int rem = cid & 511;
                int row = rem >> 3, seg = rem & 7;
                uint32_t dst = smem_u32 + (uint32_t)((boff + arr * 64 * SK + row * SK) * 2 + seg * 16);
                const hf* src = (arr == 0) ? g_Kh + gq + (size_t)(ks + row) * 64 + seg * 8
                                           : g_VTh + gvt + (size_t)row * NSUBP + ks + seg * 8;
                cpasync16(dst, src);
            }
            cpcommit();
            cpwait1();
        } else {
            cpwait0();
        }
        __syncthreads();

        const int bufbase = SM_BUF + (kt & 1) * BUF_SZ;
        const uint32_t khb = smem_u32 + (uint32_t)((bufbase) * 2) + boff_lane;
        const uint32_t vhb = smem_u32 + (uint32_t)((bufbase + 64 * SK) * 2) + boff_lane;

        // ---- S = Q K^T : (qh + ql) x kh ----
        float sacc[8][4];
        #pragma unroll
        for (int j = 0; j < 8; j++) {
            #pragma unroll
            for (int t = 0; t < 4; t++) sacc[j][t] = 0.f;
            uint32_t bh[8];
            uint32_t a = khb + (uint32_t)(j * 8 * SK * 2);
            ldmat4(bh, a); ldmat4(bh + 4, a + 64);
            #pragma unroll
            for (int kc = 0; kc < 4; kc++) {
                mma16816h(sacc[j], qh[kc], bh[2 * kc], bh[2 * kc + 1]);
                mma16816h(sacc[j], ql[kc], bh[2 * kc], bh[2 * kc + 1]);
            }
        }

        // ---- absolute softmax (fixed max 0), per-lane partial l ----
        #pragma unroll
        for (int j = 0; j < 8; j++) {
            sacc[j][0] = exp2f(sacc[j][0]);
            sacc[j][1] = exp2f(sacc[j][1]);
            sacc[j][2] = exp2f(sacc[j][2]);
            sacc[j][3] = exp2f(sacc[j][3]);
            l0 += sacc[j][0] + sacc[j][1];
            l1 += sacc[j][2] + sacc[j][3];
        }

        // ---- P fragments (fp16 hi only) ----
        uint32_t pah[4][4];
        #pragma unroll
        for (int kc = 0; kc < 4; kc++) {
            int j0 = 2 * kc, j1 = 2 * kc + 1;
            pah[kc][0] = packhf(sacc[j0][1], sacc[j0][0]);
            pah[kc][1] = packhf(sacc[j0][3], sacc[j0][2]);
            pah[kc][2] = packhf(sacc[j1][1], sacc[j1][0]);
            pah[kc][3] = packhf(sacc[j1][3], sacc[j1][2]);
        }

        // ---- PV : ph x vh ----
        #pragma unroll
        for (int j = 0; j < 8; j++) {
            uint32_t bh[8];
            uint32_t a = vhb + (uint32_t)(j * 8 * SK * 2);
            ldmat4(bh, a); ldmat4(bh + 4, a + 64);
            #pragma unroll
            for (int kc = 0; kc < 4; kc++)
                mma16816h(oacc[j], pah[kc], bh[2 * kc], bh[2 * kc + 1]);
        }
    }

    // ---- band pass (7 banded logits) + zero pad key (adds 1 to l) ----
    __syncthreads();
    float* Kband = (float*)(sm + SM_BUF);
    float* Vband = Kband + 134 * BSW;
    for (int i = tid; i < 134 * 64; i += 256) {
        int rr = i >> 6, d = i & 63;
        int g = q0 - 3 + rr;
        float kv = 0.f, vv = 0.f;
        if (g >= 0) {
            size_t o = gq + (size_t)g * 64 + d;
            kv = __half2float(g_Kh[o]);
            vv = g_Vf[o];
        }
        Kband[rr * BSW + d] = kv;
        Vband[rr * BSW + d] = vv;
    }
    __syncthreads();

    float bl[2][2];
    #pragma unroll
    for (int rh = 0; rh < 2; rh++) {
        int qlcl = w * 16 + lq + 8 * rh;
        int kk0 = c, kk1 = c + 4;
        float acc0 = 0.f, acc1 = 0.f;
        const float* kb0 = Kband + (qlcl + kk0) * BSW;
        const float* kb1 = Kband + (qlcl + kk1) * BSW;
        #pragma unroll 8
        for (int d = 0; d < 64; d++) {
            float qf = __half2float(QhS[qlcl * SK + d]) + __half2float(QlS[qlcl * SK + d]);
            acc0 += qf * kb0[d];
            if (kk1 < 7) acc1 += qf * kb1[d];
        }
        bl[rh][0] = acc0;
        bl[rh][1] = acc1;
    }

    {
        float p00 = exp2f(bl[0][0]);
        float p01 = (c + 4 < 7) ? exp2f(bl[0][1]) : 0.f;
        float p10 = exp2f(bl[1][0]);
        float p11 = (c + 4 < 7) ? exp2f(bl[1][1]) : 0.f;
        l0 += p00 + p01 + ((c == 0) ? 1.f : 0.f);
        l1 += p10 + p11 + ((c == 0) ? 1.f : 0.f);

        int r0 = w * 16 + lq;
        #pragma unroll
        for (int kk = 0; kk < 7; kk++) {
            int src = (l & ~3) | (kk & 3);
            float pb0 = __shfl_sync(0xffffffffu, (kk < 4) ? p00 : p01, src);
            float pb1 = __shfl_sync(0xffffffffu, (kk < 4) ? p10 : p11, src);
            const float* v0 = Vband + (r0 + kk) * BSW + c * 2;
            const float* v1 = Vband + (r0 + 8 + kk) * BSW + c * 2;
            #pragma unroll
            for (int j = 0; j < 8; j++) {
                float2 a = *(const float2*)(v0 + j * 8);
                float2 bq = *(const float2*)(v1 + j * 8);
                oacc[j][0] += pb0 * a.x; oacc[j][1] += pb0 * a.y;
                oacc[j][2] += pb1 * bq.x; oacc[j][3] += pb1 * bq.y;
            }
        }
    }

    // ---- epilogue: quad-reduce l, normalize, store ----
    l0 += __shfl_xor_sync(0xffffffffu, l0, 1);
    l0 += __shfl_xor_sync(0xffffffffu, l0, 2);
    l1 += __shfl_xor_sync(0xffffffffu, l1, 1);
    l1 += __shfl_xor_sync(0xffffffffu, l1, 2);

    const int b = combo >> 5;
    const int h = (combo >> 2) & 7;
    const int r = combo & 3;
    float inv0 = 1.f / l0, inv1 = 1.f / l1;
    int qg = q0 + w * 16 + lq;
    size_t o0 = ((size_t)(b * SEQL + qg * 4 + r)) * OUTD + h * 64 + c * 2;
    size_t o1 = ((size_t)(b * SEQL + (qg + 8) * 4 + r)) * OUTD + h * 64 + c * 2;
    #pragma unroll
    for (int j = 0; j < 8; j++) {
        *(float2*)(out + o0 + j * 8) = make_float2(oacc[j][0] * inv0, oacc[j][1] * inv0);
        *(float2*)(out + o1 + j * 8) = make_float2(oacc[j][2] * inv1, oacc[j][3] * inv1);
    }
}

// ---------------------------------------------------------------------------
extern "C" void kernel_launch(void* const* d_in, const int* in_sizes, int n_in,
                              void* d_out, int out_size)
{
    const float* x  = (const float*)d_in[0];
    const float* Wq = (const float*)d_in[1];
    const float* Wk = (const float*)d_in[2];
    const float* Wv = (const float*)d_in[3];
    float* out = (float*)d_out;

    cudaFuncSetAttribute(attn_kernel, cudaFuncAttributeMaxDynamicSharedMemorySize, SMEM_BYTES);
    cudaFuncSetAttribute(proj_tc_kernel, cudaFuncAttributeMaxDynamicSharedMemorySize, P_SMEM_BYTES);

    splitx_kernel<<<(BATCH * SEQL * OUTD / 4) / 256, 256>>>(x);
    splitw_kernel<<<dim3(OUTD, 3), 256>>>(Wq, Wk, Wv);

    dim3 pgrid(3, NHEAD / 2, MXP / 128);        // z, head-pair, m-tile
    proj_tc_kernel<<<pgrid, 256, P_SMEM_BYTES>>>();

    dim3 agrid(SEQL / RATE / BQ, NCOMBO);
    attn_kernel<<<agrid, 256, SMEM_BYTES>>>(out);
}

// round 15
// speedup vs baseline: 1.8268x; 1.0718x over previous
#include <cuda_runtime.h>
#include <cuda_fp16.h>
#include <cstdint>

#define BATCH 2
#define SEQL  4096
#define OUTD  512
#define NHEAD 8
#define RATE  4
#define NSUB  1025
#define NSUBP 1088
#define NCOMBO 64
#define SCALE 0.125f
#define LOG2E 1.44269504088896340736f

#define MPB   4160
#define MXP   (2 * MPB)     // 8320 = 65 * 128

#define BQ 128
#define SK 72
#define BSW 68

typedef __half hf;

// fp16 scratch (zero-init; pad keys >= 1024 stay zero)
__device__ hf g_Qh[(size_t)NCOMBO * NSUBP * 64];            // fp16-single Q (pre-scaled)
__device__ hf g_Kh[(size_t)NCOMBO * NSUBP * 64];
__device__ hf g_VTh[(size_t)NCOMBO * 64 * NSUBP];
__device__ float g_Vf[(size_t)NCOMBO * NSUBP * 64];
__device__ hf g_xh[(size_t)MXP * OUTD];
__device__ hf g_xl[(size_t)MXP * OUTD];
__device__ hf g_WhT[3][OUTD * OUTD];

__device__ __forceinline__ uint32_t packhf(float hi, float lo) {
    uint32_t r; asm("cvt.rn.f16x2.f32 %0, %1, %2;" : "=r"(r) : "f"(hi), "f"(lo)); return r;
}
__device__ __forceinline__ void cpasync16(uint32_t s, const void* g) {
    asm volatile("cp.async.cg.shared.global [%0], [%1], 16;\n" :: "r"(s), "l"(g));
}
__device__ __forceinline__ void cpcommit() { asm volatile("cp.async.commit_group;\n"); }
__device__ __forceinline__ void cpwait0()  { asm volatile("cp.async.wait_group 0;\n"); }
__device__ __forceinline__ void cpwait1()  { asm volatile("cp.async.wait_group 1;\n"); }

__device__ __forceinline__ void mma16816h(float* d, const uint32_t* a, uint32_t b0, uint32_t b1) {
    asm volatile("mma.sync.aligned.m16n8k16.row.col.f32.f16.f16.f32 "
        "{%0,%1,%2,%3}, {%4,%5,%6,%7}, {%8,%9}, {%0,%1,%2,%3};"
        : "+f"(d[0]), "+f"(d[1]), "+f"(d[2]), "+f"(d[3])
        : "r"(a[0]), "r"(a[1]), "r"(a[2]), "r"(a[3]), "r"(b0), "r"(b1));
}
__device__ __forceinline__ void ldmat4(uint32_t* r, uint32_t addr) {
    asm volatile("ldmatrix.sync.aligned.m8n8.x4.shared.b16 {%0,%1,%2,%3}, [%4];"
        : "=r"(r[0]), "=r"(r[1]), "=r"(r[2]), "=r"(r[3]) : "r"(addr));
}

// ---------------------------------------------------------------------------
__global__ __launch_bounds__(256) void splitx_kernel(const float* __restrict__ x)
{
    int idx = blockIdx.x * 256 + threadIdx.x;
    int flat = idx * 4;
    int b = flat / (SEQL * OUTD);
    int rem = flat - b * (SEQL * OUTD);
    int t = rem / OUTD;
    int k = rem - t * OUTD;
    float4 v = *(const float4*)(x + (size_t)flat);
    size_t o = ((size_t)(b * MPB + t)) * OUTD + k;
    float hx = __half2float(__float2half_rn(v.x));
    float hy = __half2float(__float2half_rn(v.y));
    float hz = __half2float(__float2half_rn(v.z));
    float hw = __half2float(__float2half_rn(v.w));
    *(uint2*)(g_xh + o) = make_uint2(packhf(hy, hx), packhf(hw, hz));
    *(uint2*)(g_xl + o) = make_uint2(packhf(v.y - hy, v.x - hx), packhf(v.w - hw, v.z - hz));
}

__global__ __launch_bounds__(256) void splitw_kernel(
    const float* __restrict__ Wq, const float* __restrict__ Wk, const float* __restrict__ Wv)
{
    int k = blockIdx.x, z = blockIdx.y;
    const float* W = (z == 0) ? Wq : (z == 1) ? Wk : Wv;
    #pragma unroll
    for (int half = 0; half < 2; half++) {
        int n = threadIdx.x + half * 256;
        g_WhT[z][(size_t)n * OUTD + k] = __float2half_rn(W[(size_t)k * OUTD + n]);
    }
}

// ---------------------------------------------------------------------------
// Tensor-core projection: fp16 2-term split ((xh + xl) * Wh). Unchanged R14.
// ---------------------------------------------------------------------------
#define KT 32
#define SA 40
#define P_AH 0
#define P_AL (2 * 128 * SA)
#define P_BH (4 * 128 * SA)
#define SC 132
#define P_SMEM_BYTES 81920

__global__ __launch_bounds__(256, 2) void proj_tc_kernel()
{
    extern __shared__ __align__(16) hf psm[];
    const int tid = threadIdx.x;
    const int w = tid >> 5, l = tid & 31;
    const int lq = l >> 2, c = l & 3;
    const int wm = w & 3, wn = w >> 2;
    const int z  = blockIdx.x;
    const int hp = blockIdx.y;
    const int m0 = blockIdx.z * 128;
    const int n0 = hp * 128;
    const uint32_t su = (uint32_t)__cvta_generic_to_shared(psm);

    const hf* WhT = g_WhT[z] + (size_t)n0 * OUTD;

    auto stage = [&](int kt, int bi) {
        const int k0 = kt * KT;
        #pragma unroll
        for (int it = 0; it < 4; it++) {
            int cid = tid + it * 256;
            int sp = cid >> 9, rem = cid & 511;
            int row = rem >> 2, seg = rem & 3;
            uint32_t dst = su + (uint32_t)(((sp ? P_AL : P_AH) + bi * 128 * SA + row * SA + seg * 8) * 2);
            const hf* src = (sp ? g_xl : g_xh) + (size_t)(m0 + row) * OUTD + k0 + seg * 8;
            cpasync16(dst, src);
        }
        #pragma unroll
        for (int it = 0; it < 2; it++) {
            int cid = tid + it * 256;
            int row = cid >> 2, seg = cid & 3;
            uint32_t dst = su + (uint32_t)((P_BH + bi * 128 * SA + row * SA + seg * 8) * 2);
            const hf* src = WhT + (size_t)row * OUTD + k0 + seg * 8;
            cpasync16(dst, src);
        }
        cpcommit();
    };

    stage(0, 0);

    float acc[2][8][4];
    #pragma unroll
    for (int i = 0; i < 2; i++)
        #pragma unroll
        for (int j = 0; j < 8; j++)
            #pragma unroll
            for (int t = 0; t < 4; t++) acc[i][j][t] = 0.f;

    const int la16 = l & 15;
    const int la8  = l >> 4;
    const int rB   = ((l >> 4) << 3) + (l & 7);
    const int cB8  = ((l >> 3) & 1) * 8;

    for (int kt = 0; kt < OUTD / KT; kt++) {
        if (kt < OUTD / KT - 1) { stage(kt + 1, (kt + 1) & 1); cpwait1(); }
        else cpwait0();
        __syncthreads();
        const int bi = kt & 1;
        const uint32_t ahb = su + (uint32_t)((P_AH + bi * 128 * SA) * 2);
        const uint32_t alb = su + (uint32_t)((P_AL + bi * 128 * SA) * 2);
        const uint32_t bhb = su + (uint32_t)((P_BH + bi * 128 * SA) * 2);

        #pragma unroll
        for (int hh = 0; hh < 2; hh++) {
            const int kb = hh * 16;
            uint32_t ah[2][4], al[2][4];
            #pragma unroll
            for (int mb = 0; mb < 2; mb++) {
                uint32_t off = (uint32_t)((wm * 32 + mb * 16 + la16) * SA * 2 + (kb + la8 * 8) * 2);
                ldmat4(ah[mb], ahb + off);
                ldmat4(al[mb], alb + off);
            }
            #pragma unroll
            for (int nbp = 0; nbp < 4; nbp++) {
                uint32_t off = (uint32_t)((wn * 64 + nbp * 16 + rB) * SA * 2 + (kb + cB8) * 2);
                uint32_t bh4[4];
                ldmat4(bh4, bhb + off);
                #pragma unroll
                for (int half = 0; half < 2; half++) {
                    int nb = nbp * 2 + half;
                    #pragma unroll
                    for (int mb = 0; mb < 2; mb++) {
                        mma16816h(acc[mb][nb], ah[mb], bh4[2 * half], bh4[2 * half + 1]);
                        mma16816h(acc[mb][nb], al[mb], bh4[2 * half], bh4[2 * half + 1]);
                    }
                }
            }
        }
        __syncthreads();
    }

    if (z <= 1) {
        hf* G = z ? g_Kh : g_Qh;
        const float fac = z ? 1.f : (SCALE * LOG2E);
        #pragma unroll
        for (int mb = 0; mb < 2; mb++) {
            #pragma unroll
            for (int rh = 0; rh < 2; rh++) {
                int r = wm * 32 + mb * 16 + lq + rh * 8;
                int m = m0 + r;
                int b = m / MPB;
                int t = m - b * MPB;
                if (t >= SEQL) continue;
                int iq = t >> 2, r4 = t & 3;
                #pragma unroll
                for (int nb = 0; nb < 8; nb++) {
                    int col = wn * 64 + nb * 8 + c * 2;
                    int head = hp * 2 + (col >> 6);
                    int d = col & 63;
                    int combo = (b * NHEAD + head) * RATE + r4;
                    size_t o = ((size_t)combo * NSUBP + iq) * 64 + d;
                    float v0 = acc[mb][nb][rh * 2 + 0] * fac;
                    float v1 = acc[mb][nb][rh * 2 + 1] * fac;
                    *(uint32_t*)(G + o) = packhf(v1, v0);
                }
            }
        }
        return;
    }

    // z==2: stage C, then Vf (fp32, row-major) + VTh (fp16, transposed)
    float* C = (float*)psm;
    #pragma unroll
    for (int mb = 0; mb < 2; mb++) {
        int r0 = wm * 32 + mb * 16 + lq;
        #pragma unroll
        for (int nb = 0; nb < 8; nb++) {
            int col = wn * 64 + nb * 8 + c * 2;
            *(float2*)(C + r0 * SC + col)       = make_float2(acc[mb][nb][0], acc[mb][nb][1]);
            *(float2*)(C + (r0 + 8) * SC + col) = make_float2(acc[mb][nb][2], acc[mb][nb][3]);
        }
    }
    __syncthreads();

    const int bb = m0 / MPB;
    const int t0 = m0 - bb * MPB;
    const bool fast = ((m0 + 127) / MPB == bb) && (t0 + 128 <= SEQL);

    if (fast) {
        const int iq0 = t0 >> 2;
        {
            int r = tid >> 1, hh2 = tid & 1;
            int head = hp * 2 + hh2;
            int t = t0 + r;
            int iq = t >> 2, r4 = t & 3;
            int combo = (bb * NHEAD + head) * RATE + r4;
            size_t orow = ((size_t)combo * NSUBP + iq) * 64;
            #pragma unroll
            for (int j = 0; j < 16; j++)
                *(float4*)(g_Vf + orow + j * 4) = *(const float4*)(C + r * SC + hh2 * 64 + j * 4);
        }
        {
            int hh2 = tid & 1;
            int head = hp * 2 + hh2;
            int tid2 = tid >> 1;
            int g = tid2 & 7, r4 = (tid2 >> 3) & 3, dl = tid2 >> 5;
            int combo = (bb * NHEAD + head) * RATE + r4;
            #pragma unroll
            for (int it = 0; it < 16; it++) {
                int d = it * 4 + dl;
                float v[4];
                #pragma unroll
                for (int j = 0; j < 4; j++) {
                    int r = (g * 4 + j) * 4 + r4;
                    v[j] = C[r * SC + hh2 * 64 + d];
                }
                uint2 uh = make_uint2(packhf(v[1], v[0]), packhf(v[3], v[2]));
                size_t o = ((size_t)combo * 64 + d) * NSUBP + iq0 + g * 4;
                *(uint2*)(g_VTh + o) = uh;
            }
        }
    } else {
        int r = tid >> 1, hh2 = tid & 1;
        int head = hp * 2 + hh2;
        int m = m0 + r;
        int b = m / MPB;
        int t = m - b * MPB;
        if (t < SEQL) {
            int iq = t >> 2, r4 = t & 3;
            int combo = (b * NHEAD + head) * RATE + r4;
            size_t orow = ((size_t)combo * NSUBP + iq) * 64;
            #pragma unroll
            for (int j = 0; j < 16; j++) {
                int d = j * 4;
                float4 v = *(const float4*)(C + r * SC + hh2 * 64 + d);
                *(float4*)(g_Vf + orow + d) = v;
                float vf[4] = {v.x, v.y, v.z, v.w};
                #pragma unroll
                for (int e = 0; e < 4; e++) {
                    size_t ot = ((size_t)combo * 64 + d + e) * NSUBP + iq;
                    g_VTh[ot] = __float2half_rn(vf[e]);
                }
            }
        }
    }
}

// ---------------------------------------------------------------------------
// Flash attention: Q fp16-single (QK 1-term), PV 1-term, fixed-max softmax,
// BK=128 staging (two 64-key subpasses per staged buffer).
// ---------------------------------------------------------------------------
#define SM_QH 0
#define SM_BUF (BQ * SK)                         // 9216 elems = 18432 B
#define TILEU (2 * 64 * SK)                      // one 64-key tile pair (Kh+VTh)
#define BUF128 (2 * TILEU)                       // one 128-key buffer
#define SMEM_BYTES ((SM_BUF + 2 * BUF128) * 2)   // 92160 B

__global__ __launch_bounds__(256, 2) void attn_kernel(float* __restrict__ out)
{
    extern __shared__ __align__(16) hf sm[];
    hf* QhS = sm + SM_QH;

    const int tid = threadIdx.x;
    const int w = tid >> 5, l = tid & 31;
    const int lq = l >> 2;
    const int c  = l & 3;
    const int combo = blockIdx.y;
    const int q0 = blockIdx.x * BQ;
    const uint32_t smem_u32 = (uint32_t)__cvta_generic_to_shared(sm);

    const size_t gq = (size_t)combo * NSUBP * 64;
    const size_t gvt = (size_t)combo * 64 * NSUBP;

    // Q staging (fp16 single): 1024 x 16B
    #pragma unroll
    for (int it = 0; it < 4; it++) {
        int cid = tid + it * 256;
        int row = cid >> 3, seg = cid & 7;
        uint32_t dst = smem_u32 + (uint32_t)((SM_QH + row * SK) * 2 + seg * 16);
        cpasync16(dst, g_Qh + gq + (size_t)(q0 + row) * 64 + seg * 8);
    }
    cpcommit();

    // stage 128-key buffer: 2048 x 16B
    auto stageB = [&](int ks, int buf) {
        #pragma unroll
        for (int it = 0; it < 8; it++) {
            int cid = tid + it * 256;
            int ts = cid >> 10;                  // sub-tile 0/1
            int rem = cid & 1023;
            int arr = rem >> 9;                  // 0 = Kh, 1 = VTh
            int rem2 = rem & 511;
            int row = rem2 >> 3, seg = rem2 & 7;
            uint32_t dst = smem_u32 + (uint32_t)((SM_BUF + buf * BUF128 + ts * TILEU
                                                  + arr * 64 * SK + row * SK) * 2 + seg * 16);
            const hf* src = (arr == 0)
                ? g_Kh + gq + (size_t)(ks + ts * 64 + row) * 64 + seg * 8
                : g_VTh + gvt + (size_t)row * NSUBP + ks + ts * 64 + seg * 8;
            cpasync16(dst, src);
        }
        cpcommit();
    };
    stageB(0, 0);
    cpwait0();
    __syncthreads();

    uint32_t qh[4][4];
    {
        const int la16 = l & 15, la8 = l >> 4;
        uint32_t qhb = smem_u32 + (uint32_t)((SM_QH + (w * 16 + la16) * SK) * 2);
        #pragma unroll
        for (int kc = 0; kc < 4; kc++)
            ldmat4(qh[kc], qhb + (uint32_t)((kc * 16 + la8 * 8) * 2));
    }

    float oacc[8][4];
    #pragma unroll
    for (int j = 0; j < 8; j++)
        #pragma unroll
        for (int t = 0; t < 4; t++) oacc[j][t] = 0.f;
    float l0 = 0.f, l1 = 0.f;

    const int lrow8 = l & 7;
    const int lcol8 = l >> 3;
    const uint32_t boff_lane = (uint32_t)(lrow8 * SK * 2 + lcol8 * 16);

    for (int kt2 = 0; kt2 < 8; kt2++) {
        __syncthreads();
        if (kt2 < 7) {
            stageB((kt2 + 1) * 128, (kt2 + 1) & 1);
            cpwait1();
        } else {
            cpwait0();
        }
        __syncthreads();

        #pragma unroll
        for (int s = 0; s < 2; s++) {
            const int tb = SM_BUF + (kt2 & 1) * BUF128 + s * TILEU;
            const uint32_t khb = smem_u32 + (uint32_t)(tb * 2) + boff_lane;
            const uint32_t vhb = smem_u32 + (uint32_t)((tb + 64 * SK) * 2) + boff_lane;

            // ---- S = Q K^T : qh x kh ----
            float sacc[8][4];
            #pragma unroll
            for (int j = 0; j < 8; j++) {
                #pragma unroll
                for (int t = 0; t < 4; t++) sacc[j][t] = 0.f;
                uint32_t bh[8];
                uint32_t a = khb + (uint32_t)(j * 8 * SK * 2);
                ldmat4(bh, a); ldmat4(bh + 4, a + 64);
                #pragma unroll
                for (int kc = 0; kc < 4; kc++)
                    mma16816h(sacc[j], qh[kc], bh[2 * kc], bh[2 * kc + 1]);
            }

            // ---- absolute softmax (fixed max 0), per-lane partial l ----
            #pragma unroll
            for (int j = 0; j < 8; j++) {
                sacc[j][0] = exp2f(sacc[j][0]);
                sacc[j][1] = exp2f(sacc[j][1]);
                sacc[j][2] = exp2f(sacc[j][2]);
                sacc[j][3] = exp2f(sacc[j][3]);
                l0 += sacc[j][0] + sacc[j][1];
                l1 += sacc[j][2] + sacc[j][3];
            }

            // ---- P fragments (fp16 hi only) ----
            uint32_t pah[4][4];
            #pragma unroll
            for (int kc = 0; kc < 4; kc++) {
                int j0 = 2 * kc, j1 = 2 * kc + 1;
                pah[kc][0] = packhf(sacc[j0][1], sacc[j0][0]);
                pah[kc][1] = packhf(sacc[j0][3], sacc[j0][2]);
                pah[kc][2] = packhf(sacc[j1][1], sacc[j1][0]);
                pah[kc][3] = packhf(sacc[j1][3], sacc[j1][2]);
            }

            // ---- PV : ph x vh ----
            #pragma unroll
            for (int j = 0; j < 8; j++) {
                uint32_t bh[8];
                uint32_t a = vhb + (uint32_t)(j * 8 * SK * 2);
                ldmat4(bh, a); ldmat4(bh + 4, a + 64);
                #pragma unroll
                for (int kc = 0; kc < 4; kc++)
                    mma16816h(oacc[j], pah[kc], bh[2 * kc], bh[2 * kc + 1]);
            }
        }
    }

    // ---- band pass (7 banded logits) + zero pad key (adds 1 to l) ----
    __syncthreads();
    float* Kband = (float*)(sm + SM_BUF);
    float* Vband = Kband + 134 * BSW;
    for (int i = tid; i < 134 * 64; i += 256) {
        int rr = i >> 6, d = i & 63;
        int g = q0 - 3 + rr;
        float kv = 0.f, vv = 0.f;
        if (g >= 0) {
            size_t o = gq + (size_t)g * 64 + d;
            kv = __half2float(g_Kh[o]);
            vv = g_Vf[o];
        }
        Kband[rr * BSW + d] = kv;
        Vband[rr * BSW + d] = vv;
    }
    __syncthreads();

    float bl[2][2];
    #pragma unroll
    for (int rh = 0; rh < 2; rh++) {
        int qlcl = w * 16 + lq + 8 * rh;
        int kk0 = c, kk1 = c + 4;
        float acc0 = 0.f, acc1 = 0.f;
        const float* kb0 = Kband + (qlcl + kk0) * BSW;
        const float* kb1 = Kband + (qlcl + kk1) * BSW;
        #pragma unroll 8
        for (int d = 0; d < 64; d++) {
            float qf = __half2float(QhS[qlcl * SK + d]);
            acc0 += qf * kb0[d];
            if (kk1 < 7) acc1 += qf * kb1[d];
        }
        bl[rh][0] = acc0;
        bl[rh][1] = acc1;
    }

    {
        float p00 = exp2f(bl[0][0]);
        float p01 = (c + 4 < 7) ? exp2f(bl[0][1]) : 0.f;
        float p10 = exp2f(bl[1][0]);
        float p11 = (c + 4 < 7) ? exp2f(bl[1][1]) : 0.f;
        l0 += p00 + p01 + ((c == 0) ? 1.f : 0.f);
        l1 += p10 + p11 + ((c == 0) ? 1.f : 0.f);

        int r0 = w * 16 + lq;
        #pragma unroll
        for (int kk = 0; kk < 7; kk++) {
            int src = (l & ~3) | (kk & 3);
            float pb0 = __shfl_sync(0xffffffffu, (kk < 4) ? p00 : p01, src);
            float pb1 = __shfl_sync(0xffffffffu, (kk < 4) ? p10 : p11, src);
            const float* v0 = Vband + (r0 + kk) * BSW + c * 2;
            const float* v1 = Vband + (r0 + 8 + kk) * BSW + c * 2;
            #pragma unroll
            for (int j = 0; j < 8; j++) {
                float2 a = *(const float2*)(v0 + j * 8);
                float2 bq = *(const float2*)(v1 + j * 8);
                oacc[j][0] += pb0 * a.x; oacc[j][1] += pb0 * a.y;
                oacc[j][2] += pb1 * bq.x; oacc[j][3] += pb1 * bq.y;
            }
        }
    }

    // ---- epilogue: quad-reduce l, normalize, store ----
    l0 += __shfl_xor_sync(0xffffffffu, l0, 1);
    l0 += __shfl_xor_sync(0xffffffffu, l0, 2);
    l1 += __shfl_xor_sync(0xffffffffu, l1, 1);
    l1 += __shfl_xor_sync(0xffffffffu, l1, 2);

    const int b = combo >> 5;
    const int h = (combo >> 2) & 7;
    const int r = combo & 3;
    float inv0 = 1.f / l0, inv1 = 1.f / l1;
    int qg = q0 + w * 16 + lq;
    size_t o0 = ((size_t)(b * SEQL + qg * 4 + r)) * OUTD + h * 64 + c * 2;
    size_t o1 = ((size_t)(b * SEQL + (qg + 8) * 4 + r)) * OUTD + h * 64 + c * 2;
    #pragma unroll
    for (int j = 0; j < 8; j++) {
        *(float2*)(out + o0 + j * 8) = make_float2(oacc[j][0] * inv0, oacc[j][1] * inv0);
        *(float2*)(out + o1 + j * 8) = make_float2(oacc[j][2] * inv1, oacc[j][3] * inv1);
    }
}

// ---------------------------------------------------------------------------
extern "C" void kernel_launch(void* const* d_in, const int* in_sizes, int n_in,
                              void* d_out, int out_size)
{
    const float* x  = (const float*)d_in[0];
    const float* Wq = (const float*)d_in[1];
    const float* Wk = (const float*)d_in[2];
    const float* Wv = (const float*)d_in[3];
    float* out = (float*)d_out;

    cudaFuncSetAttribute(attn_kernel, cudaFuncAttributeMaxDynamicSharedMemorySize, SMEM_BYTES);
    cudaFuncSetAttribute(proj_tc_kernel, cudaFuncAttributeMaxDynamicSharedMemorySize, P_SMEM_BYTES);

    splitx_kernel<<<(BATCH * SEQL * OUTD / 4) / 256, 256>>>(x);
    splitw_kernel<<<dim3(OUTD, 3), 256>>>(Wq, Wk, Wv);

    dim3 pgrid(3, NHEAD / 2, MXP / 128);        // z, head-pair, m-tile
    proj_tc_kernel<<<pgrid, 256, P_SMEM_BYTES>>>();

    dim3 agrid(SEQL / RATE / BQ, NCOMBO);
    attn_kernel<<<agrid, 256, SMEM_BYTES>>>(out);
}

// round 16
// speedup vs baseline: 2.1844x; 1.1958x over previous
#include <cuda_runtime.h>
#include <cuda_fp16.h>
#include <cstdint>

#define BATCH 2
#define SEQL  4096
#define OUTD  512
#define NHEAD 8
#define RATE  4
#define NSUB  1025
#define NSUBP 1088
#define NCOMBO 64
#define SCALE 0.125f
#define LOG2E 1.44269504088896340736f

#define MPB   4160
#define MXP   (2 * MPB)     // 8320 = 65 * 128

#define BQ 128
#define SK 72
#define BSW 68

typedef __half hf;

// fp16 scratch (zero-init; pad keys >= 1024 stay zero)
__device__ hf g_Qh[(size_t)NCOMBO * NSUBP * 64];
__device__ hf g_Kh[(size_t)NCOMBO * NSUBP * 64];
__device__ hf g_VTh[(size_t)NCOMBO * 64 * NSUBP];
__device__ float g_Vf[(size_t)NCOMBO * NSUBP * 64];
__device__ hf g_xh[(size_t)MXP * OUTD];
__device__ hf g_WhT[3][OUTD * OUTD];

__device__ __forceinline__ uint32_t packhf(float hi, float lo) {
    uint32_t r; asm("cvt.rn.f16x2.f32 %0, %1, %2;" : "=r"(r) : "f"(hi), "f"(lo)); return r;
}
__device__ __forceinline__ void cpasync16(uint32_t s, const void* g) {
    asm volatile("cp.async.cg.shared.global [%0], [%1], 16;\n" :: "r"(s), "l"(g));
}
__device__ __forceinline__ void cpcommit() { asm volatile("cp.async.commit_group;\n"); }
__device__ __forceinline__ void cpwait0()  { asm volatile("cp.async.wait_group 0;\n"); }
__device__ __forceinline__ void cpwait1()  { asm volatile("cp.async.wait_group 1;\n"); }

__device__ __forceinline__ void mma16816h(float* d, const uint32_t* a, uint32_t b0, uint32_t b1) {
    asm volatile("mma.sync.aligned.m16n8k16.row.col.f32.f16.f16.f32 "
        "{%0,%1,%2,%3}, {%4,%5,%6,%7}, {%8,%9}, {%0,%1,%2,%3};"
        : "+f"(d[0]), "+f"(d[1]), "+f"(d[2]), "+f"(d[3])
        : "r"(a[0]), "r"(a[1]), "r"(a[2]), "r"(a[3]), "r"(b0), "r"(b1));
}
__device__ __forceinline__ void ldmat4(uint32_t* r, uint32_t addr) {
    asm volatile("ldmatrix.sync.aligned.m8n8.x4.shared.b16 {%0,%1,%2,%3}, [%4];"
        : "=r"(r[0]), "=r"(r[1]), "=r"(r[2]), "=r"(r[3]) : "r"(addr));
}

// ---------------------------------------------------------------------------
__global__ __launch_bounds__(256) void splitx_kernel(const float* __restrict__ x)
{
    int idx = blockIdx.x * 256 + threadIdx.x;
    int flat = idx * 4;
    int b = flat / (SEQL * OUTD);
    int rem = flat - b * (SEQL * OUTD);
    int t = rem / OUTD;
    int k = rem - t * OUTD;
    float4 v = *(const float4*)(x + (size_t)flat);
    size_t o = ((size_t)(b * MPB + t)) * OUTD + k;
    *(uint2*)(g_xh + o) = make_uint2(packhf(v.y, v.x), packhf(v.w, v.z));
}

__global__ __launch_bounds__(256) void splitw_kernel(
    const float* __restrict__ Wq, const float* __restrict__ Wk, const float* __restrict__ Wv)
{
    int k = blockIdx.x, z = blockIdx.y;
    const float* W = (z == 0) ? Wq : (z == 1) ? Wk : Wv;
    #pragma unroll
    for (int half = 0; half < 2; half++) {
        int n = threadIdx.x + half * 256;
        g_WhT[z][(size_t)n * OUTD + k] = __float2half_rn(W[(size_t)k * OUTD + n]);
    }
}

// ---------------------------------------------------------------------------
// Tensor-core projection: pure fp16 (xh * Wh), 1 term.
// ---------------------------------------------------------------------------
#define KT 32
#define SA 40
#define P_AH 0
#define P_BH (2 * 128 * SA)
#define SC 132
#define P_SMEM_BYTES 81920      // C epilogue (67584 B) dominates staging (40960 B)

__global__ __launch_bounds__(256, 2) void proj_tc_kernel()
{
    extern __shared__ __align__(16) hf psm[];
    const int tid = threadIdx.x;
    const int w = tid >> 5, l = tid & 31;
    const int lq = l >> 2, c = l & 3;
    const int wm = w & 3, wn = w >> 2;
    const int z  = blockIdx.x;
    const int hp = blockIdx.y;
    const int m0 = blockIdx.z * 128;
    const int n0 = hp * 128;
    const uint32_t su = (uint32_t)__cvta_generic_to_shared(psm);

    const hf* WhT = g_WhT[z] + (size_t)n0 * OUTD;

    auto stage = [&](int kt, int bi) {
        const int k0 = kt * KT;
        #pragma unroll
        for (int it = 0; it < 2; it++) {         // A: xh, 512 transfers
            int cid = tid + it * 256;
            int row = cid >> 2, seg = cid & 3;
            uint32_t dst = su + (uint32_t)((P_AH + bi * 128 * SA + row * SA + seg * 8) * 2);
            cpasync16(dst, g_xh + (size_t)(m0 + row) * OUTD + k0 + seg * 8);
        }
        #pragma unroll
        for (int it = 0; it < 2; it++) {         // B: Wh, 512 transfers
            int cid = tid + it * 256;
            int row = cid >> 2, seg = cid & 3;
            uint32_t dst = su + (uint32_t)((P_BH + bi * 128 * SA + row * SA + seg * 8) * 2);
            cpasync16(dst, WhT + (size_t)row * OUTD + k0 + seg * 8);
        }
        cpcommit();
    };

    stage(0, 0);

    float acc[2][8][4];
    #pragma unroll
    for (int i = 0; i < 2; i++)
        #pragma unroll
        for (int j = 0; j < 8; j++)
            #pragma unroll
            for (int t = 0; t < 4; t++) acc[i][j][t] = 0.f;

    const int la16 = l & 15;
    const int la8  = l >> 4;
    const int rB   = ((l >> 4) << 3) + (l & 7);
    const int cB8  = ((l >> 3) & 1) * 8;

    for (int kt = 0; kt < OUTD / KT; kt++) {
        if (kt < OUTD / KT - 1) { stage(kt + 1, (kt + 1) & 1); cpwait1(); }
        else cpwait0();
        __syncthreads();
        const int bi = kt & 1;
        const uint32_t ahb = su + (uint32_t)((P_AH + bi * 128 * SA) * 2);
        const uint32_t bhb = su + (uint32_t)((P_BH + bi * 128 * SA) * 2);

        #pragma unroll
        for (int hh = 0; hh < 2; hh++) {
            const int kb = hh * 16;
            uint32_t ah[2][4];
            #pragma unroll
            for (int mb = 0; mb < 2; mb++) {
                uint32_t off = (uint32_t)((wm * 32 + mb * 16 + la16) * SA * 2 + (kb + la8 * 8) * 2);
                ldmat4(ah[mb], ahb + off);
            }
            #pragma unroll
            for (int nbp = 0; nbp < 4; nbp++) {
                uint32_t off = (uint32_t)((wn * 64 + nbp * 16 + rB) * SA * 2 + (kb + cB8) * 2);
                uint32_t bh4[4];
                ldmat4(bh4, bhb + off);
                #pragma unroll
                for (int half = 0; half < 2; half++) {
                    int nb = nbp * 2 + half;
                    #pragma unroll
                    for (int mb = 0; mb < 2; mb++)
                        mma16816h(acc[mb][nb], ah[mb], bh4[2 * half], bh4[2 * half + 1]);
                }
            }
        }
        __syncthreads();
    }

    if (z <= 1) {
        hf* G = z ? g_Kh : g_Qh;
        const float fac = z ? 1.f : (SCALE * LOG2E);
        #pragma unroll
        for (int mb = 0; mb < 2; mb++) {
            #pragma unroll
            for (int rh = 0; rh < 2; rh++) {
                int r = wm * 32 + mb * 16 + lq + rh * 8;
                int m = m0 + r;
                int b = m / MPB;
                int t = m - b * MPB;
                if (t >= SEQL) continue;
                int iq = t >> 2, r4 = t & 3;
                #pragma unroll
                for (int nb = 0; nb < 8; nb++) {
                    int col = wn * 64 + nb * 8 + c * 2;
                    int head = hp * 2 + (col >> 6);
                    int d = col & 63;
                    int combo = (b * NHEAD + head) * RATE + r4;
                    size_t o = ((size_t)combo * NSUBP + iq) * 64 + d;
                    float v0 = acc[mb][nb][rh * 2 + 0] * fac;
                    float v1 = acc[mb][nb][rh * 2 + 1] * fac;
                    *(uint32_t*)(G + o) = packhf(v1, v0);
                }
            }
        }
        return;
    }

    // z==2: stage C, then Vf (fp32, row-major) + VTh (fp16, transposed)
    float* C = (float*)psm;
    #pragma unroll
    for (int mb = 0; mb < 2; mb++) {
        int r0 = wm * 32 + mb * 16 + lq;
        #pragma unroll
        for (int nb = 0; nb < 8; nb++) {
            int col = wn * 64 + nb * 8 + c * 2;
            *(float2*)(C + r0 * SC + col)       = make_float2(acc[mb][nb][0], acc[mb][nb][1]);
            *(float2*)(C + (r0 + 8) * SC + col) = make_float2(acc[mb][nb][2], acc[mb][nb][3]);
        }
    }
    __syncthreads();

    const int bb = m0 / MPB;
    const int t0 = m0 - bb * MPB;
    const bool fast = ((m0 + 127) / MPB == bb) && (t0 + 128 <= SEQL);

    if (fast) {
        const int iq0 = t0 >> 2;
        {
            int r = tid >> 1, hh2 = tid & 1;
            int head = hp * 2 + hh2;
            int t = t0 + r;
            int iq = t >> 2, r4 = t & 3;
            int combo = (bb * NHEAD + head) * RATE + r4;
            size_t orow = ((size_t)combo * NSUBP + iq) * 64;
            #pragma unroll
            for (int j = 0; j < 16; j++)
                *(float4*)(g_Vf + orow + j * 4) = *(const float4*)(C + r * SC + hh2 * 64 + j * 4);
        }
        {
            int hh2 = tid & 1;
            int head = hp * 2 + hh2;
            int tid2 = tid >> 1;
            int g = tid2 & 7, r4 = (tid2 >> 3) & 3, dl = tid2 >> 5;
            int combo = (bb * NHEAD + head) * RATE + r4;
            #pragma unroll
            for (int it = 0; it < 16; it++) {
                int d = it * 4 + dl;
                float v[4];
                #pragma unroll
                for (int j = 0; j < 4; j++) {
                    int r = (g * 4 + j) * 4 + r4;
                    v[j] = C[r * SC + hh2 * 64 + d];
                }
                uint2 uh = make_uint2(packhf(v[1], v[0]), packhf(v[3], v[2]));
                size_t o = ((size_t)combo * 64 + d) * NSUBP + iq0 + g * 4;
                *(uint2*)(g_VTh + o) = uh;
            }
        }
    } else {
        int r = tid >> 1, hh2 = tid & 1;
        int head = hp * 2 + hh2;
        int m = m0 + r;
        int b = m / MPB;
        int t = m - b * MPB;
        if (t < SEQL) {
            int iq = t >> 2, r4 = t & 3;
            int combo = (b * NHEAD + head) * RATE + r4;
            size_t orow = ((size_t)combo * NSUBP + iq) * 64;
            #pragma unroll
            for (int j = 0; j < 16; j++) {
                int d = j * 4;
                float4 v = *(const float4*)(C + r * SC + hh2 * 64 + d);
                *(float4*)(g_Vf + orow + d) = v;
                float vf[4] = {v.x, v.y, v.z, v.w};
                #pragma unroll
                for (int e = 0; e < 4; e++) {
                    size_t ot = ((size_t)combo * 64 + d + e) * NSUBP + iq;
                    g_VTh[ot] = __float2half_rn(vf[e]);
                }
            }
        }
    }
}

// ---------------------------------------------------------------------------
// Flash attention: unchanged R15 (Q fp16-single, PV 1-term, fixed-max, BK=128).
// ---------------------------------------------------------------------------
#define SM_QH 0
#define SM_BUF (BQ * SK)
#define TILEU (2 * 64 * SK)
#define BUF128 (2 * TILEU)
#define SMEM_BYTES ((SM_BUF + 2 * BUF128) * 2)   // 92160 B

__global__ __launch_bounds__(256, 2) void attn_kernel(float* __restrict__ out)
{
    extern __shared__ __align__(16) hf sm[];
    hf* QhS = sm + SM_QH;

    const int tid = threadIdx.x;
    const int w = tid >> 5, l = tid & 31;
    const int lq = l >> 2;
    const int c  = l & 3;
    const int combo = blockIdx.y;
    const int q0 = blockIdx.x * BQ;
    const uint32_t smem_u32 = (uint32_t)__cvta_generic_to_shared(sm);

    const size_t gq = (size_t)combo * NSUBP * 64;
    const size_t gvt = (size_t)combo * 64 * NSUBP;

    #pragma unroll
    for (int it = 0; it < 4; it++) {
        int cid = tid + it * 256;
        int row = cid >> 3, seg = cid & 7;
        uint32_t dst = smem_u32 + (uint32_t)((SM_QH + row * SK) * 2 + seg * 16);
        cpasync16(dst, g_Qh + gq + (size_t)(q0 + row) * 64 + seg * 8);
    }
    cpcommit();

    auto stageB = [&](int ks, int buf) {
        #pragma unroll
        for (int it = 0; it < 8; it++) {
            int cid = tid + it * 256;
            int ts = cid >> 10;
            int rem = cid & 1023;
            int arr = rem >> 9;
            int rem2 = rem & 511;
            int row = rem2 >> 3, seg = rem2 & 7;
            uint32_t dst = smem_u32 + (uint32_t)((SM_BUF + buf * BUF128 + ts * TILEU
                                                  + arr * 64 * SK + row * SK) * 2 + seg * 16);
            const hf* src = (arr == 0)
                ? g_Kh + gq + (size_t)(ks + ts * 64 + row) * 64 + seg * 8
                : g_VTh + gvt + (size_t)row * NSUBP + ks + ts * 64 + seg * 8;
            cpasync16(dst, src);
        }
        cpcommit();
    };
    stageB(0, 0);
    cpwait0();
    __syncthreads();

    uint32_t qh[4][4];
    {
        const int la16 = l & 15, la8 = l >> 4;
        uint32_t qhb = smem_u32 + (uint32_t)((SM_QH + (w * 16 + la16) * SK) * 2);
        #pragma unroll
        for (int kc = 0; kc < 4; kc++)
            ldmat4(qh[kc], qhb + (uint32_t)((kc * 16 + la8 * 8) * 2));
    }

    float oacc[8][4];
    #pragma unroll
    for (int j = 0; j < 8; j++)
        #pragma unroll
        for (int t = 0; t < 4; t++) oacc[j][t] = 0.f;
    float l0 = 0.f, l1 = 0.f;

    const int lrow8 = l & 7;
    const int lcol8 = l >> 3;
    const uint32_t boff_lane = (uint32_t)(lrow8 * SK * 2 + lcol8 * 16);

    for (int kt2 = 0; kt2 < 8; kt2++) {
        __syncthreads();
        if (kt2 < 7) {
            stageB((kt2 + 1) * 128, (kt2 + 1) & 1);
            cpwait1();
        } else {
            cpwait0();
        }
        __syncthreads();

        #pragma unroll
        for (int s = 0; s < 2; s++) {
            const int tb = SM_BUF + (kt2 & 1) * BUF128 + s * TILEU;
            const uint32_t khb = smem_u32 + (uint32_t)(tb * 2) + boff_lane;
            const uint32_t vhb = smem_u32 + (uint32_t)((tb + 64 * SK) * 2) + boff_lane;

            float sacc[8][4];
            #pragma unroll
            for (int j = 0; j < 8; j++) {
                #pragma unroll
                for (int t = 0; t < 4; t++) sacc[j][t] = 0.f;
                uint32_t bh[8];
                uint32_t a = khb + (uint32_t)(j * 8 * SK * 2);
                ldmat4(bh, a); ldmat4(bh + 4, a + 64);
                #pragma unroll
                for (int kc = 0; kc < 4; kc++)
                    mma16816h(sacc[j], qh[kc], bh[2 * kc], bh[2 * kc + 1]);
            }

            #pragma unroll
            for (int j = 0; j < 8; j++) {
                sacc[j][0] = exp2f(sacc[j][0]);
                sacc[j][1] = exp2f(sacc[j][1]);
                sacc[j][2] = exp2f(sacc[j][2]);
                sacc[j][3] = exp2f(sacc[j][3]);
                l0 += sacc[j][0] + sacc[j][1];
                l1 += sacc[j][2] + sacc[j][3];
            }

            uint32_t pah[4][4];
            #pragma unroll
            for (int kc = 0; kc < 4; kc++) {
                int j0 = 2 * kc, j1 = 2 * kc + 1;
                pah[kc][0] = packhf(sacc[j0][1], sacc[j0][0]);
                pah[kc][1] = packhf(sacc[j0][3], sacc[j0][2]);
                pah[kc][2] = packhf(sacc[j1][1], sacc[j1][0]);
                pah[kc][3] = packhf(sacc[j1][3], sacc[j1][2]);
            }

            #pragma unroll
            for (int j = 0; j < 8; j++) {
                uint32_t bh[8];
                uint32_t a = vhb + (uint32_t)(j * 8 * SK * 2);
                ldmat4(bh, a); ldmat4(bh + 4, a + 64);
                #pragma unroll
                for (int kc = 0; kc < 4; kc++)
                    mma16816h(oacc[j], pah[kc], bh[2 * kc], bh[2 * kc + 1]);
            }
        }
    }

    // ---- band pass (7 banded logits) + zero pad key (adds 1 to l) ----
    __syncthreads();
    float* Kband = (float*)(sm + SM_BUF);
    float* Vband = Kband + 134 * BSW;
    for (int i = tid; i < 134 * 64; i += 256) {
        int rr = i >> 6, d = i & 63;
        int g = q0 - 3 + rr;
        float kv = 0.f, vv = 0.f;
        if (g >= 0) {
            size_t o = gq + (size_t)g * 64 + d;
            kv = __half2float(g_Kh[o]);
            vv = g_Vf[o];
        }
        Kband[rr * BSW + d] = kv;
        Vband[rr * BSW + d] = vv;
    }
    __syncthreads();

    float bl[2][2];
    #pragma unroll
    for (int rh = 0; rh < 2; rh++) {
        int qlcl = w * 16 + lq + 8 * rh;
        int kk0 = c, kk1 = c + 4;
        float acc0 = 0.f, acc1 = 0.f;
        const float* kb0 = Kband + (qlcl + kk0) * BSW;
        const float* kb1 = Kband + (qlcl + kk1) * BSW;
        #pragma unroll 8
        for (int d = 0; d < 64; d++) {
            float qf = __half2float(QhS[qlcl * SK + d]);
            acc0 += qf * kb0[d];
            if (kk1 < 7) acc1 += qf * kb1[d];
        }
        bl[rh][0] = acc0;
        bl[rh][1] = acc1;
    }

    {
        float p00 = exp2f(bl[0][0]);
        float p01 = (c + 4 < 7) ? exp2f(bl[0][1]) : 0.f;
        float p10 = exp2f(bl[1][0]);
        float p11 = (c + 4 < 7) ? exp2f(bl[1][1]) : 0.f;
        l0 += p00 + p01 + ((c == 0) ? 1.f : 0.f);
        l1 += p10 + p11 + ((c == 0) ? 1.f : 0.f);

        int r0 = w * 16 + lq;
        #pragma unroll
        for (int kk = 0; kk < 7; kk++) {
            int src = (l & ~3) | (kk & 3);
            float pb0 = __shfl_sync(0xffffffffu, (kk < 4) ? p00 : p01, src);
            float pb1 = __shfl_sync(0xffffffffu, (kk < 4) ? p10 : p11, src);
            const float* v0 = Vband + (r0 + kk) * BSW + c * 2;
            const float* v1 = Vband + (r0 + 8 + kk) * BSW + c * 2;
            #pragma unroll
            for (int j = 0; j < 8; j++) {
                float2 a = *(const float2*)(v0 + j * 8);
                float2 bq = *(const float2*)(v1 + j * 8);
                oacc[j][0] += pb0 * a.x; oacc[j][1] += pb0 * a.y;
                oacc[j][2] += pb1 * bq.x; oacc[j][3] += pb1 * bq.y;
            }
        }
    }

    // ---- epilogue ----
    l0 += __shfl_xor_sync(0xffffffffu, l0, 1);
    l0 += __shfl_xor_sync(0xffffffffu, l0, 2);
    l1 += __shfl_xor_sync(0xffffffffu, l1, 1);
    l1 += __shfl_xor_sync(0xffffffffu, l1, 2);

    const int b = combo >> 5;
    const int h = (combo >> 2) & 7;
    const int r = combo & 3;
    float inv0 = 1.f / l0, inv1 = 1.f / l1;
    int qg = q0 + w * 16 + lq;
    size_t o0 = ((size_t)(b * SEQL + qg * 4 + r)) * OUTD + h * 64 + c * 2;
    size_t o1 = ((size_t)(b * SEQL + (qg + 8) * 4 + r)) * OUTD + h * 64 + c * 2;
    #pragma unroll
    for (int j = 0; j < 8; j++) {
        *(float2*)(out + o0 + j * 8) = make_float2(oacc[j][0] * inv0, oacc[j][1] * inv0);
        *(float2*)(out + o1 + j * 8) = make_float2(oacc[j][2] * inv1, oacc[j][3] * inv1);
    }
}

// ---------------------------------------------------------------------------
extern "C" void kernel_launch(void* const* d_in, const int* in_sizes, int n_in,
                              void* d_out, int out_size)
{
    const float* x  = (const float*)d_in[0];
    const float* Wq = (const float*)d_in[1];
    const float* Wk = (const float*)d_in[2];
    const float* Wv = (const float*)d_in[3];
    float* out = (float*)d_out;

    cudaFuncSetAttribute(attn_kernel, cudaFuncAttributeMaxDynamicSharedMemorySize, SMEM_BYTES);
    cudaFuncSetAttribute(proj_tc_kernel, cudaFuncAttributeMaxDynamicSharedMemorySize, P_SMEM_BYTES);

    splitx_kernel<<<(BATCH * SEQL * OUTD / 4) / 256, 256>>>(x);
    splitw_kernel<<<dim3(OUTD, 3), 256>>>(Wq, Wk, Wv);

    dim3 pgrid(3, NHEAD / 2, MXP / 128);        // z, head-pair, m-tile
    proj_tc_kernel<<<pgrid, 256, P_SMEM_BYTES>>>();

    dim3 agrid(SEQL / RATE / BQ, NCOMBO);
    attn_kernel<<<agrid, 256, SMEM_BYTES>>>(out);
}